// round 9
// baseline (speedup 1.0000x reference)
#include <cuda_runtime.h>
#include <cuda_bf16.h>
#include <cstdint>
#include <math.h>

#define T_  2048
#define D_  2048
#define H_  16
#define HD_ 128

typedef __nv_bfloat16 bf16;

// ---------------------------------------------------------------------------
// Scratch (allocation-free rule: __device__ globals)
// ---------------------------------------------------------------------------
__device__ bf16 g_xhi[T_ * D_];
__device__ bf16 g_xlo[T_ * D_];
__device__ bf16 g_Ahi[T_ * D_];
__device__ bf16 g_Alo[T_ * D_];
__device__ bf16 g_Qhi[T_ * D_];
__device__ bf16 g_Qlo[T_ * D_];
__device__ bf16 g_Khi[T_ * D_];
__device__ bf16 g_Klo[T_ * D_];
__device__ bf16 g_Vhi[T_ * D_];
__device__ bf16 g_Vlo[T_ * D_];
__device__ bf16 g_Wthi[4][D_ * D_];   // transposed weights [N,K], hi part
__device__ bf16 g_Wtlo[4][D_ * D_];   // transposed weights [N,K], lo part

// ---------------------------------------------------------------------------
// PTX helpers (compute_103-safe: mma.sync / ldmatrix / cp.async only)
// ---------------------------------------------------------------------------
__device__ __forceinline__ uint32_t smem_u32(const void* p) {
    uint32_t a;
    asm("{ .reg .u64 t; cvta.to.shared.u64 t, %1; cvt.u32.u64 %0, t; }"
        : "=r"(a) : "l"(p));
    return a;
}

#define CPA16(dst, src) \
    asm volatile("cp.async.cg.shared.global [%0], [%1], 16;" :: "r"(dst), "l"(src) : "memory")
#define CPA_COMMIT() asm volatile("cp.async.commit_group;" ::: "memory")
#define CPA_WAIT(n)  asm volatile("cp.async.wait_group %0;" :: "n"(n) : "memory")

__device__ __forceinline__ void ldsm_x4(uint32_t* r, uint32_t addr) {
    asm volatile("ldmatrix.sync.aligned.m8n8.x4.shared.b16 {%0,%1,%2,%3}, [%4];"
                 : "=r"(r[0]), "=r"(r[1]), "=r"(r[2]), "=r"(r[3]) : "r"(addr));
}

__device__ __forceinline__ void ldsm_x4_t(uint32_t* r, uint32_t addr) {
    asm volatile("ldmatrix.sync.aligned.m8n8.x4.trans.shared.b16 {%0,%1,%2,%3}, [%4];"
                 : "=r"(r[0]), "=r"(r[1]), "=r"(r[2]), "=r"(r[3]) : "r"(addr));
}

__device__ __forceinline__ void mma_bf16(float* d, const uint32_t* a,
                                         const uint32_t* b) {
    asm volatile(
        "mma.sync.aligned.m16n8k16.row.col.f32.bf16.bf16.f32 "
        "{%0,%1,%2,%3}, {%4,%5,%6,%7}, {%8,%9}, {%0,%1,%2,%3};"
        : "+f"(d[0]), "+f"(d[1]), "+f"(d[2]), "+f"(d[3])
        : "r"(a[0]), "r"(a[1]), "r"(a[2]), "r"(a[3]), "r"(b[0]), "r"(b[1]));
}

__device__ __forceinline__ uint32_t packbf(float lo, float hi) {
    uint32_t r;
    asm("cvt.rn.bf16x2.f32 %0, %1, %2;" : "=r"(r) : "f"(hi), "f"(lo));
    return r;
}

__device__ __forceinline__ float bfround(float v) {
    return __bfloat162float(__float2bfloat16(v));
}

// ---------------------------------------------------------------------------
// Split fp32 -> (hi, lo) bf16, row-major
// ---------------------------------------------------------------------------
__global__ __launch_bounds__(256) void split_kernel(const float* __restrict__ src,
                                                    bf16* __restrict__ hi,
                                                    bf16* __restrict__ lo)
{
    int i = blockIdx.x * 256 + threadIdx.x;
    if (i >= T_ * D_) return;
    float v = src[i];
    bf16 h = __float2bfloat16(v);
    float r = v - __bfloat162float(h);
    hi[i] = h;
    lo[i] = __float2bfloat16(r);
}

// ---------------------------------------------------------------------------
// Transpose + split all 4 weights in one launch: W[K,N] -> Thi/Tlo[N,K].
// ---------------------------------------------------------------------------
__global__ __launch_bounds__(256) void transpose_split4(
    const float* __restrict__ W0, const float* __restrict__ W1,
    const float* __restrict__ W2, const float* __restrict__ W3,
    bf16* __restrict__ ThiB, bf16* __restrict__ TloB)
{
    __shared__ float tile[32][33];
    const size_t WSZ = (size_t)D_ * D_;
    int z = blockIdx.z;
    const float* W = (z == 0) ? W0 : (z == 1) ? W1 : (z == 2) ? W2 : W3;
    bf16* Thi = ThiB + z * WSZ;
    bf16* Tlo = TloB + z * WSZ;

    int bx = blockIdx.x * 32;
    int by = blockIdx.y * 32;
    int tx = threadIdx.x;
    int ty = threadIdx.y;
#pragma unroll
    for (int j = 0; j < 32; j += 8)
        tile[ty + j][tx] = W[(size_t)(by + ty + j) * D_ + bx + tx];
    __syncthreads();
#pragma unroll
    for (int j = 0; j < 32; j += 8) {
        float v = tile[tx][ty + j];
        bf16 h = __float2bfloat16(v);
        float r = v - __bfloat162float(h);
        size_t o = (size_t)(bx + ty + j) * D_ + by + tx;
        Thi[o] = h;
        Tlo[o] = __float2bfloat16(r);
    }
}

// ---------------------------------------------------------------------------
// GEMM mainloop: CTA tile 128x256, warp tile 64x64, BK=64, 2-stage cp.async,
// single sync per chunk, split-bf16 3-MMA. acc[4][8][4].
// Stage: Ahi 16KB | Alo 16KB | Bhi 32KB | Blo 32KB = 96KB. 2 stages = 192KB.
// ---------------------------------------------------------------------------
#define QSTAGE 98304u
#define GSMEM_BYTES 196608

__device__ __forceinline__ void gemm_mainloop(
    const bf16* __restrict__ Ahi, const bf16* __restrict__ Alo,
    const bf16* __restrict__ Bhi, const bf16* __restrict__ Blo,
    int row0, int col0, char* smem, float acc[4][8][4])
{
    uint32_t sb = smem_u32(smem);
    const int tid  = threadIdx.x;
    const int wid  = tid >> 5;
    const int lane = tid & 31;
    const int wm = wid >> 2;
    const int wn = wid & 3;

    const char* baseA[2] = {(const char*)(Ahi + (size_t)row0 * D_),
                            (const char*)(Alo + (size_t)row0 * D_)};
    const char* baseB[2] = {(const char*)(Bhi + (size_t)col0 * D_),
                            (const char*)(Blo + (size_t)col0 * D_)};

    auto load_stage = [&](int c, int s) {
        uint32_t st = sb + s * QSTAGE;
#pragma unroll
        for (int j = 0; j < 24; j++) {
            int q = tid + (j << 8);
            const char* src;
            uint32_t dst;
            if (q < 2048) {                      // A hi (j<4) / lo (j<8)
                int m = q >> 10;
                int idx = q & 1023;
                int r = idx >> 3, cb = (idx & 7) << 4;
                src = baseA[m] + (size_t)r * (D_ * 2) + c * 128 + cb;
                dst = st + m * 16384u + (uint32_t)(r * 128) + (cb ^ ((r & 7) << 4));
            } else {                             // B hi (j<16) / lo
                int qq = q - 2048;
                int m = qq >> 11;
                int idx = qq & 2047;
                int r = idx >> 3, cb = (idx & 7) << 4;
                src = baseB[m] + (size_t)r * (D_ * 2) + c * 128 + cb;
                dst = st + 32768u + m * 32768u + (uint32_t)(r * 128) + (cb ^ ((r & 7) << 4));
            }
            CPA16(dst, src);
        }
        CPA_COMMIT();
    };

    load_stage(0, 0);

    for (int c = 0; c < 32; c++) {
        CPA_WAIT(0);
        __syncthreads();
        if (c + 1 < 32) load_stage(c + 1, (c + 1) & 1);

        uint32_t st = sb + (c & 1) * QSTAGE;

#pragma unroll
        for (int ks = 0; ks < 4; ks++) {
            uint32_t ah[4][4], al[4][4];
#pragma unroll
            for (int i = 0; i < 4; i++) {
                int row = wm * 64 + i * 16 + (lane & 15);
                uint32_t colb = ks * 32 + ((lane >> 4) & 1) * 16;
                uint32_t off = (uint32_t)(row * 128) + (colb ^ ((row & 7) << 4));
                ldsm_x4(ah[i], st + off);
                ldsm_x4(al[i], st + 16384u + off);
            }
#pragma unroll
            for (int jp = 0; jp < 4; jp++) {
                uint32_t bh[4], bl[4];
                int row = wn * 64 + jp * 16 + ((lane >> 4) & 1) * 8 + (lane & 7);
                uint32_t colb = ks * 32 + ((lane >> 3) & 1) * 16;
                uint32_t off = (uint32_t)(row * 128) + (colb ^ ((row & 7) << 4));
                ldsm_x4(bh, st + 32768u + off);
                ldsm_x4(bl, st + 65536u + off);
#pragma unroll
                for (int i = 0; i < 4; i++) {
                    mma_bf16(acc[i][2 * jp],     ah[i], &bh[0]);
                    mma_bf16(acc[i][2 * jp],     al[i], &bh[0]);
                    mma_bf16(acc[i][2 * jp],     ah[i], &bl[0]);
                    mma_bf16(acc[i][2 * jp + 1], ah[i], &bh[2]);
                    mma_bf16(acc[i][2 * jp + 1], al[i], &bh[2]);
                    mma_bf16(acc[i][2 * jp + 1], ah[i], &bl[2]);
                }
            }
        }
    }
}

// ---------------------------------------------------------------------------
// QKV GEMM with fused RoPE (z<2) + split-bf16 epilogue via smem staging.
// ---------------------------------------------------------------------------
#define LDC 264

__global__ __launch_bounds__(256) void gemm_qkv(
    const bf16* __restrict__ xhi, const bf16* __restrict__ xlo,
    const bf16* __restrict__ Wthi, const bf16* __restrict__ Wtlo,
    const float* __restrict__ sint, const float* __restrict__ cost,
    bf16* __restrict__ Qhi, bf16* __restrict__ Qlo,
    bf16* __restrict__ Khi, bf16* __restrict__ Klo,
    bf16* __restrict__ Vhi, bf16* __restrict__ Vlo)
{
    extern __shared__ char smem[];
    const int z = blockIdx.z;
    const int row0 = blockIdx.y * 128;
    const int col0 = blockIdx.x * 256;
    const size_t WSZ = (size_t)D_ * D_;

    float acc[4][8][4];
#pragma unroll
    for (int i = 0; i < 4; i++)
#pragma unroll
        for (int j = 0; j < 8; j++)
#pragma unroll
            for (int q = 0; q < 4; q++) acc[i][j][q] = 0.0f;

    gemm_mainloop(xhi, xlo, Wthi + z * WSZ, Wtlo + z * WSZ, row0, col0, smem, acc);

    // Stage fp32 tile through smem (all warps done with stage buffers first).
    __syncthreads();
    float* sC = (float*)smem;
    const int tid  = threadIdx.x;
    const int wid  = tid >> 5;
    const int lane = tid & 31;
    const int wm = wid >> 2, wn = wid & 3;
    const int g = lane >> 2, t = lane & 3;
#pragma unroll
    for (int i = 0; i < 4; i++)
#pragma unroll
        for (int nt = 0; nt < 8; nt++) {
            int row = wm * 64 + i * 16 + g;
            int col = wn * 64 + nt * 8 + 2 * t;
            *(float2*)&sC[row * LDC + col] =
                make_float2(acc[i][nt][0], acc[i][nt][1]);
            *(float2*)&sC[(row + 8) * LDC + col] =
                make_float2(acc[i][nt][2], acc[i][nt][3]);
        }
    __syncthreads();

    bf16* Ohi = (z == 0) ? Qhi : (z == 1) ? Khi : Vhi;
    bf16* Olo = (z == 0) ? Qlo : (z == 1) ? Klo : Vlo;
    const bool dorope = (z < 2);

#pragma unroll 4
    for (int it = 0; it < 64; it++) {
        int idx = it * 256 + tid;            // 0..16383
        int r = idx >> 7;                    // 0..127
        int cth = idx & 127;
        int head = cth >> 6, d = cth & 63;
        int cp = head * 128 + d;
        float v1 = sC[r * LDC + cp];
        float v2 = sC[r * LDC + cp + 64];
        int tg = row0 + r;
        float o1 = v1, o2 = v2;
        if (dorope) {
            float s1 = sint[tg * HD_ + d],      c1 = cost[tg * HD_ + d];
            float s2 = sint[tg * HD_ + d + 64], c2 = cost[tg * HD_ + d + 64];
            o1 = v1 * c1 - v2 * s1;
            o2 = v2 * c2 + v1 * s2;
        }
        size_t gi = (size_t)tg * D_ + col0 + cp;
        Ohi[gi]      = __float2bfloat16(o1);
        Olo[gi]      = __float2bfloat16(o1 - bfround(o1));
        Ohi[gi + 64] = __float2bfloat16(o2);
        Olo[gi + 64] = __float2bfloat16(o2 - bfround(o2));
    }
}

// ---------------------------------------------------------------------------
// O-projection GEMM: fp32 output, direct register epilogue.
// ---------------------------------------------------------------------------
__global__ __launch_bounds__(256) void gemm_out(
    const bf16* __restrict__ Ahi, const bf16* __restrict__ Alo,
    const bf16* __restrict__ Bhi, const bf16* __restrict__ Blo,
    float* __restrict__ C)
{
    extern __shared__ char smem[];
    const int row0 = blockIdx.y * 128;
    const int col0 = blockIdx.x * 256;

    float acc[4][8][4];
#pragma unroll
    for (int i = 0; i < 4; i++)
#pragma unroll
        for (int j = 0; j < 8; j++)
#pragma unroll
            for (int q = 0; q < 4; q++) acc[i][j][q] = 0.0f;

    gemm_mainloop(Ahi, Alo, Bhi, Blo, row0, col0, smem, acc);

    const int tid  = threadIdx.x;
    const int wid  = tid >> 5;
    const int lane = tid & 31;
    const int wm = wid >> 2, wn = wid & 3;
    const int g = lane >> 2, t = lane & 3;
#pragma unroll
    for (int i = 0; i < 4; i++)
#pragma unroll
        for (int nt = 0; nt < 8; nt++) {
            int row = row0 + wm * 64 + i * 16 + g;
            int col = col0 + wn * 64 + nt * 8 + 2 * t;
            *(float2*)&C[(size_t)row * D_ + col] =
                make_float2(acc[i][nt][0], acc[i][nt][1]);
            *(float2*)&C[(size_t)(row + 8) * D_ + col] =
                make_float2(acc[i][nt][2], acc[i][nt][3]);
        }
}

// ---------------------------------------------------------------------------
// HMMA flash attention with causal + same-doc mask (unchanged from R7).
// ---------------------------------------------------------------------------
#define BMA 128
#define BNA 64
#define ASMEM_BYTES 131072

__global__ __launch_bounds__(256, 1) void attn_hmma(
    const bf16* __restrict__ Qhi, const bf16* __restrict__ Qlo,
    const bf16* __restrict__ Khi, const bf16* __restrict__ Klo,
    const bf16* __restrict__ Vhi, const bf16* __restrict__ Vlo,
    const int* __restrict__ doc,
    bf16* __restrict__ Ahi, bf16* __restrict__ Alo)
{
    extern __shared__ char smem[];
    const uint32_t sQh = smem_u32(smem);
    const uint32_t sQl = sQh + 32768;
    const uint32_t sKh = sQh + 65536;
    const uint32_t sKl = sQh + 81920;
    const uint32_t sVh = sQh + 98304;
    const uint32_t sVl = sQh + 114688;
    __shared__ int qdoc[BMA];
    __shared__ int kdoc[BNA];

    const int h = blockIdx.y;
    const int qt = blockIdx.x;
    const int qbase = qt * BMA;
    const int tid = threadIdx.x;
    const int wid = tid >> 5;
    const int lane = tid & 31;
    const int g = lane >> 2;
    const int t = lane & 3;
    const int r0 = wid * 16;
    const float scale = 0.08838834764831845f;

    for (int i = tid; i < BMA * 16; i += 256) {
        int r = i >> 4;
        int cb = (i & 15) << 4;
        size_t gidx = (size_t)(qbase + r) * D_ + h * HD_ + (cb >> 1);
        uint32_t off = (uint32_t)(r * 256) + (cb ^ ((r & 7) << 4));
        *(uint4*)(smem + off)         = *(const uint4*)&Qhi[gidx];
        *(uint4*)(smem + 32768 + off) = *(const uint4*)&Qlo[gidx];
    }
    if (tid < BMA) qdoc[tid] = doc[qbase + tid];
    __syncthreads();

    float oacc[16][4];
#pragma unroll
    for (int nt = 0; nt < 16; nt++)
#pragma unroll
        for (int q = 0; q < 4; q++) oacc[nt][q] = 0.0f;

    float m0 = -1e30f, m1 = -1e30f, l0 = 0.0f, l1 = 0.0f;
    const int qd_first = qdoc[0];
    const int qr0 = qbase + r0 + g;
    const int qr1 = qr0 + 8;
    const int dq0 = qdoc[r0 + g];
    const int dq1 = qdoc[r0 + g + 8];

    const int ktmax = 2 * qt + 1;
    for (int kt = 0; kt <= ktmax; kt++) {
        const int kbase = kt * BNA;
        if (doc[kbase + BNA - 1] < qd_first) continue;

        __syncthreads();
        for (int i = tid; i < BNA * 16; i += 256) {
            int r = i >> 4;
            int cb = (i & 15) << 4;
            size_t gidx = (size_t)(kbase + r) * D_ + h * HD_ + (cb >> 1);
            uint32_t off = (uint32_t)(r * 256) + (cb ^ ((r & 7) << 4));
            *(uint4*)(smem + 65536 + off)  = *(const uint4*)&Khi[gidx];
            *(uint4*)(smem + 81920 + off)  = *(const uint4*)&Klo[gidx];
            *(uint4*)(smem + 98304 + off)  = *(const uint4*)&Vhi[gidx];
            *(uint4*)(smem + 114688 + off) = *(const uint4*)&Vlo[gidx];
        }
        if (tid < BNA) kdoc[tid] = doc[kbase + tid];
        __syncthreads();

        float sacc[8][4];
#pragma unroll
        for (int nt = 0; nt < 8; nt++)
#pragma unroll
            for (int q = 0; q < 4; q++) sacc[nt][q] = 0.0f;

#pragma unroll
        for (int ks = 0; ks < 8; ks++) {
            uint32_t qh[4], ql[4];
            {
                int row = r0 + (lane & 15);
                int cb = ks * 32 + ((lane >> 4) & 1) * 16;
                uint32_t off = (uint32_t)(row * 256) + (cb ^ ((row & 7) << 4));
                ldsm_x4(qh, sQh + off);
                ldsm_x4(ql, sQl + off);
            }
#pragma unroll
            for (int jp = 0; jp < 4; jp++) {
                uint32_t kh[4], kl[4];
                int row = jp * 16 + ((lane >> 4) & 1) * 8 + (lane & 7);
                int cb = ks * 32 + ((lane >> 3) & 1) * 16;
                uint32_t off = (uint32_t)(row * 256) + (cb ^ ((row & 7) << 4));
                ldsm_x4(kh, sKh + off);
                ldsm_x4(kl, sKl + off);
                mma_bf16(sacc[2 * jp],     qh, &kh[0]);
                mma_bf16(sacc[2 * jp],     ql, &kh[0]);
                mma_bf16(sacc[2 * jp],     qh, &kl[0]);
                mma_bf16(sacc[2 * jp + 1], qh, &kh[2]);
                mma_bf16(sacc[2 * jp + 1], ql, &kh[2]);
                mma_bf16(sacc[2 * jp + 1], qh, &kl[2]);
            }
        }

#pragma unroll
        for (int nt = 0; nt < 8; nt++) {
#pragma unroll
            for (int e = 0; e < 2; e++) {
                int col = nt * 8 + 2 * t + e;
                int kc = kbase + col;
                int kd = kdoc[col];
                float v0 = sacc[nt][e] * scale;
                float v1 = sacc[nt][2 + e] * scale;
                sacc[nt][e]     = (kc <= qr0 && kd == dq0) ? v0 : -1e30f;
                sacc[nt][2 + e] = (kc <= qr1 && kd == dq1) ? v1 : -1e30f;
            }
        }

        float mr0 = -1e30f, mr1 = -1e30f;
#pragma unroll
        for (int nt = 0; nt < 8; nt++) {
            mr0 = fmaxf(mr0, fmaxf(sacc[nt][0], sacc[nt][1]));
            mr1 = fmaxf(mr1, fmaxf(sacc[nt][2], sacc[nt][3]));
        }
        mr0 = fmaxf(mr0, __shfl_xor_sync(0xffffffffu, mr0, 1));
        mr0 = fmaxf(mr0, __shfl_xor_sync(0xffffffffu, mr0, 2));
        mr1 = fmaxf(mr1, __shfl_xor_sync(0xffffffffu, mr1, 1));
        mr1 = fmaxf(mr1, __shfl_xor_sync(0xffffffffu, mr1, 2));
        float mn0 = fmaxf(m0, mr0), mn1 = fmaxf(m1, mr1);
        float rs0 = __expf(m0 - mn0), rs1 = __expf(m1 - mn1);
        float s0 = 0.0f, s1 = 0.0f;
#pragma unroll
        for (int nt = 0; nt < 8; nt++) {
#pragma unroll
            for (int e = 0; e < 2; e++) {
                float a = sacc[nt][e];
                a = (a <= -1e29f) ? 0.0f : __expf(a - mn0);
                sacc[nt][e] = a; s0 += a;
                float b = sacc[nt][2 + e];
                b = (b <= -1e29f) ? 0.0f : __expf(b - mn1);
                sacc[nt][2 + e] = b; s1 += b;
            }
        }
        s0 += __shfl_xor_sync(0xffffffffu, s0, 1);
        s0 += __shfl_xor_sync(0xffffffffu, s0, 2);
        s1 += __shfl_xor_sync(0xffffffffu, s1, 1);
        s1 += __shfl_xor_sync(0xffffffffu, s1, 2);
        l0 = l0 * rs0 + s0; m0 = mn0;
        l1 = l1 * rs1 + s1; m1 = mn1;

#pragma unroll
        for (int nt = 0; nt < 16; nt++) {
            oacc[nt][0] *= rs0; oacc[nt][1] *= rs0;
            oacc[nt][2] *= rs1; oacc[nt][3] *= rs1;
        }

#pragma unroll
        for (int ks = 0; ks < 4; ks++) {
            float p00 = sacc[2 * ks][0],     p01 = sacc[2 * ks][1];
            float p02 = sacc[2 * ks][2],     p03 = sacc[2 * ks][3];
            float p10 = sacc[2 * ks + 1][0], p11 = sacc[2 * ks + 1][1];
            float p12 = sacc[2 * ks + 1][2], p13 = sacc[2 * ks + 1][3];
            uint32_t phi[4], plo[4];
            phi[0] = packbf(p00, p01); phi[1] = packbf(p02, p03);
            phi[2] = packbf(p10, p11); phi[3] = packbf(p12, p13);
            plo[0] = packbf(p00 - bfround(p00), p01 - bfround(p01));
            plo[1] = packbf(p02 - bfround(p02), p03 - bfround(p03));
            plo[2] = packbf(p10 - bfround(p10), p11 - bfround(p11));
            plo[3] = packbf(p12 - bfround(p12), p13 - bfround(p13));

#pragma unroll
            for (int n0 = 0; n0 < 128; n0 += 16) {
                uint32_t vh[4], vl[4];
                int row = ks * 16 + ((lane >> 3) & 1) * 8 + (lane & 7);
                int cb = n0 * 2 + ((lane >> 4) & 1) * 16;
                uint32_t off = (uint32_t)(row * 256) + (cb ^ ((row & 7) << 4));
                ldsm_x4_t(vh, sVh + off);
                ldsm_x4_t(vl, sVl + off);
                int nt = n0 >> 3;
                mma_bf16(oacc[nt],     phi, &vh[0]);
                mma_bf16(oacc[nt],     plo, &vh[0]);
                mma_bf16(oacc[nt],     phi, &vl[0]);
                mma_bf16(oacc[nt + 1], phi, &vh[2]);
                mma_bf16(oacc[nt + 1], plo, &vh[2]);
                mma_bf16(oacc[nt + 1], phi, &vl[2]);
            }
        }
    }

    float i0 = 1.0f / l0, i1 = 1.0f / l1;
#pragma unroll
    for (int nt = 0; nt < 16; nt++) {
        float v0 = oacc[nt][0] * i0, v1 = oacc[nt][1] * i0;
        float v2 = oacc[nt][2] * i1, v3 = oacc[nt][3] * i1;
        size_t idx0 = (size_t)qr0 * D_ + h * HD_ + nt * 8 + 2 * t;
        size_t idx1 = idx0 + (size_t)8 * D_;
        *(uint32_t*)&Ahi[idx0] = packbf(v0, v1);
        *(uint32_t*)&Alo[idx0] = packbf(v0 - bfround(v0), v1 - bfround(v1));
        *(uint32_t*)&Ahi[idx1] = packbf(v2, v3);
        *(uint32_t*)&Alo[idx1] = packbf(v2 - bfround(v2), v3 - bfround(v3));
    }
}

// ---------------------------------------------------------------------------
// Launch
// ---------------------------------------------------------------------------
extern "C" void kernel_launch(void* const* d_in, const int* in_sizes, int n_in,
                              void* d_out, int out_size)
{
    const float* x    = (const float*)d_in[0];
    const float* Wq   = (const float*)d_in[1];
    const float* Wk   = (const float*)d_in[2];
    const float* Wv   = (const float*)d_in[3];
    const float* Wo   = (const float*)d_in[4];
    const float* sint = (const float*)d_in[5];
    const float* cost = (const float*)d_in[6];
    const int*   doc  = (const int*)d_in[7];

    bf16 *xhi, *xlo, *Ahi, *Alo, *Wthi, *Wtlo;
    bf16 *Qhi, *Qlo, *Khi, *Klo, *Vhi, *Vlo;
    cudaGetSymbolAddress((void**)&xhi, g_xhi);
    cudaGetSymbolAddress((void**)&xlo, g_xlo);
    cudaGetSymbolAddress((void**)&Ahi, g_Ahi);
    cudaGetSymbolAddress((void**)&Alo, g_Alo);
    cudaGetSymbolAddress((void**)&Qhi, g_Qhi);
    cudaGetSymbolAddress((void**)&Qlo, g_Qlo);
    cudaGetSymbolAddress((void**)&Khi, g_Khi);
    cudaGetSymbolAddress((void**)&Klo, g_Klo);
    cudaGetSymbolAddress((void**)&Vhi, g_Vhi);
    cudaGetSymbolAddress((void**)&Vlo, g_Vlo);
    cudaGetSymbolAddress((void**)&Wthi, g_Wthi);
    cudaGetSymbolAddress((void**)&Wtlo, g_Wtlo);

    const size_t WSZ = (size_t)D_ * D_;
    const int NELEM = T_ * D_;

    split_kernel<<<(NELEM + 255) / 256, 256>>>(x, xhi, xlo);
    dim3 tsGrid(D_ / 32, D_ / 32, 4), tsBlk(32, 8);
    transpose_split4<<<tsGrid, tsBlk>>>(Wq, Wk, Wv, Wo, Wthi, Wtlo);

    cudaFuncSetAttribute(gemm_qkv,
                         cudaFuncAttributeMaxDynamicSharedMemorySize, GSMEM_BYTES);
    cudaFuncSetAttribute(gemm_out,
                         cudaFuncAttributeMaxDynamicSharedMemorySize, GSMEM_BYTES);

    dim3 gGridQKV(D_ / 256, T_ / 128, 3);   // (8, 16, 3)
    gemm_qkv<<<gGridQKV, 256, GSMEM_BYTES>>>(xhi, xlo, Wthi, Wtlo, sint, cost,
                                             Qhi, Qlo, Khi, Klo, Vhi, Vlo);

    cudaFuncSetAttribute(attn_hmma,
                         cudaFuncAttributeMaxDynamicSharedMemorySize, ASMEM_BYTES);
    attn_hmma<<<dim3(T_ / BMA, H_), 256, ASMEM_BYTES>>>(
        Qhi, Qlo, Khi, Klo, Vhi, Vlo, doc, Ahi, Alo);

    dim3 gGridO(D_ / 256, T_ / 128, 1);     // (8, 16)
    gemm_out<<<gGridO, 256, GSMEM_BYTES>>>(Ahi, Alo, Wthi + 3 * WSZ, Wtlo + 3 * WSZ,
                                           (float*)d_out);
}

// round 10
// speedup vs baseline: 1.0346x; 1.0346x over previous
#include <cuda_runtime.h>
#include <cuda_bf16.h>
#include <cstdint>
#include <math.h>

#define T_  2048
#define D_  2048
#define H_  16
#define HD_ 128

typedef __nv_bfloat16 bf16;

// ---------------------------------------------------------------------------
// Scratch (allocation-free rule: __device__ globals)
// ---------------------------------------------------------------------------
__device__ bf16 g_xhi[T_ * D_];
__device__ bf16 g_xlo[T_ * D_];
__device__ bf16 g_Ahi[T_ * D_];
__device__ bf16 g_Alo[T_ * D_];
__device__ bf16 g_Qhi[T_ * D_];
__device__ bf16 g_Qlo[T_ * D_];
__device__ bf16 g_Khi[T_ * D_];
__device__ bf16 g_Klo[T_ * D_];
__device__ bf16 g_Vhi[T_ * D_];
__device__ bf16 g_Vlo[T_ * D_];
__device__ bf16 g_Wthi[4][D_ * D_];   // transposed weights [N,K], hi part
__device__ bf16 g_Wtlo[4][D_ * D_];   // transposed weights [N,K], lo part

// ---------------------------------------------------------------------------
// PTX helpers (compute_103-safe: mma.sync / ldmatrix / cp.async only)
// ---------------------------------------------------------------------------
__device__ __forceinline__ uint32_t smem_u32(const void* p) {
    uint32_t a;
    asm("{ .reg .u64 t; cvta.to.shared.u64 t, %1; cvt.u32.u64 %0, t; }"
        : "=r"(a) : "l"(p));
    return a;
}

#define CPA16(dst, src) \
    asm volatile("cp.async.cg.shared.global [%0], [%1], 16;" :: "r"(dst), "l"(src) : "memory")
#define CPA_COMMIT() asm volatile("cp.async.commit_group;" ::: "memory")
#define CPA_WAIT(n)  asm volatile("cp.async.wait_group %0;" :: "n"(n) : "memory")

__device__ __forceinline__ void ldsm_x4(uint32_t* r, uint32_t addr) {
    asm volatile("ldmatrix.sync.aligned.m8n8.x4.shared.b16 {%0,%1,%2,%3}, [%4];"
                 : "=r"(r[0]), "=r"(r[1]), "=r"(r[2]), "=r"(r[3]) : "r"(addr));
}

__device__ __forceinline__ void ldsm_x4_t(uint32_t* r, uint32_t addr) {
    asm volatile("ldmatrix.sync.aligned.m8n8.x4.trans.shared.b16 {%0,%1,%2,%3}, [%4];"
                 : "=r"(r[0]), "=r"(r[1]), "=r"(r[2]), "=r"(r[3]) : "r"(addr));
}

__device__ __forceinline__ void mma_bf16(float* d, const uint32_t* a,
                                         const uint32_t* b) {
    asm volatile(
        "mma.sync.aligned.m16n8k16.row.col.f32.bf16.bf16.f32 "
        "{%0,%1,%2,%3}, {%4,%5,%6,%7}, {%8,%9}, {%0,%1,%2,%3};"
        : "+f"(d[0]), "+f"(d[1]), "+f"(d[2]), "+f"(d[3])
        : "r"(a[0]), "r"(a[1]), "r"(a[2]), "r"(a[3]), "r"(b[0]), "r"(b[1]));
}

__device__ __forceinline__ uint32_t packbf(float lo, float hi) {
    uint32_t r;
    asm("cvt.rn.bf16x2.f32 %0, %1, %2;" : "=r"(r) : "f"(hi), "f"(lo));
    return r;
}

__device__ __forceinline__ float bfround(float v) {
    return __bfloat162float(__float2bfloat16(v));
}

// ---------------------------------------------------------------------------
// Split fp32 -> (hi, lo) bf16, row-major
// ---------------------------------------------------------------------------
__global__ __launch_bounds__(256) void split_kernel(const float* __restrict__ src,
                                                    bf16* __restrict__ hi,
                                                    bf16* __restrict__ lo)
{
    int i = blockIdx.x * 256 + threadIdx.x;
    if (i >= T_ * D_) return;
    float v = src[i];
    bf16 h = __float2bfloat16(v);
    float r = v - __bfloat162float(h);
    hi[i] = h;
    lo[i] = __float2bfloat16(r);
}

// ---------------------------------------------------------------------------
// Transpose + split all 4 weights in one launch: W[K,N] -> Thi/Tlo[N,K].
// ---------------------------------------------------------------------------
__global__ __launch_bounds__(256) void transpose_split4(
    const float* __restrict__ W0, const float* __restrict__ W1,
    const float* __restrict__ W2, const float* __restrict__ W3,
    bf16* __restrict__ ThiB, bf16* __restrict__ TloB)
{
    __shared__ float tile[32][33];
    const size_t WSZ = (size_t)D_ * D_;
    int z = blockIdx.z;
    const float* W = (z == 0) ? W0 : (z == 1) ? W1 : (z == 2) ? W2 : W3;
    bf16* Thi = ThiB + z * WSZ;
    bf16* Tlo = TloB + z * WSZ;

    int bx = blockIdx.x * 32;
    int by = blockIdx.y * 32;
    int tx = threadIdx.x;
    int ty = threadIdx.y;
#pragma unroll
    for (int j = 0; j < 32; j += 8)
        tile[ty + j][tx] = W[(size_t)(by + ty + j) * D_ + bx + tx];
    __syncthreads();
#pragma unroll
    for (int j = 0; j < 32; j += 8) {
        float v = tile[tx][ty + j];
        bf16 h = __float2bfloat16(v);
        float r = v - __bfloat162float(h);
        size_t o = (size_t)(bx + ty + j) * D_ + by + tx;
        Thi[o] = h;
        Tlo[o] = __float2bfloat16(r);
    }
}

// ---------------------------------------------------------------------------
// GEMM mainloop (R7 proven config): CTA tile 128x128, warp tile 64x32,
// BK=64, 3-stage cp.async, single sync per chunk, split-bf16 3-MMA.
// ---------------------------------------------------------------------------
#define STAGE_BYTES 65536
#define GSMEM_BYTES (3 * STAGE_BYTES)

__device__ __forceinline__ void gemm_mainloop128(
    const bf16* __restrict__ Ahi, const bf16* __restrict__ Alo,
    const bf16* __restrict__ Bhi, const bf16* __restrict__ Blo,
    int row0, int col0, char* smem, float acc[4][4][4])
{
    uint32_t sb = smem_u32(smem);
    const int tid  = threadIdx.x;
    const int wid  = tid >> 5;
    const int lane = tid & 31;
    const int wm = wid >> 2;
    const int wn = wid & 3;

    const char* base[4] = {
        (const char*)(Ahi + (size_t)row0 * D_),
        (const char*)(Alo + (size_t)row0 * D_),
        (const char*)(Bhi + (size_t)col0 * D_),
        (const char*)(Blo + (size_t)col0 * D_)
    };

    auto load_stage = [&](int c, int s) {
        uint32_t st = sb + s * STAGE_BYTES;
#pragma unroll
        for (int j = 0; j < 16; j++) {
            int m = j >> 2;
            int rem = tid + ((j & 3) << 8);
            int r = rem >> 3;
            int cb = (rem & 7) << 4;
            const char* src = base[m] + (size_t)r * (D_ * 2) + c * 128 + cb;
            uint32_t off = (uint32_t)(r * 128) + (cb ^ ((r & 7) << 4));
            CPA16(st + m * 16384 + off, src);
        }
        CPA_COMMIT();
    };

    load_stage(0, 0);
    load_stage(1, 1);

    for (int c = 0; c < 32; c++) {
        if (c < 31) CPA_WAIT(1);
        else        CPA_WAIT(0);
        __syncthreads();
        if (c + 2 < 32) load_stage(c + 2, (c + 2) % 3);

        uint32_t st   = sb + (c % 3) * STAGE_BYTES;
        uint32_t sAhi = st;
        uint32_t sAlo = st + 16384;
        uint32_t sBhi = st + 32768;
        uint32_t sBlo = st + 49152;

#pragma unroll
        for (int ks = 0; ks < 4; ks++) {
            uint32_t ah[4][4], al[4][4];
#pragma unroll
            for (int i = 0; i < 4; i++) {
                int row = wm * 64 + i * 16 + (lane & 15);
                uint32_t colb = ks * 32 + ((lane >> 4) & 1) * 16;
                uint32_t off = (uint32_t)(row * 128) + (colb ^ ((row & 7) << 4));
                ldsm_x4(ah[i], sAhi + off);
                ldsm_x4(al[i], sAlo + off);
            }
            uint32_t bh[8], bl[8];
#pragma unroll
            for (int jp = 0; jp < 2; jp++) {
                int row = wn * 32 + jp * 16 + ((lane >> 4) & 1) * 8 + (lane & 7);
                uint32_t colb = ks * 32 + ((lane >> 3) & 1) * 16;
                uint32_t off = (uint32_t)(row * 128) + (colb ^ ((row & 7) << 4));
                ldsm_x4(&bh[jp * 4], sBhi + off);
                ldsm_x4(&bl[jp * 4], sBlo + off);
            }
#pragma unroll
            for (int i = 0; i < 4; i++)
#pragma unroll
                for (int j = 0; j < 4; j++) {
                    mma_bf16(acc[i][j], ah[i], &bh[j * 2]);
                    mma_bf16(acc[i][j], al[i], &bh[j * 2]);
                    mma_bf16(acc[i][j], ah[i], &bl[j * 2]);
                }
        }
    }
}

// ---------------------------------------------------------------------------
// QKV GEMM with fused RoPE (z<2) + split-bf16 epilogue via smem staging.
// CTA's 128 output cols = exactly one head.
// ---------------------------------------------------------------------------
#define LDC 132

__global__ __launch_bounds__(256) void gemm_qkv(
    const bf16* __restrict__ xhi, const bf16* __restrict__ xlo,
    const bf16* __restrict__ Wthi, const bf16* __restrict__ Wtlo,
    const float* __restrict__ sint, const float* __restrict__ cost,
    bf16* __restrict__ Qhi, bf16* __restrict__ Qlo,
    bf16* __restrict__ Khi, bf16* __restrict__ Klo,
    bf16* __restrict__ Vhi, bf16* __restrict__ Vlo)
{
    extern __shared__ char smem[];
    const int z = blockIdx.z;
    const int row0 = blockIdx.y * 128;
    const int col0 = blockIdx.x * 128;
    const size_t WSZ = (size_t)D_ * D_;

    float acc[4][4][4];
#pragma unroll
    for (int i = 0; i < 4; i++)
#pragma unroll
        for (int j = 0; j < 4; j++)
#pragma unroll
            for (int q = 0; q < 4; q++) acc[i][j][q] = 0.0f;

    gemm_mainloop128(xhi, xlo, Wthi + z * WSZ, Wtlo + z * WSZ, row0, col0,
                     smem, acc);

    // Stage fp32 tile through smem.
    __syncthreads();
    float* sC = (float*)smem;
    const int tid  = threadIdx.x;
    const int wid  = tid >> 5;
    const int lane = tid & 31;
    const int wm = wid >> 2, wn = wid & 3;
    const int g = lane >> 2, t = lane & 3;
#pragma unroll
    for (int i = 0; i < 4; i++)
#pragma unroll
        for (int j = 0; j < 4; j++) {
            int row = wm * 64 + i * 16 + g;
            int col = wn * 32 + j * 8 + 2 * t;
            *(float2*)&sC[row * LDC + col] = make_float2(acc[i][j][0], acc[i][j][1]);
            *(float2*)&sC[(row + 8) * LDC + col] = make_float2(acc[i][j][2], acc[i][j][3]);
        }
    __syncthreads();

    bf16* Ohi = (z == 0) ? Qhi : (z == 1) ? Khi : Vhi;
    bf16* Olo = (z == 0) ? Qlo : (z == 1) ? Klo : Vlo;
    const bool dorope = (z < 2);

    // 128 rows x 64 (d, d+64) pairs = 8192 items.
#pragma unroll 4
    for (int it = 0; it < 32; it++) {
        int idx = it * 256 + tid;
        int r = idx >> 6;                 // 0..127
        int d = idx & 63;                 // 0..63
        float v1 = sC[r * LDC + d];
        float v2 = sC[r * LDC + d + 64];
        int tg = row0 + r;
        float o1 = v1, o2 = v2;
        if (dorope) {
            float s1 = sint[tg * HD_ + d],      c1 = cost[tg * HD_ + d];
            float s2 = sint[tg * HD_ + d + 64], c2 = cost[tg * HD_ + d + 64];
            o1 = v1 * c1 - v2 * s1;
            o2 = v2 * c2 + v1 * s2;
        }
        size_t gi = (size_t)tg * D_ + col0 + d;
        Ohi[gi]      = __float2bfloat16(o1);
        Olo[gi]      = __float2bfloat16(o1 - bfround(o1));
        Ohi[gi + 64] = __float2bfloat16(o2);
        Olo[gi + 64] = __float2bfloat16(o2 - bfround(o2));
    }
}

// ---------------------------------------------------------------------------
// O-projection GEMM: fp32 output, direct register epilogue.
// ---------------------------------------------------------------------------
__global__ __launch_bounds__(256) void gemm_out(
    const bf16* __restrict__ Ahi, const bf16* __restrict__ Alo,
    const bf16* __restrict__ Bhi, const bf16* __restrict__ Blo,
    float* __restrict__ C)
{
    extern __shared__ char smem[];
    const int row0 = blockIdx.y * 128;
    const int col0 = blockIdx.x * 128;

    float acc[4][4][4];
#pragma unroll
    for (int i = 0; i < 4; i++)
#pragma unroll
        for (int j = 0; j < 4; j++)
#pragma unroll
            for (int q = 0; q < 4; q++) acc[i][j][q] = 0.0f;

    gemm_mainloop128(Ahi, Alo, Bhi, Blo, row0, col0, smem, acc);

    const int tid  = threadIdx.x;
    const int wid  = tid >> 5;
    const int lane = tid & 31;
    const int wm = wid >> 2, wn = wid & 3;
    const int g = lane >> 2, t = lane & 3;
#pragma unroll
    for (int i = 0; i < 4; i++)
#pragma unroll
        for (int j = 0; j < 4; j++) {
            int row = row0 + wm * 64 + i * 16 + g;
            int col = col0 + wn * 32 + j * 8 + 2 * t;
            *(float2*)&C[(size_t)row * D_ + col] =
                make_float2(acc[i][j][0], acc[i][j][1]);
            *(float2*)&C[(size_t)(row + 8) * D_ + col] =
                make_float2(acc[i][j][2], acc[i][j][3]);
        }
}

// ---------------------------------------------------------------------------
// HMMA flash attention, BMA=64 q rows, 4 warps (128 thr), 96KB smem
// -> 2 CTAs/SM. Split-bf16 3-term MMA for S and PV.
// ---------------------------------------------------------------------------
#define BMA 64
#define BNA 64
#define ASMEM_BYTES 98304

__global__ __launch_bounds__(128, 2) void attn_hmma(
    const bf16* __restrict__ Qhi, const bf16* __restrict__ Qlo,
    const bf16* __restrict__ Khi, const bf16* __restrict__ Klo,
    const bf16* __restrict__ Vhi, const bf16* __restrict__ Vlo,
    const int* __restrict__ doc,
    bf16* __restrict__ Ahi, bf16* __restrict__ Alo)
{
    extern __shared__ char smem[];
    const uint32_t sQh = smem_u32(smem);
    const uint32_t sQl = sQh + 16384;
    const uint32_t sKh = sQh + 32768;
    const uint32_t sKl = sQh + 49152;
    const uint32_t sVh = sQh + 65536;
    const uint32_t sVl = sQh + 81920;
    __shared__ int qdoc[BMA];
    __shared__ int kdoc[BNA];

    const int h = blockIdx.y;
    const int qt = blockIdx.x;
    const int qbase = qt * BMA;
    const int tid = threadIdx.x;
    const int wid = tid >> 5;        // 0..3
    const int lane = tid & 31;
    const int g = lane >> 2;
    const int t = lane & 3;
    const int r0 = wid * 16;
    const float scale = 0.08838834764831845f;

    for (int i = tid; i < BMA * 16; i += 128) {
        int r = i >> 4;
        int cb = (i & 15) << 4;
        size_t gidx = (size_t)(qbase + r) * D_ + h * HD_ + (cb >> 1);
        uint32_t off = (uint32_t)(r * 256) + (cb ^ ((r & 7) << 4));
        *(uint4*)(smem + off)         = *(const uint4*)&Qhi[gidx];
        *(uint4*)(smem + 16384 + off) = *(const uint4*)&Qlo[gidx];
    }
    if (tid < BMA) qdoc[tid] = doc[qbase + tid];
    __syncthreads();

    float oacc[16][4];
#pragma unroll
    for (int nt = 0; nt < 16; nt++)
#pragma unroll
        for (int q = 0; q < 4; q++) oacc[nt][q] = 0.0f;

    float m0 = -1e30f, m1 = -1e30f, l0 = 0.0f, l1 = 0.0f;
    const int qd_first = qdoc[0];
    const int qr0 = qbase + r0 + g;
    const int qr1 = qr0 + 8;
    const int dq0 = qdoc[r0 + g];
    const int dq1 = qdoc[r0 + g + 8];

    for (int kt = 0; kt <= qt; kt++) {
        const int kbase = kt * BNA;
        if (doc[kbase + BNA - 1] < qd_first) continue;

        __syncthreads();
        for (int i = tid; i < BNA * 16; i += 128) {
            int r = i >> 4;
            int cb = (i & 15) << 4;
            size_t gidx = (size_t)(kbase + r) * D_ + h * HD_ + (cb >> 1);
            uint32_t off = (uint32_t)(r * 256) + (cb ^ ((r & 7) << 4));
            *(uint4*)(smem + 32768 + off) = *(const uint4*)&Khi[gidx];
            *(uint4*)(smem + 49152 + off) = *(const uint4*)&Klo[gidx];
            *(uint4*)(smem + 65536 + off) = *(const uint4*)&Vhi[gidx];
            *(uint4*)(smem + 81920 + off) = *(const uint4*)&Vlo[gidx];
        }
        if (tid < BNA) kdoc[tid] = doc[kbase + tid];
        __syncthreads();

        float sacc[8][4];
#pragma unroll
        for (int nt = 0; nt < 8; nt++)
#pragma unroll
            for (int q = 0; q < 4; q++) sacc[nt][q] = 0.0f;

#pragma unroll
        for (int ks = 0; ks < 8; ks++) {
            uint32_t qh[4], ql[4];
            {
                int row = r0 + (lane & 15);
                int cb = ks * 32 + ((lane >> 4) & 1) * 16;
                uint32_t off = (uint32_t)(row * 256) + (cb ^ ((row & 7) << 4));
                ldsm_x4(qh, sQh + off);
                ldsm_x4(ql, sQl + off);
            }
#pragma unroll
            for (int jp = 0; jp < 4; jp++) {
                uint32_t kh[4], kl[4];
                int row = jp * 16 + ((lane >> 4) & 1) * 8 + (lane & 7);
                int cb = ks * 32 + ((lane >> 3) & 1) * 16;
                uint32_t off = (uint32_t)(row * 256) + (cb ^ ((row & 7) << 4));
                ldsm_x4(kh, sKh + off);
                ldsm_x4(kl, sKl + off);
                mma_bf16(sacc[2 * jp],     qh, &kh[0]);
                mma_bf16(sacc[2 * jp],     ql, &kh[0]);
                mma_bf16(sacc[2 * jp],     qh, &kl[0]);
                mma_bf16(sacc[2 * jp + 1], qh, &kh[2]);
                mma_bf16(sacc[2 * jp + 1], ql, &kh[2]);
                mma_bf16(sacc[2 * jp + 1], qh, &kl[2]);
            }
        }

#pragma unroll
        for (int nt = 0; nt < 8; nt++) {
#pragma unroll
            for (int e = 0; e < 2; e++) {
                int col = nt * 8 + 2 * t + e;
                int kc = kbase + col;
                int kd = kdoc[col];
                float v0 = sacc[nt][e] * scale;
                float v1 = sacc[nt][2 + e] * scale;
                sacc[nt][e]     = (kc <= qr0 && kd == dq0) ? v0 : -1e30f;
                sacc[nt][2 + e] = (kc <= qr1 && kd == dq1) ? v1 : -1e30f;
            }
        }

        float mr0 = -1e30f, mr1 = -1e30f;
#pragma unroll
        for (int nt = 0; nt < 8; nt++) {
            mr0 = fmaxf(mr0, fmaxf(sacc[nt][0], sacc[nt][1]));
            mr1 = fmaxf(mr1, fmaxf(sacc[nt][2], sacc[nt][3]));
        }
        mr0 = fmaxf(mr0, __shfl_xor_sync(0xffffffffu, mr0, 1));
        mr0 = fmaxf(mr0, __shfl_xor_sync(0xffffffffu, mr0, 2));
        mr1 = fmaxf(mr1, __shfl_xor_sync(0xffffffffu, mr1, 1));
        mr1 = fmaxf(mr1, __shfl_xor_sync(0xffffffffu, mr1, 2));
        float mn0 = fmaxf(m0, mr0), mn1 = fmaxf(m1, mr1);
        float rs0 = __expf(m0 - mn0), rs1 = __expf(m1 - mn1);
        float s0 = 0.0f, s1 = 0.0f;
#pragma unroll
        for (int nt = 0; nt < 8; nt++) {
#pragma unroll
            for (int e = 0; e < 2; e++) {
                float a = sacc[nt][e];
                a = (a <= -1e29f) ? 0.0f : __expf(a - mn0);
                sacc[nt][e] = a; s0 += a;
                float b = sacc[nt][2 + e];
                b = (b <= -1e29f) ? 0.0f : __expf(b - mn1);
                sacc[nt][2 + e] = b; s1 += b;
            }
        }
        s0 += __shfl_xor_sync(0xffffffffu, s0, 1);
        s0 += __shfl_xor_sync(0xffffffffu, s0, 2);
        s1 += __shfl_xor_sync(0xffffffffu, s1, 1);
        s1 += __shfl_xor_sync(0xffffffffu, s1, 2);
        l0 = l0 * rs0 + s0; m0 = mn0;
        l1 = l1 * rs1 + s1; m1 = mn1;

#pragma unroll
        for (int nt = 0; nt < 16; nt++) {
            oacc[nt][0] *= rs0; oacc[nt][1] *= rs0;
            oacc[nt][2] *= rs1; oacc[nt][3] *= rs1;
        }

#pragma unroll
        for (int ks = 0; ks < 4; ks++) {
            float p00 = sacc[2 * ks][0],     p01 = sacc[2 * ks][1];
            float p02 = sacc[2 * ks][2],     p03 = sacc[2 * ks][3];
            float p10 = sacc[2 * ks + 1][0], p11 = sacc[2 * ks + 1][1];
            float p12 = sacc[2 * ks + 1][2], p13 = sacc[2 * ks + 1][3];
            uint32_t phi[4], plo[4];
            phi[0] = packbf(p00, p01); phi[1] = packbf(p02, p03);
            phi[2] = packbf(p10, p11); phi[3] = packbf(p12, p13);
            plo[0] = packbf(p00 - bfround(p00), p01 - bfround(p01));
            plo[1] = packbf(p02 - bfround(p02), p03 - bfround(p03));
            plo[2] = packbf(p10 - bfround(p10), p11 - bfround(p11));
            plo[3] = packbf(p12 - bfround(p12), p13 - bfround(p13));

#pragma unroll
            for (int n0 = 0; n0 < 128; n0 += 16) {
                uint32_t vh[4], vl[4];
                int row = ks * 16 + ((lane >> 3) & 1) * 8 + (lane & 7);
                int cb = n0 * 2 + ((lane >> 4) & 1) * 16;
                uint32_t off = (uint32_t)(row * 256) + (cb ^ ((row & 7) << 4));
                ldsm_x4_t(vh, sVh + off);
                ldsm_x4_t(vl, sVl + off);
                int nt = n0 >> 3;
                mma_bf16(oacc[nt],     phi, &vh[0]);
                mma_bf16(oacc[nt],     plo, &vh[0]);
                mma_bf16(oacc[nt],     phi, &vl[0]);
                mma_bf16(oacc[nt + 1], phi, &vh[2]);
                mma_bf16(oacc[nt + 1], plo, &vh[2]);
                mma_bf16(oacc[nt + 1], phi, &vl[2]);
            }
        }
    }

    float i0 = 1.0f / l0, i1 = 1.0f / l1;
#pragma unroll
    for (int nt = 0; nt < 16; nt++) {
        float v0 = oacc[nt][0] * i0, v1 = oacc[nt][1] * i0;
        float v2 = oacc[nt][2] * i1, v3 = oacc[nt][3] * i1;
        size_t idx0 = (size_t)qr0 * D_ + h * HD_ + nt * 8 + 2 * t;
        size_t idx1 = idx0 + (size_t)8 * D_;
        *(uint32_t*)&Ahi[idx0] = packbf(v0, v1);
        *(uint32_t*)&Alo[idx0] = packbf(v0 - bfround(v0), v1 - bfround(v1));
        *(uint32_t*)&Ahi[idx1] = packbf(v2, v3);
        *(uint32_t*)&Alo[idx1] = packbf(v2 - bfround(v2), v3 - bfround(v3));
    }
}

// ---------------------------------------------------------------------------
// Launch
// ---------------------------------------------------------------------------
extern "C" void kernel_launch(void* const* d_in, const int* in_sizes, int n_in,
                              void* d_out, int out_size)
{
    const float* x    = (const float*)d_in[0];
    const float* Wq   = (const float*)d_in[1];
    const float* Wk   = (const float*)d_in[2];
    const float* Wv   = (const float*)d_in[3];
    const float* Wo   = (const float*)d_in[4];
    const float* sint = (const float*)d_in[5];
    const float* cost = (const float*)d_in[6];
    const int*   doc  = (const int*)d_in[7];

    bf16 *xhi, *xlo, *Ahi, *Alo, *Wthi, *Wtlo;
    bf16 *Qhi, *Qlo, *Khi, *Klo, *Vhi, *Vlo;
    cudaGetSymbolAddress((void**)&xhi, g_xhi);
    cudaGetSymbolAddress((void**)&xlo, g_xlo);
    cudaGetSymbolAddress((void**)&Ahi, g_Ahi);
    cudaGetSymbolAddress((void**)&Alo, g_Alo);
    cudaGetSymbolAddress((void**)&Qhi, g_Qhi);
    cudaGetSymbolAddress((void**)&Qlo, g_Qlo);
    cudaGetSymbolAddress((void**)&Khi, g_Khi);
    cudaGetSymbolAddress((void**)&Klo, g_Klo);
    cudaGetSymbolAddress((void**)&Vhi, g_Vhi);
    cudaGetSymbolAddress((void**)&Vlo, g_Vlo);
    cudaGetSymbolAddress((void**)&Wthi, g_Wthi);
    cudaGetSymbolAddress((void**)&Wtlo, g_Wtlo);

    const size_t WSZ = (size_t)D_ * D_;
    const int NELEM = T_ * D_;

    split_kernel<<<(NELEM + 255) / 256, 256>>>(x, xhi, xlo);
    dim3 tsGrid(D_ / 32, D_ / 32, 4), tsBlk(32, 8);
    transpose_split4<<<tsGrid, tsBlk>>>(Wq, Wk, Wv, Wo, Wthi, Wtlo);

    cudaFuncSetAttribute(gemm_qkv,
                         cudaFuncAttributeMaxDynamicSharedMemorySize, GSMEM_BYTES);
    cudaFuncSetAttribute(gemm_out,
                         cudaFuncAttributeMaxDynamicSharedMemorySize, GSMEM_BYTES);

    dim3 gGridQKV(D_ / 128, T_ / 128, 3);   // (16, 16, 3)
    gemm_qkv<<<gGridQKV, 256, GSMEM_BYTES>>>(xhi, xlo, Wthi, Wtlo, sint, cost,
                                             Qhi, Qlo, Khi, Klo, Vhi, Vlo);

    cudaFuncSetAttribute(attn_hmma,
                         cudaFuncAttributeMaxDynamicSharedMemorySize, ASMEM_BYTES);
    attn_hmma<<<dim3(T_ / BMA, H_), 128, ASMEM_BYTES>>>(
        Qhi, Qlo, Khi, Klo, Vhi, Vlo, doc, Ahi, Alo);

    dim3 gGridO(D_ / 128, T_ / 128, 1);     // (16, 16)
    gemm_out<<<gGridO, 256, GSMEM_BYTES>>>(Ahi, Alo, Wthi + 3 * WSZ, Wtlo + 3 * WSZ,
                                           (float*)d_out);
}

// round 12
// speedup vs baseline: 1.0668x; 1.0311x over previous
#include <cuda_runtime.h>
#include <cuda_bf16.h>
#include <cstdint>
#include <math.h>

#define T_  2048
#define D_  2048
#define H_  16
#define HD_ 128

typedef __nv_bfloat16 bf16;

// ---------------------------------------------------------------------------
// Scratch (allocation-free rule: __device__ globals)
// ---------------------------------------------------------------------------
__device__ bf16 g_xhi[T_ * D_];
__device__ bf16 g_xlo[T_ * D_];
__device__ bf16 g_Ahi[T_ * D_];
__device__ bf16 g_Alo[T_ * D_];
__device__ bf16 g_Qhi[T_ * D_];
__device__ bf16 g_Qlo[T_ * D_];
__device__ bf16 g_Khi[T_ * D_];
__device__ bf16 g_Klo[T_ * D_];
__device__ bf16 g_Vhi[T_ * D_];
__device__ bf16 g_Vlo[T_ * D_];
__device__ bf16 g_Wthi[4][D_ * D_];   // transposed weights [N,K], hi part
__device__ bf16 g_Wtlo[4][D_ * D_];   // transposed weights [N,K], lo part

// ---------------------------------------------------------------------------
// PTX helpers (compute_103-safe: mma.sync / ldmatrix / cp.async only)
// ---------------------------------------------------------------------------
__device__ __forceinline__ uint32_t smem_u32(const void* p) {
    uint32_t a;
    asm("{ .reg .u64 t; cvta.to.shared.u64 t, %1; cvt.u32.u64 %0, t; }"
        : "=r"(a) : "l"(p));
    return a;
}

#define CPA16(dst, src) \
    asm volatile("cp.async.cg.shared.global [%0], [%1], 16;" :: "r"(dst), "l"(src) : "memory")
#define CPA_COMMIT() asm volatile("cp.async.commit_group;" ::: "memory")
#define CPA_WAIT(n)  asm volatile("cp.async.wait_group %0;" :: "n"(n) : "memory")

__device__ __forceinline__ void ldsm_x4(uint32_t* r, uint32_t addr) {
    asm volatile("ldmatrix.sync.aligned.m8n8.x4.shared.b16 {%0,%1,%2,%3}, [%4];"
                 : "=r"(r[0]), "=r"(r[1]), "=r"(r[2]), "=r"(r[3]) : "r"(addr));
}

__device__ __forceinline__ void ldsm_x4_t(uint32_t* r, uint32_t addr) {
    asm volatile("ldmatrix.sync.aligned.m8n8.x4.trans.shared.b16 {%0,%1,%2,%3}, [%4];"
                 : "=r"(r[0]), "=r"(r[1]), "=r"(r[2]), "=r"(r[3]) : "r"(addr));
}

__device__ __forceinline__ void mma_bf16(float* d, const uint32_t* a,
                                         const uint32_t* b) {
    asm volatile(
        "mma.sync.aligned.m16n8k16.row.col.f32.bf16.bf16.f32 "
        "{%0,%1,%2,%3}, {%4,%5,%6,%7}, {%8,%9}, {%0,%1,%2,%3};"
        : "+f"(d[0]), "+f"(d[1]), "+f"(d[2]), "+f"(d[3])
        : "r"(a[0]), "r"(a[1]), "r"(a[2]), "r"(a[3]), "r"(b[0]), "r"(b[1]));
}

__device__ __forceinline__ uint32_t packbf(float lo, float hi) {
    uint32_t r;
    asm("cvt.rn.bf16x2.f32 %0, %1, %2;" : "=r"(r) : "f"(hi), "f"(lo));
    return r;
}

__device__ __forceinline__ float bfround(float v) {
    return __bfloat162float(__float2bfloat16(v));
}

// ---------------------------------------------------------------------------
// Split fp32 -> (hi, lo) bf16, row-major
// ---------------------------------------------------------------------------
__global__ __launch_bounds__(256) void split_kernel(const float* __restrict__ src,
                                                    bf16* __restrict__ hi,
                                                    bf16* __restrict__ lo)
{
    int i = blockIdx.x * 256 + threadIdx.x;
    if (i >= T_ * D_) return;
    float v = src[i];
    bf16 h = __float2bfloat16(v);
    float r = v - __bfloat162float(h);
    hi[i] = h;
    lo[i] = __float2bfloat16(r);
}

// ---------------------------------------------------------------------------
// Transpose + split all 4 weights in one launch: W[K,N] -> Thi/Tlo[N,K].
// ---------------------------------------------------------------------------
__global__ __launch_bounds__(256) void transpose_split4(
    const float* __restrict__ W0, const float* __restrict__ W1,
    const float* __restrict__ W2, const float* __restrict__ W3,
    bf16* __restrict__ ThiB, bf16* __restrict__ TloB)
{
    __shared__ float tile[32][33];
    const size_t WSZ = (size_t)D_ * D_;
    int z = blockIdx.z;
    const float* W = (z == 0) ? W0 : (z == 1) ? W1 : (z == 2) ? W2 : W3;
    bf16* Thi = ThiB + z * WSZ;
    bf16* Tlo = TloB + z * WSZ;

    int bx = blockIdx.x * 32;
    int by = blockIdx.y * 32;
    int tx = threadIdx.x;
    int ty = threadIdx.y;
#pragma unroll
    for (int j = 0; j < 32; j += 8)
        tile[ty + j][tx] = W[(size_t)(by + ty + j) * D_ + bx + tx];
    __syncthreads();
#pragma unroll
    for (int j = 0; j < 32; j += 8) {
        float v = tile[tx][ty + j];
        bf16 h = __float2bfloat16(v);
        float r = v - __bfloat162float(h);
        size_t o = (size_t)(bx + ty + j) * D_ + by + tx;
        Thi[o] = h;
        Tlo[o] = __float2bfloat16(r);
    }
}

// ---------------------------------------------------------------------------
// GEMM mainloop (proven config, FROZEN): CTA tile 128x128, warp tile 64x32,
// BK=64, 3-stage cp.async, single sync per chunk, split-bf16 3-MMA.
// ---------------------------------------------------------------------------
#define STAGE_BYTES 65536
#define GSMEM_BYTES (3 * STAGE_BYTES)

__device__ __forceinline__ void gemm_mainloop128(
    const bf16* __restrict__ Ahi, const bf16* __restrict__ Alo,
    const bf16* __restrict__ Bhi, const bf16* __restrict__ Blo,
    int row0, int col0, char* smem, float acc[4][4][4])
{
    uint32_t sb = smem_u32(smem);
    const int tid  = threadIdx.x;
    const int wid  = tid >> 5;
    const int lane = tid & 31;
    const int wm = wid >> 2;
    const int wn = wid & 3;

    const char* base[4] = {
        (const char*)(Ahi + (size_t)row0 * D_),
        (const char*)(Alo + (size_t)row0 * D_),
        (const char*)(Bhi + (size_t)col0 * D_),
        (const char*)(Blo + (size_t)col0 * D_)
    };

    auto load_stage = [&](int c, int s) {
        uint32_t st = sb + s * STAGE_BYTES;
#pragma unroll
        for (int j = 0; j < 16; j++) {
            int m = j >> 2;
            int rem = tid + ((j & 3) << 8);
            int r = rem >> 3;
            int cb = (rem & 7) << 4;
            const char* src = base[m] + (size_t)r * (D_ * 2) + c * 128 + cb;
            uint32_t off = (uint32_t)(r * 128) + (cb ^ ((r & 7) << 4));
            CPA16(st + m * 16384 + off, src);
        }
        CPA_COMMIT();
    };

    load_stage(0, 0);
    load_stage(1, 1);

    for (int c = 0; c < 32; c++) {
        if (c < 31) CPA_WAIT(1);
        else        CPA_WAIT(0);
        __syncthreads();
        if (c + 2 < 32) load_stage(c + 2, (c + 2) % 3);

        uint32_t st   = sb + (c % 3) * STAGE_BYTES;
        uint32_t sAhi = st;
        uint32_t sAlo = st + 16384;
        uint32_t sBhi = st + 32768;
        uint32_t sBlo = st + 49152;

#pragma unroll
        for (int ks = 0; ks < 4; ks++) {
            uint32_t ah[4][4], al[4][4];
#pragma unroll
            for (int i = 0; i < 4; i++) {
                int row = wm * 64 + i * 16 + (lane & 15);
                uint32_t colb = ks * 32 + ((lane >> 4) & 1) * 16;
                uint32_t off = (uint32_t)(row * 128) + (colb ^ ((row & 7) << 4));
                ldsm_x4(ah[i], sAhi + off);
                ldsm_x4(al[i], sAlo + off);
            }
            uint32_t bh[8], bl[8];
#pragma unroll
            for (int jp = 0; jp < 2; jp++) {
                int row = wn * 32 + jp * 16 + ((lane >> 4) & 1) * 8 + (lane & 7);
                uint32_t colb = ks * 32 + ((lane >> 3) & 1) * 16;
                uint32_t off = (uint32_t)(row * 128) + (colb ^ ((row & 7) << 4));
                ldsm_x4(&bh[jp * 4], sBhi + off);
                ldsm_x4(&bl[jp * 4], sBlo + off);
            }
#pragma unroll
            for (int i = 0; i < 4; i++)
#pragma unroll
                for (int j = 0; j < 4; j++) {
                    mma_bf16(acc[i][j], ah[i], &bh[j * 2]);
                    mma_bf16(acc[i][j], al[i], &bh[j * 2]);
                    mma_bf16(acc[i][j], ah[i], &bl[j * 2]);
                }
        }
    }
}

// ---------------------------------------------------------------------------
// QKV GEMM with fused RoPE (z<2) + split-bf16 epilogue via smem staging.
// ---------------------------------------------------------------------------
#define LDC 132

__global__ __launch_bounds__(256) void gemm_qkv(
    const bf16* __restrict__ xhi, const bf16* __restrict__ xlo,
    const bf16* __restrict__ Wthi, const bf16* __restrict__ Wtlo,
    const float* __restrict__ sint, const float* __restrict__ cost,
    bf16* __restrict__ Qhi, bf16* __restrict__ Qlo,
    bf16* __restrict__ Khi, bf16* __restrict__ Klo,
    bf16* __restrict__ Vhi, bf16* __restrict__ Vlo)
{
    extern __shared__ char smem[];
    const int z = blockIdx.z;
    const int row0 = blockIdx.y * 128;
    const int col0 = blockIdx.x * 128;
    const size_t WSZ = (size_t)D_ * D_;

    float acc[4][4][4];
#pragma unroll
    for (int i = 0; i < 4; i++)
#pragma unroll
        for (int j = 0; j < 4; j++)
#pragma unroll
            for (int q = 0; q < 4; q++) acc[i][j][q] = 0.0f;

    gemm_mainloop128(xhi, xlo, Wthi + z * WSZ, Wtlo + z * WSZ, row0, col0,
                     smem, acc);

    __syncthreads();
    float* sC = (float*)smem;
    const int tid  = threadIdx.x;
    const int wid  = tid >> 5;
    const int lane = tid & 31;
    const int wm = wid >> 2, wn = wid & 3;
    const int g = lane >> 2, t = lane & 3;
#pragma unroll
    for (int i = 0; i < 4; i++)
#pragma unroll
        for (int j = 0; j < 4; j++) {
            int row = wm * 64 + i * 16 + g;
            int col = wn * 32 + j * 8 + 2 * t;
            *(float2*)&sC[row * LDC + col] = make_float2(acc[i][j][0], acc[i][j][1]);
            *(float2*)&sC[(row + 8) * LDC + col] = make_float2(acc[i][j][2], acc[i][j][3]);
        }
    __syncthreads();

    bf16* Ohi = (z == 0) ? Qhi : (z == 1) ? Khi : Vhi;
    bf16* Olo = (z == 0) ? Qlo : (z == 1) ? Klo : Vlo;
    const bool dorope = (z < 2);

#pragma unroll 4
    for (int it = 0; it < 32; it++) {
        int idx = it * 256 + tid;
        int r = idx >> 6;
        int d = idx & 63;
        float v1 = sC[r * LDC + d];
        float v2 = sC[r * LDC + d + 64];
        int tg = row0 + r;
        float o1 = v1, o2 = v2;
        if (dorope) {
            float s1 = sint[tg * HD_ + d],      c1 = cost[tg * HD_ + d];
            float s2 = sint[tg * HD_ + d + 64], c2 = cost[tg * HD_ + d + 64];
            o1 = v1 * c1 - v2 * s1;
            o2 = v2 * c2 + v1 * s2;
        }
        size_t gi = (size_t)tg * D_ + col0 + d;
        Ohi[gi]      = __float2bfloat16(o1);
        Olo[gi]      = __float2bfloat16(o1 - bfround(o1));
        Ohi[gi + 64] = __float2bfloat16(o2);
        Olo[gi + 64] = __float2bfloat16(o2 - bfround(o2));
    }
}

// ---------------------------------------------------------------------------
// O-projection GEMM: fp32 output, direct register epilogue.
// ---------------------------------------------------------------------------
__global__ __launch_bounds__(256) void gemm_out(
    const bf16* __restrict__ Ahi, const bf16* __restrict__ Alo,
    const bf16* __restrict__ Bhi, const bf16* __restrict__ Blo,
    float* __restrict__ C)
{
    extern __shared__ char smem[];
    const int row0 = blockIdx.y * 128;
    const int col0 = blockIdx.x * 128;

    float acc[4][4][4];
#pragma unroll
    for (int i = 0; i < 4; i++)
#pragma unroll
        for (int j = 0; j < 4; j++)
#pragma unroll
            for (int q = 0; q < 4; q++) acc[i][j][q] = 0.0f;

    gemm_mainloop128(Ahi, Alo, Bhi, Blo, row0, col0, smem, acc);

    const int tid  = threadIdx.x;
    const int wid  = tid >> 5;
    const int lane = tid & 31;
    const int wm = wid >> 2, wn = wid & 3;
    const int g = lane >> 2, t = lane & 3;
#pragma unroll
    for (int i = 0; i < 4; i++)
#pragma unroll
        for (int j = 0; j < 4; j++) {
            int row = row0 + wm * 64 + i * 16 + g;
            int col = col0 + wn * 32 + j * 8 + 2 * t;
            *(float2*)&C[(size_t)row * D_ + col] =
                make_float2(acc[i][j][0], acc[i][j][1]);
            *(float2*)&C[(size_t)(row + 8) * D_ + col] =
                make_float2(acc[i][j][2], acc[i][j][3]);
        }
}

// ---------------------------------------------------------------------------
// HMMA flash attention, BMA=64, 4 warps, 96KB smem -> 2 CTAs/SM.
// cp.async-pipelined K/V (temporal single-buffering), contiguous live range,
// reversed qt order. Split-bf16 3-term MMA for S and PV.
// ---------------------------------------------------------------------------
#define BMA 64
#define BNA 64
#define ASMEM_BYTES 98304

__global__ __launch_bounds__(128, 2) void attn_hmma(
    const bf16* __restrict__ Qhi, const bf16* __restrict__ Qlo,
    const bf16* __restrict__ Khi, const bf16* __restrict__ Klo,
    const bf16* __restrict__ Vhi, const bf16* __restrict__ Vlo,
    const int* __restrict__ doc,
    bf16* __restrict__ Ahi, bf16* __restrict__ Alo)
{
    extern __shared__ char smem[];
    const uint32_t sQh = smem_u32(smem);
    const uint32_t sQl = sQh + 16384;
    const uint32_t sKh = sQh + 32768;
    const uint32_t sKl = sQh + 49152;
    const uint32_t sVh = sQh + 65536;
    const uint32_t sVl = sQh + 81920;
    __shared__ int qdoc[BMA];

    const int h = blockIdx.y;
    const int qt = (int)(gridDim.x - 1 - blockIdx.x);   // heavy tiles first
    const int qbase = qt * BMA;
    const int tid = threadIdx.x;
    const int wid = tid >> 5;
    const int lane = tid & 31;
    const int g = lane >> 2;
    const int t = lane & 3;
    const int r0 = wid * 16;
    const float scale = 0.08838834764831845f;

    const int qd_first = doc[qbase];

    // Contiguous live range: doc[] sorted => predicate monotone in kt.
    int kt0 = 0;
    while (doc[kt0 * BNA + BNA - 1] < qd_first) kt0++;

    // cp.async loaders: K pair / V pair, one commit group each.
    // Per matrix: 64 rows x 256B = 16KB = 1024 x 16B chunks; pair = 2048.
    auto load_K = [&](int kt) {
        const bf16* srcs[2] = {Khi, Klo};
#pragma unroll
        for (int j = 0; j < 16; j++) {
            int i = tid + (j << 7);          // 0..2047
            int m = i >> 10;
            int idx = i & 1023;
            int r = idx >> 4;                // 0..63
            int cb = (idx & 15) << 4;        // 0..240
            size_t gidx = (size_t)(kt * BNA + r) * D_ + h * HD_ + (cb >> 1);
            uint32_t off = (uint32_t)(r * 256) + (cb ^ ((r & 7) << 4));
            CPA16((m ? sKl : sKh) + off, (const char*)&srcs[m][gidx]);
        }
        CPA_COMMIT();
    };
    auto load_V = [&](int kt) {
        const bf16* srcs[2] = {Vhi, Vlo};
#pragma unroll
        for (int j = 0; j < 16; j++) {
            int i = tid + (j << 7);
            int m = i >> 10;
            int idx = i & 1023;
            int r = idx >> 4;
            int cb = (idx & 15) << 4;
            size_t gidx = (size_t)(kt * BNA + r) * D_ + h * HD_ + (cb >> 1);
            uint32_t off = (uint32_t)(r * 256) + (cb ^ ((r & 7) << 4));
            CPA16((m ? sVl : sVh) + off, (const char*)&srcs[m][gidx]);
        }
        CPA_COMMIT();
    };

    load_K(kt0);
    load_V(kt0);

    // Q tiles (sync loads, overlap the cp.async above).
    for (int i = tid; i < BMA * 16; i += 128) {
        int r = i >> 4;
        int cb = (i & 15) << 4;
        size_t gidx = (size_t)(qbase + r) * D_ + h * HD_ + (cb >> 1);
        uint32_t off = (uint32_t)(r * 256) + (cb ^ ((r & 7) << 4));
        *(uint4*)(smem + off)         = *(const uint4*)&Qhi[gidx];
        *(uint4*)(smem + 16384 + off) = *(const uint4*)&Qlo[gidx];
    }
    if (tid < BMA) qdoc[tid] = doc[qbase + tid];
    __syncthreads();

    float oacc[16][4];
#pragma unroll
    for (int nt = 0; nt < 16; nt++)
#pragma unroll
        for (int q = 0; q < 4; q++) oacc[nt][q] = 0.0f;

    float m0 = -1e30f, m1 = -1e30f, l0 = 0.0f, l1 = 0.0f;
    const int qr0 = qbase + r0 + g;
    const int qr1 = qr0 + 8;
    const int dq0 = qdoc[r0 + g];
    const int dq1 = qdoc[r0 + g + 8];

    for (int kt = kt0; kt <= qt; kt++) {
        const int kbase = kt * BNA;
        const bool more = (kt < qt);

        // K(kt) ready (V(kt) may still be in flight).
        CPA_WAIT(1);
        __syncthreads();

        // --- S = Q K^T ---
        float sacc[8][4];
#pragma unroll
        for (int nt = 0; nt < 8; nt++)
#pragma unroll
            for (int q = 0; q < 4; q++) sacc[nt][q] = 0.0f;

#pragma unroll
        for (int ks = 0; ks < 8; ks++) {
            uint32_t qh[4], ql[4];
            {
                int row = r0 + (lane & 15);
                int cb = ks * 32 + ((lane >> 4) & 1) * 16;
                uint32_t off = (uint32_t)(row * 256) + (cb ^ ((row & 7) << 4));
                ldsm_x4(qh, sQh + off);
                ldsm_x4(ql, sQl + off);
            }
#pragma unroll
            for (int jp = 0; jp < 4; jp++) {
                uint32_t kh[4], kl[4];
                int row = jp * 16 + ((lane >> 4) & 1) * 8 + (lane & 7);
                int cb = ks * 32 + ((lane >> 3) & 1) * 16;
                uint32_t off = (uint32_t)(row * 256) + (cb ^ ((row & 7) << 4));
                ldsm_x4(kh, sKh + off);
                ldsm_x4(kl, sKl + off);
                mma_bf16(sacc[2 * jp],     qh, &kh[0]);
                mma_bf16(sacc[2 * jp],     ql, &kh[0]);
                mma_bf16(sacc[2 * jp],     qh, &kl[0]);
                mma_bf16(sacc[2 * jp + 1], qh, &kh[2]);
                mma_bf16(sacc[2 * jp + 1], ql, &kh[2]);
                mma_bf16(sacc[2 * jp + 1], qh, &kl[2]);
            }
        }

        // sK consumed -> prefetch K(kt+1) (overlaps softmax + PV).
        __syncthreads();
        if (more) load_K(kt + 1);

        // --- scale + mask (kdoc via L2-hot gmem reads) ---
#pragma unroll
        for (int nt = 0; nt < 8; nt++) {
#pragma unroll
            for (int e = 0; e < 2; e++) {
                int col = nt * 8 + 2 * t + e;
                int kc = kbase + col;
                int kd = doc[kc];
                float v0 = sacc[nt][e] * scale;
                float v1 = sacc[nt][2 + e] * scale;
                sacc[nt][e]     = (kc <= qr0 && kd == dq0) ? v0 : -1e30f;
                sacc[nt][2 + e] = (kc <= qr1 && kd == dq1) ? v1 : -1e30f;
            }
        }

        // --- online softmax ---
        float mr0 = -1e30f, mr1 = -1e30f;
#pragma unroll
        for (int nt = 0; nt < 8; nt++) {
            mr0 = fmaxf(mr0, fmaxf(sacc[nt][0], sacc[nt][1]));
            mr1 = fmaxf(mr1, fmaxf(sacc[nt][2], sacc[nt][3]));
        }
        mr0 = fmaxf(mr0, __shfl_xor_sync(0xffffffffu, mr0, 1));
        mr0 = fmaxf(mr0, __shfl_xor_sync(0xffffffffu, mr0, 2));
        mr1 = fmaxf(mr1, __shfl_xor_sync(0xffffffffu, mr1, 1));
        mr1 = fmaxf(mr1, __shfl_xor_sync(0xffffffffu, mr1, 2));
        float mn0 = fmaxf(m0, mr0), mn1 = fmaxf(m1, mr1);
        float rs0 = __expf(m0 - mn0), rs1 = __expf(m1 - mn1);
        float s0 = 0.0f, s1 = 0.0f;
#pragma unroll
        for (int nt = 0; nt < 8; nt++) {
#pragma unroll
            for (int e = 0; e < 2; e++) {
                float a = sacc[nt][e];
                a = (a <= -1e29f) ? 0.0f : __expf(a - mn0);
                sacc[nt][e] = a; s0 += a;
                float b = sacc[nt][2 + e];
                b = (b <= -1e29f) ? 0.0f : __expf(b - mn1);
                sacc[nt][2 + e] = b; s1 += b;
            }
        }
        s0 += __shfl_xor_sync(0xffffffffu, s0, 1);
        s0 += __shfl_xor_sync(0xffffffffu, s0, 2);
        s1 += __shfl_xor_sync(0xffffffffu, s1, 1);
        s1 += __shfl_xor_sync(0xffffffffu, s1, 2);
        l0 = l0 * rs0 + s0; m0 = mn0;
        l1 = l1 * rs1 + s1; m1 = mn1;

#pragma unroll
        for (int nt = 0; nt < 16; nt++) {
            oacc[nt][0] *= rs0; oacc[nt][1] *= rs0;
            oacc[nt][2] *= rs1; oacc[nt][3] *= rs1;
        }

        // V(kt) ready (K(kt+1) may be in flight).
        if (more) { CPA_WAIT(1); } else { CPA_WAIT(0); }
        __syncthreads();

        // --- O += P V ---
#pragma unroll
        for (int ks = 0; ks < 4; ks++) {
            float p00 = sacc[2 * ks][0],     p01 = sacc[2 * ks][1];
            float p02 = sacc[2 * ks][2],     p03 = sacc[2 * ks][3];
            float p10 = sacc[2 * ks + 1][0], p11 = sacc[2 * ks + 1][1];
            float p12 = sacc[2 * ks + 1][2], p13 = sacc[2 * ks + 1][3];
            uint32_t phi[4], plo[4];
            phi[0] = packbf(p00, p01); phi[1] = packbf(p02, p03);
            phi[2] = packbf(p10, p11); phi[3] = packbf(p12, p13);
            plo[0] = packbf(p00 - bfround(p00), p01 - bfround(p01));
            plo[1] = packbf(p02 - bfround(p02), p03 - bfround(p03));
            plo[2] = packbf(p10 - bfround(p10), p11 - bfround(p11));
            plo[3] = packbf(p12 - bfround(p12), p13 - bfround(p13));

#pragma unroll
            for (int n0 = 0; n0 < 128; n0 += 16) {
                uint32_t vh[4], vl[4];
                int row = ks * 16 + ((lane >> 3) & 1) * 8 + (lane & 7);
                int cb = n0 * 2 + ((lane >> 4) & 1) * 16;
                uint32_t off = (uint32_t)(row * 256) + (cb ^ ((row & 7) << 4));
                ldsm_x4_t(vh, sVh + off);
                ldsm_x4_t(vl, sVl + off);
                int nt = n0 >> 3;
                mma_bf16(oacc[nt],     phi, &vh[0]);
                mma_bf16(oacc[nt],     plo, &vh[0]);
                mma_bf16(oacc[nt],     phi, &vl[0]);
                mma_bf16(oacc[nt + 1], phi, &vh[2]);
                mma_bf16(oacc[nt + 1], plo, &vh[2]);
                mma_bf16(oacc[nt + 1], phi, &vl[2]);
            }
        }

        // sV consumed -> prefetch V(kt+1) (overlaps next S + softmax).
        __syncthreads();
        if (more) load_V(kt + 1);
    }

    float i0 = 1.0f / l0, i1 = 1.0f / l1;
#pragma unroll
    for (int nt = 0; nt < 16; nt++) {
        float v0 = oacc[nt][0] * i0, v1 = oacc[nt][1] * i0;
        float v2 = oacc[nt][2] * i1, v3 = oacc[nt][3] * i1;
        size_t idx0 = (size_t)qr0 * D_ + h * HD_ + nt * 8 + 2 * t;
        size_t idx1 = idx0 + (size_t)8 * D_;
        *(uint32_t*)&Ahi[idx0] = packbf(v0, v1);
        *(uint32_t*)&Alo[idx0] = packbf(v0 - bfround(v0), v1 - bfround(v1));
        *(uint32_t*)&Ahi[idx1] = packbf(v2, v3);
        *(uint32_t*)&Alo[idx1] = packbf(v2 - bfround(v2), v3 - bfround(v3));
    }
}

// ---------------------------------------------------------------------------
// Launch
// ---------------------------------------------------------------------------
extern "C" void kernel_launch(void* const* d_in, const int* in_sizes, int n_in,
                              void* d_out, int out_size)
{
    const float* x    = (const float*)d_in[0];
    const float* Wq   = (const float*)d_in[1];
    const float* Wk   = (const float*)d_in[2];
    const float* Wv   = (const float*)d_in[3];
    const float* Wo   = (const float*)d_in[4];
    const float* sint = (const float*)d_in[5];
    const float* cost = (const float*)d_in[6];
    const int*   doc  = (const int*)d_in[7];

    bf16 *xhi, *xlo, *Ahi, *Alo, *Wthi, *Wtlo;
    bf16 *Qhi, *Qlo, *Khi, *Klo, *Vhi, *Vlo;
    cudaGetSymbolAddress((void**)&xhi, g_xhi);
    cudaGetSymbolAddress((void**)&xlo, g_xlo);
    cudaGetSymbolAddress((void**)&Ahi, g_Ahi);
    cudaGetSymbolAddress((void**)&Alo, g_Alo);
    cudaGetSymbolAddress((void**)&Qhi, g_Qhi);
    cudaGetSymbolAddress((void**)&Qlo, g_Qlo);
    cudaGetSymbolAddress((void**)&Khi, g_Khi);
    cudaGetSymbolAddress((void**)&Klo, g_Klo);
    cudaGetSymbolAddress((void**)&Vhi, g_Vhi);
    cudaGetSymbolAddress((void**)&Vlo, g_Vlo);
    cudaGetSymbolAddress((void**)&Wthi, g_Wthi);
    cudaGetSymbolAddress((void**)&Wtlo, g_Wtlo);

    const size_t WSZ = (size_t)D_ * D_;
    const int NELEM = T_ * D_;

    split_kernel<<<(NELEM + 255) / 256, 256>>>(x, xhi, xlo);
    dim3 tsGrid(D_ / 32, D_ / 32, 4), tsBlk(32, 8);
    transpose_split4<<<tsGrid, tsBlk>>>(Wq, Wk, Wv, Wo, Wthi, Wtlo);

    cudaFuncSetAttribute(gemm_qkv,
                         cudaFuncAttributeMaxDynamicSharedMemorySize, GSMEM_BYTES);
    cudaFuncSetAttribute(gemm_out,
                         cudaFuncAttributeMaxDynamicSharedMemorySize, GSMEM_BYTES);

    dim3 gGridQKV(D_ / 128, T_ / 128, 3);   // (16, 16, 3)
    gemm_qkv<<<gGridQKV, 256, GSMEM_BYTES>>>(xhi, xlo, Wthi, Wtlo, sint, cost,
                                             Qhi, Qlo, Khi, Klo, Vhi, Vlo);

    cudaFuncSetAttribute(attn_hmma,
                         cudaFuncAttributeMaxDynamicSharedMemorySize, ASMEM_BYTES);
    attn_hmma<<<dim3(T_ / BMA, H_), 128, ASMEM_BYTES>>>(
        Qhi, Qlo, Khi, Klo, Vhi, Vlo, doc, Ahi, Alo);

    dim3 gGridO(D_ / 128, T_ / 128, 1);     // (16, 16)
    gemm_out<<<gGridO, 256, GSMEM_BYTES>>>(Ahi, Alo, Wthi + 3 * WSZ, Wtlo + 3 * WSZ,
                                           (float*)d_out);
}

// round 13
// speedup vs baseline: 1.1208x; 1.0506x over previous
#include <cuda_runtime.h>
#include <cuda_bf16.h>
#include <cstdint>
#include <math.h>

#define T_  2048
#define D_  2048
#define H_  16
#define HD_ 128

typedef __nv_bfloat16 bf16;

// ---------------------------------------------------------------------------
// Scratch (allocation-free rule: __device__ globals)
// ---------------------------------------------------------------------------
__device__ bf16 g_xhi[T_ * D_];
__device__ bf16 g_xlo[T_ * D_];
__device__ float g_Af[T_ * D_];        // attention output, tf32-rounded fp32
__device__ bf16 g_Qhi[T_ * D_];
__device__ bf16 g_Qlo[T_ * D_];
__device__ bf16 g_Khi[T_ * D_];
__device__ bf16 g_Klo[T_ * D_];
__device__ bf16 g_Vhi[T_ * D_];
__device__ bf16 g_Vlo[T_ * D_];
__device__ bf16 g_Wthi[3][D_ * D_];    // transposed QKV weights [N,K], hi
__device__ bf16 g_Wtlo[3][D_ * D_];    // transposed QKV weights [N,K], lo
__device__ float g_Wotf[D_ * D_];      // transposed Wo [N,K], tf32-rounded

// ---------------------------------------------------------------------------
// PTX helpers (compute_103-safe: mma.sync / ldmatrix / cp.async only)
// ---------------------------------------------------------------------------
__device__ __forceinline__ uint32_t smem_u32(const void* p) {
    uint32_t a;
    asm("{ .reg .u64 t; cvta.to.shared.u64 t, %1; cvt.u32.u64 %0, t; }"
        : "=r"(a) : "l"(p));
    return a;
}

#define CPA16(dst, src) \
    asm volatile("cp.async.cg.shared.global [%0], [%1], 16;" :: "r"(dst), "l"(src) : "memory")
#define CPA_COMMIT() asm volatile("cp.async.commit_group;" ::: "memory")
#define CPA_WAIT(n)  asm volatile("cp.async.wait_group %0;" :: "n"(n) : "memory")

__device__ __forceinline__ void ldsm_x4(uint32_t* r, uint32_t addr) {
    asm volatile("ldmatrix.sync.aligned.m8n8.x4.shared.b16 {%0,%1,%2,%3}, [%4];"
                 : "=r"(r[0]), "=r"(r[1]), "=r"(r[2]), "=r"(r[3]) : "r"(addr));
}

__device__ __forceinline__ void ldsm_x4_t(uint32_t* r, uint32_t addr) {
    asm volatile("ldmatrix.sync.aligned.m8n8.x4.trans.shared.b16 {%0,%1,%2,%3}, [%4];"
                 : "=r"(r[0]), "=r"(r[1]), "=r"(r[2]), "=r"(r[3]) : "r"(addr));
}

__device__ __forceinline__ void mma_bf16(float* d, const uint32_t* a,
                                         const uint32_t* b) {
    asm volatile(
        "mma.sync.aligned.m16n8k16.row.col.f32.bf16.bf16.f32 "
        "{%0,%1,%2,%3}, {%4,%5,%6,%7}, {%8,%9}, {%0,%1,%2,%3};"
        : "+f"(d[0]), "+f"(d[1]), "+f"(d[2]), "+f"(d[3])
        : "r"(a[0]), "r"(a[1]), "r"(a[2]), "r"(a[3]), "r"(b[0]), "r"(b[1]));
}

__device__ __forceinline__ void mma_tf32(float* d, const uint32_t* a,
                                         const uint32_t* b) {
    asm volatile(
        "mma.sync.aligned.m16n8k8.row.col.f32.tf32.tf32.f32 "
        "{%0,%1,%2,%3}, {%4,%5,%6,%7}, {%8,%9}, {%0,%1,%2,%3};"
        : "+f"(d[0]), "+f"(d[1]), "+f"(d[2]), "+f"(d[3])
        : "r"(a[0]), "r"(a[1]), "r"(a[2]), "r"(a[3]), "r"(b[0]), "r"(b[1]));
}

__device__ __forceinline__ uint32_t packbf(float lo, float hi) {
    uint32_t r;
    asm("cvt.rn.bf16x2.f32 %0, %1, %2;" : "=r"(r) : "f"(hi), "f"(lo));
    return r;
}

__device__ __forceinline__ float bfround(float v) {
    return __bfloat162float(__float2bfloat16(v));
}

// Round-to-nearest tf32 (rna) — required so tf32 MMA inputs carry zero-mean
// quantization error (truncation would bias the K=2048 accumulation).
__device__ __forceinline__ float tf32r(float v) {
    uint32_t r;
    asm("cvt.rna.tf32.f32 %0, %1;" : "=r"(r) : "f"(v));
    return __uint_as_float(r);
}

// ---------------------------------------------------------------------------
// Split fp32 -> (hi, lo) bf16, row-major
// ---------------------------------------------------------------------------
__global__ __launch_bounds__(256) void split_kernel(const float* __restrict__ src,
                                                    bf16* __restrict__ hi,
                                                    bf16* __restrict__ lo)
{
    int i = blockIdx.x * 256 + threadIdx.x;
    if (i >= T_ * D_) return;
    float v = src[i];
    bf16 h = __float2bfloat16(v);
    float r = v - __bfloat162float(h);
    hi[i] = h;
    lo[i] = __float2bfloat16(r);
}

// ---------------------------------------------------------------------------
// Transpose + split QKV weights (z=0..2): W[K,N] -> Thi/Tlo[N,K] bf16.
// ---------------------------------------------------------------------------
__global__ __launch_bounds__(256) void transpose_split3(
    const float* __restrict__ W0, const float* __restrict__ W1,
    const float* __restrict__ W2,
    bf16* __restrict__ ThiB, bf16* __restrict__ TloB)
{
    __shared__ float tile[32][33];
    const size_t WSZ = (size_t)D_ * D_;
    int z = blockIdx.z;
    const float* W = (z == 0) ? W0 : (z == 1) ? W1 : W2;
    bf16* Thi = ThiB + z * WSZ;
    bf16* Tlo = TloB + z * WSZ;

    int bx = blockIdx.x * 32;
    int by = blockIdx.y * 32;
    int tx = threadIdx.x;
    int ty = threadIdx.y;
#pragma unroll
    for (int j = 0; j < 32; j += 8)
        tile[ty + j][tx] = W[(size_t)(by + ty + j) * D_ + bx + tx];
    __syncthreads();
#pragma unroll
    for (int j = 0; j < 32; j += 8) {
        float v = tile[tx][ty + j];
        bf16 h = __float2bfloat16(v);
        float r = v - __bfloat162float(h);
        size_t o = (size_t)(bx + ty + j) * D_ + by + tx;
        Thi[o] = h;
        Tlo[o] = __float2bfloat16(r);
    }
}

// ---------------------------------------------------------------------------
// Transpose Wo: W[K,N] fp32 -> T[N,K] fp32, tf32-rounded.
// ---------------------------------------------------------------------------
__global__ __launch_bounds__(256) void transpose_tf32(
    const float* __restrict__ W, float* __restrict__ Tt)
{
    __shared__ float tile[32][33];
    int bx = blockIdx.x * 32;
    int by = blockIdx.y * 32;
    int tx = threadIdx.x;
    int ty = threadIdx.y;
#pragma unroll
    for (int j = 0; j < 32; j += 8)
        tile[ty + j][tx] = W[(size_t)(by + ty + j) * D_ + bx + tx];
    __syncthreads();
#pragma unroll
    for (int j = 0; j < 32; j += 8)
        Tt[(size_t)(bx + ty + j) * D_ + by + tx] = tf32r(tile[tx][ty + j]);
}

// ---------------------------------------------------------------------------
// GEMM mainloop (proven config, FROZEN): CTA tile 128x128, warp tile 64x32,
// BK=64 bf16, 3-stage cp.async, single sync per chunk, split-bf16 3-MMA.
// ---------------------------------------------------------------------------
#define STAGE_BYTES 65536
#define GSMEM_BYTES (3 * STAGE_BYTES)

__device__ __forceinline__ void gemm_mainloop128(
    const bf16* __restrict__ Ahi, const bf16* __restrict__ Alo,
    const bf16* __restrict__ Bhi, const bf16* __restrict__ Blo,
    int row0, int col0, char* smem, float acc[4][4][4])
{
    uint32_t sb = smem_u32(smem);
    const int tid  = threadIdx.x;
    const int wid  = tid >> 5;
    const int lane = tid & 31;
    const int wm = wid >> 2;
    const int wn = wid & 3;

    const char* base[4] = {
        (const char*)(Ahi + (size_t)row0 * D_),
        (const char*)(Alo + (size_t)row0 * D_),
        (const char*)(Bhi + (size_t)col0 * D_),
        (const char*)(Blo + (size_t)col0 * D_)
    };

    auto load_stage = [&](int c, int s) {
        uint32_t st = sb + s * STAGE_BYTES;
#pragma unroll
        for (int j = 0; j < 16; j++) {
            int m = j >> 2;
            int rem = tid + ((j & 3) << 8);
            int r = rem >> 3;
            int cb = (rem & 7) << 4;
            const char* src = base[m] + (size_t)r * (D_ * 2) + c * 128 + cb;
            uint32_t off = (uint32_t)(r * 128) + (cb ^ ((r & 7) << 4));
            CPA16(st + m * 16384 + off, src);
        }
        CPA_COMMIT();
    };

    load_stage(0, 0);
    load_stage(1, 1);

    for (int c = 0; c < 32; c++) {
        if (c < 31) CPA_WAIT(1);
        else        CPA_WAIT(0);
        __syncthreads();
        if (c + 2 < 32) load_stage(c + 2, (c + 2) % 3);

        uint32_t st   = sb + (c % 3) * STAGE_BYTES;
        uint32_t sAhi = st;
        uint32_t sAlo = st + 16384;
        uint32_t sBhi = st + 32768;
        uint32_t sBlo = st + 49152;

#pragma unroll
        for (int ks = 0; ks < 4; ks++) {
            uint32_t ah[4][4], al[4][4];
#pragma unroll
            for (int i = 0; i < 4; i++) {
                int row = wm * 64 + i * 16 + (lane & 15);
                uint32_t colb = ks * 32 + ((lane >> 4) & 1) * 16;
                uint32_t off = (uint32_t)(row * 128) + (colb ^ ((row & 7) << 4));
                ldsm_x4(ah[i], sAhi + off);
                ldsm_x4(al[i], sAlo + off);
            }
            uint32_t bh[8], bl[8];
#pragma unroll
            for (int jp = 0; jp < 2; jp++) {
                int row = wn * 32 + jp * 16 + ((lane >> 4) & 1) * 8 + (lane & 7);
                uint32_t colb = ks * 32 + ((lane >> 3) & 1) * 16;
                uint32_t off = (uint32_t)(row * 128) + (colb ^ ((row & 7) << 4));
                ldsm_x4(&bh[jp * 4], sBhi + off);
                ldsm_x4(&bl[jp * 4], sBlo + off);
            }
#pragma unroll
            for (int i = 0; i < 4; i++)
#pragma unroll
                for (int j = 0; j < 4; j++) {
                    mma_bf16(acc[i][j], ah[i], &bh[j * 2]);
                    mma_bf16(acc[i][j], al[i], &bh[j * 2]);
                    mma_bf16(acc[i][j], ah[i], &bl[j * 2]);
                }
        }
    }
}

// ---------------------------------------------------------------------------
// QKV GEMM with fused RoPE (z<2) + split-bf16 epilogue via smem staging.
// ---------------------------------------------------------------------------
#define LDC 132

__global__ __launch_bounds__(256) void gemm_qkv(
    const bf16* __restrict__ xhi, const bf16* __restrict__ xlo,
    const bf16* __restrict__ Wthi, const bf16* __restrict__ Wtlo,
    const float* __restrict__ sint, const float* __restrict__ cost,
    bf16* __restrict__ Qhi, bf16* __restrict__ Qlo,
    bf16* __restrict__ Khi, bf16* __restrict__ Klo,
    bf16* __restrict__ Vhi, bf16* __restrict__ Vlo)
{
    extern __shared__ char smem[];
    const int z = blockIdx.z;
    const int row0 = blockIdx.y * 128;
    const int col0 = blockIdx.x * 128;
    const size_t WSZ = (size_t)D_ * D_;

    float acc[4][4][4];
#pragma unroll
    for (int i = 0; i < 4; i++)
#pragma unroll
        for (int j = 0; j < 4; j++)
#pragma unroll
            for (int q = 0; q < 4; q++) acc[i][j][q] = 0.0f;

    gemm_mainloop128(xhi, xlo, Wthi + z * WSZ, Wtlo + z * WSZ, row0, col0,
                     smem, acc);

    __syncthreads();
    float* sC = (float*)smem;
    const int tid  = threadIdx.x;
    const int wid  = tid >> 5;
    const int lane = tid & 31;
    const int wm = wid >> 2, wn = wid & 3;
    const int g = lane >> 2, t = lane & 3;
#pragma unroll
    for (int i = 0; i < 4; i++)
#pragma unroll
        for (int j = 0; j < 4; j++) {
            int row = wm * 64 + i * 16 + g;
            int col = wn * 32 + j * 8 + 2 * t;
            *(float2*)&sC[row * LDC + col] = make_float2(acc[i][j][0], acc[i][j][1]);
            *(float2*)&sC[(row + 8) * LDC + col] = make_float2(acc[i][j][2], acc[i][j][3]);
        }
    __syncthreads();

    bf16* Ohi = (z == 0) ? Qhi : (z == 1) ? Khi : Vhi;
    bf16* Olo = (z == 0) ? Qlo : (z == 1) ? Klo : Vlo;
    const bool dorope = (z < 2);

#pragma unroll 4
    for (int it = 0; it < 32; it++) {
        int idx = it * 256 + tid;
        int r = idx >> 6;
        int d = idx & 63;
        float v1 = sC[r * LDC + d];
        float v2 = sC[r * LDC + d + 64];
        int tg = row0 + r;
        float o1 = v1, o2 = v2;
        if (dorope) {
            float s1 = sint[tg * HD_ + d],      c1 = cost[tg * HD_ + d];
            float s2 = sint[tg * HD_ + d + 64], c2 = cost[tg * HD_ + d + 64];
            o1 = v1 * c1 - v2 * s1;
            o2 = v2 * c2 + v1 * s2;
        }
        size_t gi = (size_t)tg * D_ + col0 + d;
        Ohi[gi]      = __float2bfloat16(o1);
        Olo[gi]      = __float2bfloat16(o1 - bfround(o1));
        Ohi[gi + 64] = __float2bfloat16(o2);
        Olo[gi + 64] = __float2bfloat16(o2 - bfround(o2));
    }
}

// ---------------------------------------------------------------------------
// O-projection GEMM, single-pass tf32: C = A @ Bt^T, A/Bt fp32 tf32-rounded.
// Same skeleton as bf16 mainloop: 128x128 tile, BK=64 fp32 (256B rows),
// 3 stages x 64KB, single sync per chunk. Fragments are byte-compatible:
// ldsm.x4 on fp32 tiles yields exact tf32 m16n8k8 A/B fragments.
// ---------------------------------------------------------------------------
__global__ __launch_bounds__(256) void gemm_out_tf32(
    const float* __restrict__ A, const float* __restrict__ Bt,
    float* __restrict__ C)
{
    extern __shared__ char smem[];
    uint32_t sb = smem_u32(smem);
    const int tid  = threadIdx.x;
    const int wid  = tid >> 5;
    const int lane = tid & 31;
    const int wm = wid >> 2;
    const int wn = wid & 3;
    const int row0 = blockIdx.y * 128;
    const int col0 = blockIdx.x * 128;

    const char* baseA = (const char*)(A  + (size_t)row0 * D_);
    const char* baseB = (const char*)(Bt + (size_t)col0 * D_);

    auto load_stage = [&](int c, int s) {
        uint32_t st = sb + s * STAGE_BYTES;
#pragma unroll
        for (int j = 0; j < 16; j++) {
            int m = j >> 3;                  // 0=A, 1=B
            int q = tid + ((j & 7) << 8);    // 0..2047
            int r = q >> 4;                  // row 0..127
            int cb = (q & 15) << 4;          // byte col 0..240
            const char* src = (m ? baseB : baseA)
                              + (size_t)r * (D_ * 4) + c * 256 + cb;
            uint32_t off = (uint32_t)(r * 256) + (cb ^ ((r & 7) << 4));
            CPA16(st + m * 32768 + off, src);
        }
        CPA_COMMIT();
    };

    float acc[4][4][4];
#pragma unroll
    for (int i = 0; i < 4; i++)
#pragma unroll
        for (int j = 0; j < 4; j++)
#pragma unroll
            for (int q = 0; q < 4; q++) acc[i][j][q] = 0.0f;

    load_stage(0, 0);
    load_stage(1, 1);

    for (int c = 0; c < 32; c++) {
        if (c < 31) CPA_WAIT(1);
        else        CPA_WAIT(0);
        __syncthreads();
        if (c + 2 < 32) load_stage(c + 2, (c + 2) % 3);

        uint32_t st = sb + (c % 3) * STAGE_BYTES;
        uint32_t sA = st;
        uint32_t sB = st + 32768;

#pragma unroll
        for (int kg = 0; kg < 8; kg++) {
            uint32_t a[4][4];
#pragma unroll
            for (int i = 0; i < 4; i++) {
                int row = wm * 64 + i * 16 + (lane & 15);
                uint32_t cb = kg * 32 + ((lane >> 4) & 1) * 16;
                uint32_t off = (uint32_t)(row * 256) + (cb ^ ((row & 7) << 4));
                ldsm_x4(a[i], sA + off);
            }
#pragma unroll
            for (int jp = 0; jp < 2; jp++) {
                uint32_t b[4];
                int row = wn * 32 + jp * 16 + ((lane >> 4) & 1) * 8 + (lane & 7);
                uint32_t cb = kg * 32 + ((lane >> 3) & 1) * 16;
                uint32_t off = (uint32_t)(row * 256) + (cb ^ ((row & 7) << 4));
                ldsm_x4(b, sB + off);
#pragma unroll
                for (int i = 0; i < 4; i++) {
                    mma_tf32(acc[i][2 * jp],     a[i], &b[0]);
                    mma_tf32(acc[i][2 * jp + 1], a[i], &b[2]);
                }
            }
        }
    }

    const int g = lane >> 2;
    const int t = lane & 3;
#pragma unroll
    for (int i = 0; i < 4; i++)
#pragma unroll
        for (int j = 0; j < 4; j++) {
            int row = row0 + wm * 64 + i * 16 + g;
            int col = col0 + wn * 32 + j * 8 + 2 * t;
            *(float2*)&C[(size_t)row * D_ + col] =
                make_float2(acc[i][j][0], acc[i][j][1]);
            *(float2*)&C[(size_t)(row + 8) * D_ + col] =
                make_float2(acc[i][j][2], acc[i][j][3]);
        }
}

// ---------------------------------------------------------------------------
// HMMA flash attention (FROZEN core), BMA=64, 4 warps, 96KB smem, 2 CTAs/SM.
// Epilogue now writes tf32-rounded fp32 to g_Af (feeds tf32 O-proj).
// ---------------------------------------------------------------------------
#define BMA 64
#define BNA 64
#define ASMEM_BYTES 98304

__global__ __launch_bounds__(128, 2) void attn_hmma(
    const bf16* __restrict__ Qhi, const bf16* __restrict__ Qlo,
    const bf16* __restrict__ Khi, const bf16* __restrict__ Klo,
    const bf16* __restrict__ Vhi, const bf16* __restrict__ Vlo,
    const int* __restrict__ doc,
    float* __restrict__ Af)
{
    extern __shared__ char smem[];
    const uint32_t sQh = smem_u32(smem);
    const uint32_t sQl = sQh + 16384;
    const uint32_t sKh = sQh + 32768;
    const uint32_t sKl = sQh + 49152;
    const uint32_t sVh = sQh + 65536;
    const uint32_t sVl = sQh + 81920;
    __shared__ int qdoc[BMA];

    const int h = blockIdx.y;
    const int qt = (int)(gridDim.x - 1 - blockIdx.x);
    const int qbase = qt * BMA;
    const int tid = threadIdx.x;
    const int wid = tid >> 5;
    const int lane = tid & 31;
    const int g = lane >> 2;
    const int t = lane & 3;
    const int r0 = wid * 16;
    const float scale = 0.08838834764831845f;

    const int qd_first = doc[qbase];

    int kt0 = 0;
    while (doc[kt0 * BNA + BNA - 1] < qd_first) kt0++;

    auto load_K = [&](int kt) {
        const bf16* srcs[2] = {Khi, Klo};
#pragma unroll
        for (int j = 0; j < 16; j++) {
            int i = tid + (j << 7);
            int m = i >> 10;
            int idx = i & 1023;
            int r = idx >> 4;
            int cb = (idx & 15) << 4;
            size_t gidx = (size_t)(kt * BNA + r) * D_ + h * HD_ + (cb >> 1);
            uint32_t off = (uint32_t)(r * 256) + (cb ^ ((r & 7) << 4));
            CPA16((m ? sKl : sKh) + off, (const char*)&srcs[m][gidx]);
        }
        CPA_COMMIT();
    };
    auto load_V = [&](int kt) {
        const bf16* srcs[2] = {Vhi, Vlo};
#pragma unroll
        for (int j = 0; j < 16; j++) {
            int i = tid + (j << 7);
            int m = i >> 10;
            int idx = i & 1023;
            int r = idx >> 4;
            int cb = (idx & 15) << 4;
            size_t gidx = (size_t)(kt * BNA + r) * D_ + h * HD_ + (cb >> 1);
            uint32_t off = (uint32_t)(r * 256) + (cb ^ ((r & 7) << 4));
            CPA16((m ? sVl : sVh) + off, (const char*)&srcs[m][gidx]);
        }
        CPA_COMMIT();
    };

    load_K(kt0);
    load_V(kt0);

    for (int i = tid; i < BMA * 16; i += 128) {
        int r = i >> 4;
        int cb = (i & 15) << 4;
        size_t gidx = (size_t)(qbase + r) * D_ + h * HD_ + (cb >> 1);
        uint32_t off = (uint32_t)(r * 256) + (cb ^ ((r & 7) << 4));
        *(uint4*)(smem + off)         = *(const uint4*)&Qhi[gidx];
        *(uint4*)(smem + 16384 + off) = *(const uint4*)&Qlo[gidx];
    }
    if (tid < BMA) qdoc[tid] = doc[qbase + tid];
    __syncthreads();

    float oacc[16][4];
#pragma unroll
    for (int nt = 0; nt < 16; nt++)
#pragma unroll
        for (int q = 0; q < 4; q++) oacc[nt][q] = 0.0f;

    float m0 = -1e30f, m1 = -1e30f, l0 = 0.0f, l1 = 0.0f;
    const int qr0 = qbase + r0 + g;
    const int qr1 = qr0 + 8;
    const int dq0 = qdoc[r0 + g];
    const int dq1 = qdoc[r0 + g + 8];

    for (int kt = kt0; kt <= qt; kt++) {
        const int kbase = kt * BNA;
        const bool more = (kt < qt);

        CPA_WAIT(1);
        __syncthreads();

        float sacc[8][4];
#pragma unroll
        for (int nt = 0; nt < 8; nt++)
#pragma unroll
            for (int q = 0; q < 4; q++) sacc[nt][q] = 0.0f;

#pragma unroll
        for (int ks = 0; ks < 8; ks++) {
            uint32_t qh[4], ql[4];
            {
                int row = r0 + (lane & 15);
                int cb = ks * 32 + ((lane >> 4) & 1) * 16;
                uint32_t off = (uint32_t)(row * 256) + (cb ^ ((row & 7) << 4));
                ldsm_x4(qh, sQh + off);
                ldsm_x4(ql, sQl + off);
            }
#pragma unroll
            for (int jp = 0; jp < 4; jp++) {
                uint32_t kh[4], kl[4];
                int row = jp * 16 + ((lane >> 4) & 1) * 8 + (lane & 7);
                int cb = ks * 32 + ((lane >> 3) & 1) * 16;
                uint32_t off = (uint32_t)(row * 256) + (cb ^ ((row & 7) << 4));
                ldsm_x4(kh, sKh + off);
                ldsm_x4(kl, sKl + off);
                mma_bf16(sacc[2 * jp],     qh, &kh[0]);
                mma_bf16(sacc[2 * jp],     ql, &kh[0]);
                mma_bf16(sacc[2 * jp],     qh, &kl[0]);
                mma_bf16(sacc[2 * jp + 1], qh, &kh[2]);
                mma_bf16(sacc[2 * jp + 1], ql, &kh[2]);
                mma_bf16(sacc[2 * jp + 1], qh, &kl[2]);
            }
        }

        __syncthreads();
        if (more) load_K(kt + 1);

#pragma unroll
        for (int nt = 0; nt < 8; nt++) {
#pragma unroll
            for (int e = 0; e < 2; e++) {
                int col = nt * 8 + 2 * t + e;
                int kc = kbase + col;
                int kd = doc[kc];
                float v0 = sacc[nt][e] * scale;
                float v1 = sacc[nt][2 + e] * scale;
                sacc[nt][e]     = (kc <= qr0 && kd == dq0) ? v0 : -1e30f;
                sacc[nt][2 + e] = (kc <= qr1 && kd == dq1) ? v1 : -1e30f;
            }
        }

        float mr0 = -1e30f, mr1 = -1e30f;
#pragma unroll
        for (int nt = 0; nt < 8; nt++) {
            mr0 = fmaxf(mr0, fmaxf(sacc[nt][0], sacc[nt][1]));
            mr1 = fmaxf(mr1, fmaxf(sacc[nt][2], sacc[nt][3]));
        }
        mr0 = fmaxf(mr0, __shfl_xor_sync(0xffffffffu, mr0, 1));
        mr0 = fmaxf(mr0, __shfl_xor_sync(0xffffffffu, mr0, 2));
        mr1 = fmaxf(mr1, __shfl_xor_sync(0xffffffffu, mr1, 1));
        mr1 = fmaxf(mr1, __shfl_xor_sync(0xffffffffu, mr1, 2));
        float mn0 = fmaxf(m0, mr0), mn1 = fmaxf(m1, mr1);
        float rs0 = __expf(m0 - mn0), rs1 = __expf(m1 - mn1);
        float s0 = 0.0f, s1 = 0.0f;
#pragma unroll
        for (int nt = 0; nt < 8; nt++) {
#pragma unroll
            for (int e = 0; e < 2; e++) {
                float a = sacc[nt][e];
                a = (a <= -1e29f) ? 0.0f : __expf(a - mn0);
                sacc[nt][e] = a; s0 += a;
                float b = sacc[nt][2 + e];
                b = (b <= -1e29f) ? 0.0f : __expf(b - mn1);
                sacc[nt][2 + e] = b; s1 += b;
            }
        }
        s0 += __shfl_xor_sync(0xffffffffu, s0, 1);
        s0 += __shfl_xor_sync(0xffffffffu, s0, 2);
        s1 += __shfl_xor_sync(0xffffffffu, s1, 1);
        s1 += __shfl_xor_sync(0xffffffffu, s1, 2);
        l0 = l0 * rs0 + s0; m0 = mn0;
        l1 = l1 * rs1 + s1; m1 = mn1;

#pragma unroll
        for (int nt = 0; nt < 16; nt++) {
            oacc[nt][0] *= rs0; oacc[nt][1] *= rs0;
            oacc[nt][2] *= rs1; oacc[nt][3] *= rs1;
        }

        if (more) { CPA_WAIT(1); } else { CPA_WAIT(0); }
        __syncthreads();

#pragma unroll
        for (int ks = 0; ks < 4; ks++) {
            float p00 = sacc[2 * ks][0],     p01 = sacc[2 * ks][1];
            float p02 = sacc[2 * ks][2],     p03 = sacc[2 * ks][3];
            float p10 = sacc[2 * ks + 1][0], p11 = sacc[2 * ks + 1][1];
            float p12 = sacc[2 * ks + 1][2], p13 = sacc[2 * ks + 1][3];
            uint32_t phi[4], plo[4];
            phi[0] = packbf(p00, p01); phi[1] = packbf(p02, p03);
            phi[2] = packbf(p10, p11); phi[3] = packbf(p12, p13);
            plo[0] = packbf(p00 - bfround(p00), p01 - bfround(p01));
            plo[1] = packbf(p02 - bfround(p02), p03 - bfround(p03));
            plo[2] = packbf(p10 - bfround(p10), p11 - bfround(p11));
            plo[3] = packbf(p12 - bfround(p12), p13 - bfround(p13));

#pragma unroll
            for (int n0 = 0; n0 < 128; n0 += 16) {
                uint32_t vh[4], vl[4];
                int row = ks * 16 + ((lane >> 3) & 1) * 8 + (lane & 7);
                int cb = n0 * 2 + ((lane >> 4) & 1) * 16;
                uint32_t off = (uint32_t)(row * 256) + (cb ^ ((row & 7) << 4));
                ldsm_x4_t(vh, sVh + off);
                ldsm_x4_t(vl, sVl + off);
                int nt = n0 >> 3;
                mma_bf16(oacc[nt],     phi, &vh[0]);
                mma_bf16(oacc[nt],     plo, &vh[0]);
                mma_bf16(oacc[nt],     phi, &vl[0]);
                mma_bf16(oacc[nt + 1], phi, &vh[2]);
                mma_bf16(oacc[nt + 1], plo, &vh[2]);
                mma_bf16(oacc[nt + 1], phi, &vl[2]);
            }
        }

        __syncthreads();
        if (more) load_V(kt + 1);
    }

    // Epilogue: normalize, tf32-rounded fp32 write (feeds tf32 O-proj).
    float i0 = 1.0f / l0, i1 = 1.0f / l1;
#pragma unroll
    for (int nt = 0; nt < 16; nt++) {
        float v0 = oacc[nt][0] * i0, v1 = oacc[nt][1] * i0;
        float v2 = oacc[nt][2] * i1, v3 = oacc[nt][3] * i1;
        size_t idx0 = (size_t)qr0 * D_ + h * HD_ + nt * 8 + 2 * t;
        size_t idx1 = idx0 + (size_t)8 * D_;
        *(float2*)&Af[idx0] = make_float2(tf32r(v0), tf32r(v1));
        *(float2*)&Af[idx1] = make_float2(tf32r(v2), tf32r(v3));
    }
}

// ---------------------------------------------------------------------------
// Launch
// ---------------------------------------------------------------------------
extern "C" void kernel_launch(void* const* d_in, const int* in_sizes, int n_in,
                              void* d_out, int out_size)
{
    const float* x    = (const float*)d_in[0];
    const float* Wq   = (const float*)d_in[1];
    const float* Wk   = (const float*)d_in[2];
    const float* Wv   = (const float*)d_in[3];
    const float* Wo   = (const float*)d_in[4];
    const float* sint = (const float*)d_in[5];
    const float* cost = (const float*)d_in[6];
    const int*   doc  = (const int*)d_in[7];

    bf16 *xhi, *xlo, *Wthi, *Wtlo;
    bf16 *Qhi, *Qlo, *Khi, *Klo, *Vhi, *Vlo;
    float *Af, *Wotf;
    cudaGetSymbolAddress((void**)&xhi, g_xhi);
    cudaGetSymbolAddress((void**)&xlo, g_xlo);
    cudaGetSymbolAddress((void**)&Af, g_Af);
    cudaGetSymbolAddress((void**)&Qhi, g_Qhi);
    cudaGetSymbolAddress((void**)&Qlo, g_Qlo);
    cudaGetSymbolAddress((void**)&Khi, g_Khi);
    cudaGetSymbolAddress((void**)&Klo, g_Klo);
    cudaGetSymbolAddress((void**)&Vhi, g_Vhi);
    cudaGetSymbolAddress((void**)&Vlo, g_Vlo);
    cudaGetSymbolAddress((void**)&Wthi, g_Wthi);
    cudaGetSymbolAddress((void**)&Wtlo, g_Wtlo);
    cudaGetSymbolAddress((void**)&Wotf, g_Wotf);

    const int NELEM = T_ * D_;

    split_kernel<<<(NELEM + 255) / 256, 256>>>(x, xhi, xlo);
    dim3 tsBlk(32, 8);
    dim3 tsGrid3(D_ / 32, D_ / 32, 3);
    transpose_split3<<<tsGrid3, tsBlk>>>(Wq, Wk, Wv, Wthi, Wtlo);
    dim3 tsGrid1(D_ / 32, D_ / 32);
    transpose_tf32<<<tsGrid1, tsBlk>>>(Wo, Wotf);

    cudaFuncSetAttribute(gemm_qkv,
                         cudaFuncAttributeMaxDynamicSharedMemorySize, GSMEM_BYTES);
    cudaFuncSetAttribute(gemm_out_tf32,
                         cudaFuncAttributeMaxDynamicSharedMemorySize, GSMEM_BYTES);

    dim3 gGridQKV(D_ / 128, T_ / 128, 3);   // (16, 16, 3)
    gemm_qkv<<<gGridQKV, 256, GSMEM_BYTES>>>(xhi, xlo, Wthi, Wtlo, sint, cost,
                                             Qhi, Qlo, Khi, Klo, Vhi, Vlo);

    cudaFuncSetAttribute(attn_hmma,
                         cudaFuncAttributeMaxDynamicSharedMemorySize, ASMEM_BYTES);
    attn_hmma<<<dim3(T_ / BMA, H_), 128, ASMEM_BYTES>>>(
        Qhi, Qlo, Khi, Klo, Vhi, Vlo, doc, Af);

    dim3 gGridO(D_ / 128, T_ / 128, 1);     // (16, 16)
    gemm_out_tf32<<<gGridO, 256, GSMEM_BYTES>>>(Af, Wotf, (float*)d_out);
}

// round 14
// speedup vs baseline: 1.3278x; 1.1847x over previous
#include <cuda_runtime.h>
#include <cuda_bf16.h>
#include <cstdint>
#include <math.h>

#define T_  2048
#define D_  2048
#define H_  16
#define HD_ 128

typedef __nv_bfloat16 bf16;

// ---------------------------------------------------------------------------
// Scratch (allocation-free rule: __device__ globals)
// ---------------------------------------------------------------------------
__device__ float g_xtf[T_ * D_];       // x, tf32-rounded fp32
__device__ float g_Af[T_ * D_];        // attention output, tf32-rounded fp32
__device__ bf16 g_Qhi[T_ * D_];
__device__ bf16 g_Qlo[T_ * D_];
__device__ bf16 g_Khi[T_ * D_];
__device__ bf16 g_Klo[T_ * D_];
__device__ bf16 g_Vhi[T_ * D_];
__device__ bf16 g_Vlo[T_ * D_];
__device__ float g_Wttf[4][D_ * D_];   // transposed weights [N,K], tf32-rounded

// ---------------------------------------------------------------------------
// PTX helpers (compute_103-safe: mma.sync / ldmatrix / cp.async only)
// ---------------------------------------------------------------------------
__device__ __forceinline__ uint32_t smem_u32(const void* p) {
    uint32_t a;
    asm("{ .reg .u64 t; cvta.to.shared.u64 t, %1; cvt.u32.u64 %0, t; }"
        : "=r"(a) : "l"(p));
    return a;
}

#define CPA16(dst, src) \
    asm volatile("cp.async.cg.shared.global [%0], [%1], 16;" :: "r"(dst), "l"(src) : "memory")
#define CPA_COMMIT() asm volatile("cp.async.commit_group;" ::: "memory")
#define CPA_WAIT(n)  asm volatile("cp.async.wait_group %0;" :: "n"(n) : "memory")

__device__ __forceinline__ void ldsm_x4(uint32_t* r, uint32_t addr) {
    asm volatile("ldmatrix.sync.aligned.m8n8.x4.shared.b16 {%0,%1,%2,%3}, [%4];"
                 : "=r"(r[0]), "=r"(r[1]), "=r"(r[2]), "=r"(r[3]) : "r"(addr));
}

__device__ __forceinline__ void ldsm_x4_t(uint32_t* r, uint32_t addr) {
    asm volatile("ldmatrix.sync.aligned.m8n8.x4.trans.shared.b16 {%0,%1,%2,%3}, [%4];"
                 : "=r"(r[0]), "=r"(r[1]), "=r"(r[2]), "=r"(r[3]) : "r"(addr));
}

__device__ __forceinline__ void mma_bf16(float* d, const uint32_t* a,
                                         const uint32_t* b) {
    asm volatile(
        "mma.sync.aligned.m16n8k16.row.col.f32.bf16.bf16.f32 "
        "{%0,%1,%2,%3}, {%4,%5,%6,%7}, {%8,%9}, {%0,%1,%2,%3};"
        : "+f"(d[0]), "+f"(d[1]), "+f"(d[2]), "+f"(d[3])
        : "r"(a[0]), "r"(a[1]), "r"(a[2]), "r"(a[3]), "r"(b[0]), "r"(b[1]));
}

__device__ __forceinline__ void mma_tf32(float* d, const uint32_t* a,
                                         const uint32_t* b) {
    asm volatile(
        "mma.sync.aligned.m16n8k8.row.col.f32.tf32.tf32.f32 "
        "{%0,%1,%2,%3}, {%4,%5,%6,%7}, {%8,%9}, {%0,%1,%2,%3};"
        : "+f"(d[0]), "+f"(d[1]), "+f"(d[2]), "+f"(d[3])
        : "r"(a[0]), "r"(a[1]), "r"(a[2]), "r"(a[3]), "r"(b[0]), "r"(b[1]));
}

__device__ __forceinline__ uint32_t packbf(float lo, float hi) {
    uint32_t r;
    asm("cvt.rn.bf16x2.f32 %0, %1, %2;" : "=r"(r) : "f"(hi), "f"(lo));
    return r;
}

__device__ __forceinline__ float bfround(float v) {
    return __bfloat162float(__float2bfloat16(v));
}

// Round-to-nearest tf32 (rna) — zero-mean quantization for tf32 MMA inputs.
__device__ __forceinline__ float tf32r(float v) {
    uint32_t r;
    asm("cvt.rna.tf32.f32 %0, %1;" : "=r"(r) : "f"(v));
    return __uint_as_float(r);
}

// ---------------------------------------------------------------------------
// Elementwise tf32 rounding: x -> xtf.
// ---------------------------------------------------------------------------
__global__ __launch_bounds__(256) void tf32_round_kernel(
    const float* __restrict__ src, float* __restrict__ dst)
{
    int i = blockIdx.x * 256 + threadIdx.x;
    if (i >= T_ * D_) return;
    dst[i] = tf32r(src[i]);
}

// ---------------------------------------------------------------------------
// Transpose all 4 weights: W[K,N] fp32 -> T[N,K] fp32, tf32-rounded.
// ---------------------------------------------------------------------------
__global__ __launch_bounds__(256) void transpose_tf32_4(
    const float* __restrict__ W0, const float* __restrict__ W1,
    const float* __restrict__ W2, const float* __restrict__ W3,
    float* __restrict__ TtB)
{
    __shared__ float tile[32][33];
    const size_t WSZ = (size_t)D_ * D_;
    int z = blockIdx.z;
    const float* W = (z == 0) ? W0 : (z == 1) ? W1 : (z == 2) ? W2 : W3;
    float* Tt = TtB + z * WSZ;

    int bx = blockIdx.x * 32;
    int by = blockIdx.y * 32;
    int tx = threadIdx.x;
    int ty = threadIdx.y;
#pragma unroll
    for (int j = 0; j < 32; j += 8)
        tile[ty + j][tx] = W[(size_t)(by + ty + j) * D_ + bx + tx];
    __syncthreads();
#pragma unroll
    for (int j = 0; j < 32; j += 8)
        Tt[(size_t)(bx + ty + j) * D_ + by + tx] = tf32r(tile[tx][ty + j]);
}

// ---------------------------------------------------------------------------
// tf32 GEMM mainloop (proven in R13 O-proj): CTA tile 128x128, warp 64x32,
// BK=64 fp32 (256B rows), 3-stage cp.async, single sync per chunk.
// ldsm.x4 on fp32 tiles yields exact tf32 m16n8k8 A/B fragments.
// ---------------------------------------------------------------------------
#define STAGE_BYTES 65536
#define GSMEM_BYTES (3 * STAGE_BYTES)

__device__ __forceinline__ void tf32_mainloop128(
    const float* __restrict__ A, const float* __restrict__ Bt,
    int row0, int col0, char* smem, float acc[4][4][4])
{
    uint32_t sb = smem_u32(smem);
    const int tid  = threadIdx.x;
    const int wid  = tid >> 5;
    const int lane = tid & 31;
    const int wm = wid >> 2;
    const int wn = wid & 3;

    const char* baseA = (const char*)(A  + (size_t)row0 * D_);
    const char* baseB = (const char*)(Bt + (size_t)col0 * D_);

    auto load_stage = [&](int c, int s) {
        uint32_t st = sb + s * STAGE_BYTES;
#pragma unroll
        for (int j = 0; j < 16; j++) {
            int m = j >> 3;                  // 0=A, 1=B
            int q = tid + ((j & 7) << 8);    // 0..2047
            int r = q >> 4;                  // row 0..127
            int cb = (q & 15) << 4;          // byte col 0..240
            const char* src = (m ? baseB : baseA)
                              + (size_t)r * (D_ * 4) + c * 256 + cb;
            uint32_t off = (uint32_t)(r * 256) + (cb ^ ((r & 7) << 4));
            CPA16(st + m * 32768 + off, src);
        }
        CPA_COMMIT();
    };

    load_stage(0, 0);
    load_stage(1, 1);

    for (int c = 0; c < 32; c++) {
        if (c < 31) CPA_WAIT(1);
        else        CPA_WAIT(0);
        __syncthreads();
        if (c + 2 < 32) load_stage(c + 2, (c + 2) % 3);

        uint32_t st = sb + (c % 3) * STAGE_BYTES;
        uint32_t sA = st;
        uint32_t sB = st + 32768;

#pragma unroll
        for (int kg = 0; kg < 8; kg++) {
            uint32_t a[4][4];
#pragma unroll
            for (int i = 0; i < 4; i++) {
                int row = wm * 64 + i * 16 + (lane & 15);
                uint32_t cb = kg * 32 + ((lane >> 4) & 1) * 16;
                uint32_t off = (uint32_t)(row * 256) + (cb ^ ((row & 7) << 4));
                ldsm_x4(a[i], sA + off);
            }
#pragma unroll
            for (int jp = 0; jp < 2; jp++) {
                uint32_t b[4];
                int row = wn * 32 + jp * 16 + ((lane >> 4) & 1) * 8 + (lane & 7);
                uint32_t cb = kg * 32 + ((lane >> 3) & 1) * 16;
                uint32_t off = (uint32_t)(row * 256) + (cb ^ ((row & 7) << 4));
                ldsm_x4(b, sB + off);
#pragma unroll
                for (int i = 0; i < 4; i++) {
                    mma_tf32(acc[i][2 * jp],     a[i], &b[0]);
                    mma_tf32(acc[i][2 * jp + 1], a[i], &b[2]);
                }
            }
        }
    }
}

// ---------------------------------------------------------------------------
// QKV GEMM (tf32 single-pass) with fused RoPE (z<2) + split-bf16 epilogue.
// CTA's 128 output cols = exactly one head.
// ---------------------------------------------------------------------------
#define LDC 132

__global__ __launch_bounds__(256) void gemm_qkv_tf32(
    const float* __restrict__ xtf, const float* __restrict__ Wttf,
    const float* __restrict__ sint, const float* __restrict__ cost,
    bf16* __restrict__ Qhi, bf16* __restrict__ Qlo,
    bf16* __restrict__ Khi, bf16* __restrict__ Klo,
    bf16* __restrict__ Vhi, bf16* __restrict__ Vlo)
{
    extern __shared__ char smem[];
    const int z = blockIdx.z;
    const int row0 = blockIdx.y * 128;
    const int col0 = blockIdx.x * 128;
    const size_t WSZ = (size_t)D_ * D_;

    float acc[4][4][4];
#pragma unroll
    for (int i = 0; i < 4; i++)
#pragma unroll
        for (int j = 0; j < 4; j++)
#pragma unroll
            for (int q = 0; q < 4; q++) acc[i][j][q] = 0.0f;

    tf32_mainloop128(xtf, Wttf + z * WSZ, row0, col0, smem, acc);

    __syncthreads();
    float* sC = (float*)smem;
    const int tid  = threadIdx.x;
    const int wid  = tid >> 5;
    const int lane = tid & 31;
    const int wm = wid >> 2, wn = wid & 3;
    const int g = lane >> 2, t = lane & 3;
#pragma unroll
    for (int i = 0; i < 4; i++)
#pragma unroll
        for (int j = 0; j < 4; j++) {
            int row = wm * 64 + i * 16 + g;
            int col = wn * 32 + j * 8 + 2 * t;
            *(float2*)&sC[row * LDC + col] = make_float2(acc[i][j][0], acc[i][j][1]);
            *(float2*)&sC[(row + 8) * LDC + col] = make_float2(acc[i][j][2], acc[i][j][3]);
        }
    __syncthreads();

    bf16* Ohi = (z == 0) ? Qhi : (z == 1) ? Khi : Vhi;
    bf16* Olo = (z == 0) ? Qlo : (z == 1) ? Klo : Vlo;
    const bool dorope = (z < 2);

#pragma unroll 4
    for (int it = 0; it < 32; it++) {
        int idx = it * 256 + tid;
        int r = idx >> 6;
        int d = idx & 63;
        float v1 = sC[r * LDC + d];
        float v2 = sC[r * LDC + d + 64];
        int tg = row0 + r;
        float o1 = v1, o2 = v2;
        if (dorope) {
            float s1 = sint[tg * HD_ + d],      c1 = cost[tg * HD_ + d];
            float s2 = sint[tg * HD_ + d + 64], c2 = cost[tg * HD_ + d + 64];
            o1 = v1 * c1 - v2 * s1;
            o2 = v2 * c2 + v1 * s2;
        }
        size_t gi = (size_t)tg * D_ + col0 + d;
        Ohi[gi]      = __float2bfloat16(o1);
        Olo[gi]      = __float2bfloat16(o1 - bfround(o1));
        Ohi[gi + 64] = __float2bfloat16(o2);
        Olo[gi + 64] = __float2bfloat16(o2 - bfround(o2));
    }
}

// ---------------------------------------------------------------------------
// O-projection GEMM (tf32 single-pass): fp32 output, register epilogue.
// ---------------------------------------------------------------------------
__global__ __launch_bounds__(256) void gemm_out_tf32(
    const float* __restrict__ A, const float* __restrict__ Bt,
    float* __restrict__ C)
{
    extern __shared__ char smem[];
    const int row0 = blockIdx.y * 128;
    const int col0 = blockIdx.x * 128;

    float acc[4][4][4];
#pragma unroll
    for (int i = 0; i < 4; i++)
#pragma unroll
        for (int j = 0; j < 4; j++)
#pragma unroll
            for (int q = 0; q < 4; q++) acc[i][j][q] = 0.0f;

    tf32_mainloop128(A, Bt, row0, col0, smem, acc);

    const int tid  = threadIdx.x;
    const int wid  = tid >> 5;
    const int lane = tid & 31;
    const int wm = wid >> 2, wn = wid & 3;
    const int g = lane >> 2, t = lane & 3;
#pragma unroll
    for (int i = 0; i < 4; i++)
#pragma unroll
        for (int j = 0; j < 4; j++) {
            int row = row0 + wm * 64 + i * 16 + g;
            int col = col0 + wn * 32 + j * 8 + 2 * t;
            *(float2*)&C[(size_t)row * D_ + col] =
                make_float2(acc[i][j][0], acc[i][j][1]);
            *(float2*)&C[(size_t)(row + 8) * D_ + col] =
                make_float2(acc[i][j][2], acc[i][j][3]);
        }
}

// ---------------------------------------------------------------------------
// HMMA flash attention (FROZEN core), BMA=64, 4 warps, 96KB smem, 2 CTAs/SM.
// Epilogue writes tf32-rounded fp32 to g_Af (feeds tf32 O-proj).
// ---------------------------------------------------------------------------
#define BMA 64
#define BNA 64
#define ASMEM_BYTES 98304

__global__ __launch_bounds__(128, 2) void attn_hmma(
    const bf16* __restrict__ Qhi, const bf16* __restrict__ Qlo,
    const bf16* __restrict__ Khi, const bf16* __restrict__ Klo,
    const bf16* __restrict__ Vhi, const bf16* __restrict__ Vlo,
    const int* __restrict__ doc,
    float* __restrict__ Af)
{
    extern __shared__ char smem[];
    const uint32_t sQh = smem_u32(smem);
    const uint32_t sQl = sQh + 16384;
    const uint32_t sKh = sQh + 32768;
    const uint32_t sKl = sQh + 49152;
    const uint32_t sVh = sQh + 65536;
    const uint32_t sVl = sQh + 81920;
    __shared__ int qdoc[BMA];

    const int h = blockIdx.y;
    const int qt = (int)(gridDim.x - 1 - blockIdx.x);
    const int qbase = qt * BMA;
    const int tid = threadIdx.x;
    const int wid = tid >> 5;
    const int lane = tid & 31;
    const int g = lane >> 2;
    const int t = lane & 3;
    const int r0 = wid * 16;
    const float scale = 0.08838834764831845f;

    const int qd_first = doc[qbase];

    int kt0 = 0;
    while (doc[kt0 * BNA + BNA - 1] < qd_first) kt0++;

    auto load_K = [&](int kt) {
        const bf16* srcs[2] = {Khi, Klo};
#pragma unroll
        for (int j = 0; j < 16; j++) {
            int i = tid + (j << 7);
            int m = i >> 10;
            int idx = i & 1023;
            int r = idx >> 4;
            int cb = (idx & 15) << 4;
            size_t gidx = (size_t)(kt * BNA + r) * D_ + h * HD_ + (cb >> 1);
            uint32_t off = (uint32_t)(r * 256) + (cb ^ ((r & 7) << 4));
            CPA16((m ? sKl : sKh) + off, (const char*)&srcs[m][gidx]);
        }
        CPA_COMMIT();
    };
    auto load_V = [&](int kt) {
        const bf16* srcs[2] = {Vhi, Vlo};
#pragma unroll
        for (int j = 0; j < 16; j++) {
            int i = tid + (j << 7);
            int m = i >> 10;
            int idx = i & 1023;
            int r = idx >> 4;
            int cb = (idx & 15) << 4;
            size_t gidx = (size_t)(kt * BNA + r) * D_ + h * HD_ + (cb >> 1);
            uint32_t off = (uint32_t)(r * 256) + (cb ^ ((r & 7) << 4));
            CPA16((m ? sVl : sVh) + off, (const char*)&srcs[m][gidx]);
        }
        CPA_COMMIT();
    };

    load_K(kt0);
    load_V(kt0);

    for (int i = tid; i < BMA * 16; i += 128) {
        int r = i >> 4;
        int cb = (i & 15) << 4;
        size_t gidx = (size_t)(qbase + r) * D_ + h * HD_ + (cb >> 1);
        uint32_t off = (uint32_t)(r * 256) + (cb ^ ((r & 7) << 4));
        *(uint4*)(smem + off)         = *(const uint4*)&Qhi[gidx];
        *(uint4*)(smem + 16384 + off) = *(const uint4*)&Qlo[gidx];
    }
    if (tid < BMA) qdoc[tid] = doc[qbase + tid];
    __syncthreads();

    float oacc[16][4];
#pragma unroll
    for (int nt = 0; nt < 16; nt++)
#pragma unroll
        for (int q = 0; q < 4; q++) oacc[nt][q] = 0.0f;

    float m0 = -1e30f, m1 = -1e30f, l0 = 0.0f, l1 = 0.0f;
    const int qr0 = qbase + r0 + g;
    const int qr1 = qr0 + 8;
    const int dq0 = qdoc[r0 + g];
    const int dq1 = qdoc[r0 + g + 8];

    for (int kt = kt0; kt <= qt; kt++) {
        const int kbase = kt * BNA;
        const bool more = (kt < qt);

        CPA_WAIT(1);
        __syncthreads();

        float sacc[8][4];
#pragma unroll
        for (int nt = 0; nt < 8; nt++)
#pragma unroll
            for (int q = 0; q < 4; q++) sacc[nt][q] = 0.0f;

#pragma unroll
        for (int ks = 0; ks < 8; ks++) {
            uint32_t qh[4], ql[4];
            {
                int row = r0 + (lane & 15);
                int cb = ks * 32 + ((lane >> 4) & 1) * 16;
                uint32_t off = (uint32_t)(row * 256) + (cb ^ ((row & 7) << 4));
                ldsm_x4(qh, sQh + off);
                ldsm_x4(ql, sQl + off);
            }
#pragma unroll
            for (int jp = 0; jp < 4; jp++) {
                uint32_t kh[4], kl[4];
                int row = jp * 16 + ((lane >> 4) & 1) * 8 + (lane & 7);
                int cb = ks * 32 + ((lane >> 3) & 1) * 16;
                uint32_t off = (uint32_t)(row * 256) + (cb ^ ((row & 7) << 4));
                ldsm_x4(kh, sKh + off);
                ldsm_x4(kl, sKl + off);
                mma_bf16(sacc[2 * jp],     qh, &kh[0]);
                mma_bf16(sacc[2 * jp],     ql, &kh[0]);
                mma_bf16(sacc[2 * jp],     qh, &kl[0]);
                mma_bf16(sacc[2 * jp + 1], qh, &kh[2]);
                mma_bf16(sacc[2 * jp + 1], ql, &kh[2]);
                mma_bf16(sacc[2 * jp + 1], qh, &kl[2]);
            }
        }

        __syncthreads();
        if (more) load_K(kt + 1);

#pragma unroll
        for (int nt = 0; nt < 8; nt++) {
#pragma unroll
            for (int e = 0; e < 2; e++) {
                int col = nt * 8 + 2 * t + e;
                int kc = kbase + col;
                int kd = doc[kc];
                float v0 = sacc[nt][e] * scale;
                float v1 = sacc[nt][2 + e] * scale;
                sacc[nt][e]     = (kc <= qr0 && kd == dq0) ? v0 : -1e30f;
                sacc[nt][2 + e] = (kc <= qr1 && kd == dq1) ? v1 : -1e30f;
            }
        }

        float mr0 = -1e30f, mr1 = -1e30f;
#pragma unroll
        for (int nt = 0; nt < 8; nt++) {
            mr0 = fmaxf(mr0, fmaxf(sacc[nt][0], sacc[nt][1]));
            mr1 = fmaxf(mr1, fmaxf(sacc[nt][2], sacc[nt][3]));
        }
        mr0 = fmaxf(mr0, __shfl_xor_sync(0xffffffffu, mr0, 1));
        mr0 = fmaxf(mr0, __shfl_xor_sync(0xffffffffu, mr0, 2));
        mr1 = fmaxf(mr1, __shfl_xor_sync(0xffffffffu, mr1, 1));
        mr1 = fmaxf(mr1, __shfl_xor_sync(0xffffffffu, mr1, 2));
        float mn0 = fmaxf(m0, mr0), mn1 = fmaxf(m1, mr1);
        float rs0 = __expf(m0 - mn0), rs1 = __expf(m1 - mn1);
        float s0 = 0.0f, s1 = 0.0f;
#pragma unroll
        for (int nt = 0; nt < 8; nt++) {
#pragma unroll
            for (int e = 0; e < 2; e++) {
                float a = sacc[nt][e];
                a = (a <= -1e29f) ? 0.0f : __expf(a - mn0);
                sacc[nt][e] = a; s0 += a;
                float b = sacc[nt][2 + e];
                b = (b <= -1e29f) ? 0.0f : __expf(b - mn1);
                sacc[nt][2 + e] = b; s1 += b;
            }
        }
        s0 += __shfl_xor_sync(0xffffffffu, s0, 1);
        s0 += __shfl_xor_sync(0xffffffffu, s0, 2);
        s1 += __shfl_xor_sync(0xffffffffu, s1, 1);
        s1 += __shfl_xor_sync(0xffffffffu, s1, 2);
        l0 = l0 * rs0 + s0; m0 = mn0;
        l1 = l1 * rs1 + s1; m1 = mn1;

#pragma unroll
        for (int nt = 0; nt < 16; nt++) {
            oacc[nt][0] *= rs0; oacc[nt][1] *= rs0;
            oacc[nt][2] *= rs1; oacc[nt][3] *= rs1;
        }

        if (more) { CPA_WAIT(1); } else { CPA_WAIT(0); }
        __syncthreads();

#pragma unroll
        for (int ks = 0; ks < 4; ks++) {
            float p00 = sacc[2 * ks][0],     p01 = sacc[2 * ks][1];
            float p02 = sacc[2 * ks][2],     p03 = sacc[2 * ks][3];
            float p10 = sacc[2 * ks + 1][0], p11 = sacc[2 * ks + 1][1];
            float p12 = sacc[2 * ks + 1][2], p13 = sacc[2 * ks + 1][3];
            uint32_t phi[4], plo[4];
            phi[0] = packbf(p00, p01); phi[1] = packbf(p02, p03);
            phi[2] = packbf(p10, p11); phi[3] = packbf(p12, p13);
            plo[0] = packbf(p00 - bfround(p00), p01 - bfround(p01));
            plo[1] = packbf(p02 - bfround(p02), p03 - bfround(p03));
            plo[2] = packbf(p10 - bfround(p10), p11 - bfround(p11));
            plo[3] = packbf(p12 - bfround(p12), p13 - bfround(p13));

#pragma unroll
            for (int n0 = 0; n0 < 128; n0 += 16) {
                uint32_t vh[4], vl[4];
                int row = ks * 16 + ((lane >> 3) & 1) * 8 + (lane & 7);
                int cb = n0 * 2 + ((lane >> 4) & 1) * 16;
                uint32_t off = (uint32_t)(row * 256) + (cb ^ ((row & 7) << 4));
                ldsm_x4_t(vh, sVh + off);
                ldsm_x4_t(vl, sVl + off);
                int nt = n0 >> 3;
                mma_bf16(oacc[nt],     phi, &vh[0]);
                mma_bf16(oacc[nt],     plo, &vh[0]);
                mma_bf16(oacc[nt],     phi, &vl[0]);
                mma_bf16(oacc[nt + 1], phi, &vh[2]);
                mma_bf16(oacc[nt + 1], plo, &vh[2]);
                mma_bf16(oacc[nt + 1], phi, &vl[2]);
            }
        }

        __syncthreads();
        if (more) load_V(kt + 1);
    }

    float i0 = 1.0f / l0, i1 = 1.0f / l1;
#pragma unroll
    for (int nt = 0; nt < 16; nt++) {
        float v0 = oacc[nt][0] * i0, v1 = oacc[nt][1] * i0;
        float v2 = oacc[nt][2] * i1, v3 = oacc[nt][3] * i1;
        size_t idx0 = (size_t)qr0 * D_ + h * HD_ + nt * 8 + 2 * t;
        size_t idx1 = idx0 + (size_t)8 * D_;
        *(float2*)&Af[idx0] = make_float2(tf32r(v0), tf32r(v1));
        *(float2*)&Af[idx1] = make_float2(tf32r(v2), tf32r(v3));
    }
}

// ---------------------------------------------------------------------------
// Launch
// ---------------------------------------------------------------------------
extern "C" void kernel_launch(void* const* d_in, const int* in_sizes, int n_in,
                              void* d_out, int out_size)
{
    const float* x    = (const float*)d_in[0];
    const float* Wq   = (const float*)d_in[1];
    const float* Wk   = (const float*)d_in[2];
    const float* Wv   = (const float*)d_in[3];
    const float* Wo   = (const float*)d_in[4];
    const float* sint = (const float*)d_in[5];
    const float* cost = (const float*)d_in[6];
    const int*   doc  = (const int*)d_in[7];

    bf16 *Qhi, *Qlo, *Khi, *Klo, *Vhi, *Vlo;
    float *xtf, *Af, *Wttf;
    cudaGetSymbolAddress((void**)&xtf, g_xtf);
    cudaGetSymbolAddress((void**)&Af, g_Af);
    cudaGetSymbolAddress((void**)&Qhi, g_Qhi);
    cudaGetSymbolAddress((void**)&Qlo, g_Qlo);
    cudaGetSymbolAddress((void**)&Khi, g_Khi);
    cudaGetSymbolAddress((void**)&Klo, g_Klo);
    cudaGetSymbolAddress((void**)&Vhi, g_Vhi);
    cudaGetSymbolAddress((void**)&Vlo, g_Vlo);
    cudaGetSymbolAddress((void**)&Wttf, g_Wttf);

    const size_t WSZ = (size_t)D_ * D_;
    const int NELEM = T_ * D_;

    tf32_round_kernel<<<(NELEM + 255) / 256, 256>>>(x, xtf);
    dim3 tsBlk(32, 8);
    dim3 tsGrid4(D_ / 32, D_ / 32, 4);
    transpose_tf32_4<<<tsGrid4, tsBlk>>>(Wq, Wk, Wv, Wo, Wttf);

    cudaFuncSetAttribute(gemm_qkv_tf32,
                         cudaFuncAttributeMaxDynamicSharedMemorySize, GSMEM_BYTES);
    cudaFuncSetAttribute(gemm_out_tf32,
                         cudaFuncAttributeMaxDynamicSharedMemorySize, GSMEM_BYTES);

    dim3 gGridQKV(D_ / 128, T_ / 128, 3);   // (16, 16, 3)
    gemm_qkv_tf32<<<gGridQKV, 256, GSMEM_BYTES>>>(xtf, Wttf, sint, cost,
                                                  Qhi, Qlo, Khi, Klo, Vhi, Vlo);

    cudaFuncSetAttribute(attn_hmma,
                         cudaFuncAttributeMaxDynamicSharedMemorySize, ASMEM_BYTES);
    attn_hmma<<<dim3(T_ / BMA, H_), 128, ASMEM_BYTES>>>(
        Qhi, Qlo, Khi, Klo, Vhi, Vlo, doc, Af);

    dim3 gGridO(D_ / 128, T_ / 128, 1);     // (16, 16)
    gemm_out_tf32<<<gGridO, 256, GSMEM_BYTES>>>(Af, Wttf + 3 * WSZ, (float*)d_out);
}

// round 15
// speedup vs baseline: 1.4649x; 1.1033x over previous
#include <cuda_runtime.h>
#include <cuda_bf16.h>
#include <cstdint>
#include <math.h>

#define T_  2048
#define D_  2048
#define H_  16
#define HD_ 128

typedef __nv_bfloat16 bf16;

// ---------------------------------------------------------------------------
// Scratch (allocation-free rule: __device__ globals)
// ---------------------------------------------------------------------------
__device__ float g_xtf[T_ * D_];       // x, tf32-rounded fp32
__device__ float g_Af[T_ * D_];        // attention output, tf32-rounded fp32
__device__ bf16 g_Qhi[T_ * D_];
__device__ bf16 g_Qlo[T_ * D_];
__device__ bf16 g_Khi[T_ * D_];
__device__ bf16 g_Klo[T_ * D_];
__device__ bf16 g_Vhi[T_ * D_];
__device__ bf16 g_Vlo[T_ * D_];
__device__ float g_Wttf[4][D_ * D_];   // transposed weights [N,K], tf32-rounded

// ---------------------------------------------------------------------------
// PTX helpers (compute_103-safe: mma.sync / ldmatrix / cp.async only)
// ---------------------------------------------------------------------------
__device__ __forceinline__ uint32_t smem_u32(const void* p) {
    uint32_t a;
    asm("{ .reg .u64 t; cvta.to.shared.u64 t, %1; cvt.u32.u64 %0, t; }"
        : "=r"(a) : "l"(p));
    return a;
}

#define CPA16(dst, src) \
    asm volatile("cp.async.cg.shared.global [%0], [%1], 16;" :: "r"(dst), "l"(src) : "memory")
#define CPA_COMMIT() asm volatile("cp.async.commit_group;" ::: "memory")
#define CPA_WAIT(n)  asm volatile("cp.async.wait_group %0;" :: "n"(n) : "memory")

__device__ __forceinline__ void ldsm_x4(uint32_t* r, uint32_t addr) {
    asm volatile("ldmatrix.sync.aligned.m8n8.x4.shared.b16 {%0,%1,%2,%3}, [%4];"
                 : "=r"(r[0]), "=r"(r[1]), "=r"(r[2]), "=r"(r[3]) : "r"(addr));
}

__device__ __forceinline__ void ldsm_x4_t(uint32_t* r, uint32_t addr) {
    asm volatile("ldmatrix.sync.aligned.m8n8.x4.trans.shared.b16 {%0,%1,%2,%3}, [%4];"
                 : "=r"(r[0]), "=r"(r[1]), "=r"(r[2]), "=r"(r[3]) : "r"(addr));
}

__device__ __forceinline__ void mma_bf16(float* d, const uint32_t* a,
                                         const uint32_t* b) {
    asm volatile(
        "mma.sync.aligned.m16n8k16.row.col.f32.bf16.bf16.f32 "
        "{%0,%1,%2,%3}, {%4,%5,%6,%7}, {%8,%9}, {%0,%1,%2,%3};"
        : "+f"(d[0]), "+f"(d[1]), "+f"(d[2]), "+f"(d[3])
        : "r"(a[0]), "r"(a[1]), "r"(a[2]), "r"(a[3]), "r"(b[0]), "r"(b[1]));
}

__device__ __forceinline__ void mma_tf32(float* d, const uint32_t* a,
                                         const uint32_t* b) {
    asm volatile(
        "mma.sync.aligned.m16n8k8.row.col.f32.tf32.tf32.f32 "
        "{%0,%1,%2,%3}, {%4,%5,%6,%7}, {%8,%9}, {%0,%1,%2,%3};"
        : "+f"(d[0]), "+f"(d[1]), "+f"(d[2]), "+f"(d[3])
        : "r"(a[0]), "r"(a[1]), "r"(a[2]), "r"(a[3]), "r"(b[0]), "r"(b[1]));
}

__device__ __forceinline__ uint32_t packbf(float lo, float hi) {
    uint32_t r;
    asm("cvt.rn.bf16x2.f32 %0, %1, %2;" : "=r"(r) : "f"(hi), "f"(lo));
    return r;
}

__device__ __forceinline__ float bfround(float v) {
    return __bfloat162float(__float2bfloat16(v));
}

// Round-to-nearest tf32 (rna) — zero-mean quantization for tf32 MMA inputs.
__device__ __forceinline__ float tf32r(float v) {
    uint32_t r;
    asm("cvt.rna.tf32.f32 %0, %1;" : "=r"(r) : "f"(v));
    return __uint_as_float(r);
}

// ---------------------------------------------------------------------------
// Elementwise tf32 rounding: x -> xtf.
// ---------------------------------------------------------------------------
__global__ __launch_bounds__(256) void tf32_round_kernel(
    const float* __restrict__ src, float* __restrict__ dst)
{
    int i = blockIdx.x * 256 + threadIdx.x;
    if (i >= T_ * D_) return;
    dst[i] = tf32r(src[i]);
}

// ---------------------------------------------------------------------------
// Transpose all 4 weights: W[K,N] fp32 -> T[N,K] fp32, tf32-rounded.
// ---------------------------------------------------------------------------
__global__ __launch_bounds__(256) void transpose_tf32_4(
    const float* __restrict__ W0, const float* __restrict__ W1,
    const float* __restrict__ W2, const float* __restrict__ W3,
    float* __restrict__ TtB)
{
    __shared__ float tile[32][33];
    const size_t WSZ = (size_t)D_ * D_;
    int z = blockIdx.z;
    const float* W = (z == 0) ? W0 : (z == 1) ? W1 : (z == 2) ? W2 : W3;
    float* Tt = TtB + z * WSZ;

    int bx = blockIdx.x * 32;
    int by = blockIdx.y * 32;
    int tx = threadIdx.x;
    int ty = threadIdx.y;
#pragma unroll
    for (int j = 0; j < 32; j += 8)
        tile[ty + j][tx] = W[(size_t)(by + ty + j) * D_ + bx + tx];
    __syncthreads();
#pragma unroll
    for (int j = 0; j < 32; j += 8)
        Tt[(size_t)(bx + ty + j) * D_ + by + tx] = tf32r(tile[tx][ty + j]);
}

// ---------------------------------------------------------------------------
// tf32 GEMM mainloop, 2-CTA/SM variant: CTA tile 128x128, warp 64x32,
// BK=32 fp32 (128B rows), 3 stages x 32KB = 96KB smem, single sync/chunk.
// ---------------------------------------------------------------------------
#define STAGE_BYTES 32768
#define GSMEM_BYTES (3 * STAGE_BYTES)
#define NCHUNK 64

__device__ __forceinline__ void tf32_mainloop128(
    const float* __restrict__ A, const float* __restrict__ Bt,
    int row0, int col0, char* smem, float acc[4][4][4])
{
    uint32_t sb = smem_u32(smem);
    const int tid  = threadIdx.x;
    const int wid  = tid >> 5;
    const int lane = tid & 31;
    const int wm = wid >> 2;
    const int wn = wid & 3;

    const char* baseA = (const char*)(A  + (size_t)row0 * D_);
    const char* baseB = (const char*)(Bt + (size_t)col0 * D_);

    // Stage: A 128 rows x 128B (16KB) + B 128 rows x 128B (16KB).
    auto load_stage = [&](int c, int s) {
        uint32_t st = sb + s * STAGE_BYTES;
#pragma unroll
        for (int j = 0; j < 8; j++) {
            int m = j >> 2;                  // 0=A, 1=B
            int q = tid + ((j & 3) << 8);    // 0..1023
            int r = q >> 3;                  // row 0..127
            int cb = (q & 7) << 4;           // byte col 0..112
            const char* src = (m ? baseB : baseA)
                              + (size_t)r * (D_ * 4) + c * 128 + cb;
            uint32_t off = (uint32_t)(r * 128) + (cb ^ ((r & 7) << 4));
            CPA16(st + m * 16384 + off, src);
        }
        CPA_COMMIT();
    };

    load_stage(0, 0);
    load_stage(1, 1);

    for (int c = 0; c < NCHUNK; c++) {
        if (c < NCHUNK - 1) CPA_WAIT(1);
        else                CPA_WAIT(0);
        __syncthreads();
        if (c + 2 < NCHUNK) load_stage(c + 2, (c + 2) % 3);

        uint32_t st = sb + (c % 3) * STAGE_BYTES;
        uint32_t sA = st;
        uint32_t sB = st + 16384;

#pragma unroll
        for (int kg = 0; kg < 4; kg++) {
            uint32_t a[4][4];
#pragma unroll
            for (int i = 0; i < 4; i++) {
                int row = wm * 64 + i * 16 + (lane & 15);
                uint32_t cb = kg * 32 + ((lane >> 4) & 1) * 16;
                uint32_t off = (uint32_t)(row * 128) + (cb ^ ((row & 7) << 4));
                ldsm_x4(a[i], sA + off);
            }
#pragma unroll
            for (int jp = 0; jp < 2; jp++) {
                uint32_t b[4];
                int row = wn * 32 + jp * 16 + ((lane >> 4) & 1) * 8 + (lane & 7);
                uint32_t cb = kg * 32 + ((lane >> 3) & 1) * 16;
                uint32_t off = (uint32_t)(row * 128) + (cb ^ ((row & 7) << 4));
                ldsm_x4(b, sB + off);
#pragma unroll
                for (int i = 0; i < 4; i++) {
                    mma_tf32(acc[i][2 * jp],     a[i], &b[0]);
                    mma_tf32(acc[i][2 * jp + 1], a[i], &b[2]);
                }
            }
        }
    }
}

// ---------------------------------------------------------------------------
// QKV GEMM (tf32) with fused RoPE (z<2) + split-bf16 epilogue.
// ---------------------------------------------------------------------------
#define LDC 132

__global__ __launch_bounds__(256, 2) void gemm_qkv_tf32(
    const float* __restrict__ xtf, const float* __restrict__ Wttf,
    const float* __restrict__ sint, const float* __restrict__ cost,
    bf16* __restrict__ Qhi, bf16* __restrict__ Qlo,
    bf16* __restrict__ Khi, bf16* __restrict__ Klo,
    bf16* __restrict__ Vhi, bf16* __restrict__ Vlo)
{
    extern __shared__ char smem[];
    const int z = blockIdx.z;
    const int row0 = blockIdx.y * 128;
    const int col0 = blockIdx.x * 128;
    const size_t WSZ = (size_t)D_ * D_;

    float acc[4][4][4];
#pragma unroll
    for (int i = 0; i < 4; i++)
#pragma unroll
        for (int j = 0; j < 4; j++)
#pragma unroll
            for (int q = 0; q < 4; q++) acc[i][j][q] = 0.0f;

    tf32_mainloop128(xtf, Wttf + z * WSZ, row0, col0, smem, acc);

    // Epilogue via smem staging: 128x132 fp32 = 67.6KB <= 96KB.
    __syncthreads();
    float* sC = (float*)smem;
    const int tid  = threadIdx.x;
    const int wid  = tid >> 5;
    const int lane = tid & 31;
    const int wm = wid >> 2, wn = wid & 3;
    const int g = lane >> 2, t = lane & 3;
#pragma unroll
    for (int i = 0; i < 4; i++)
#pragma unroll
        for (int j = 0; j < 4; j++) {
            int row = wm * 64 + i * 16 + g;
            int col = wn * 32 + j * 8 + 2 * t;
            *(float2*)&sC[row * LDC + col] = make_float2(acc[i][j][0], acc[i][j][1]);
            *(float2*)&sC[(row + 8) * LDC + col] = make_float2(acc[i][j][2], acc[i][j][3]);
        }
    __syncthreads();

    bf16* Ohi = (z == 0) ? Qhi : (z == 1) ? Khi : Vhi;
    bf16* Olo = (z == 0) ? Qlo : (z == 1) ? Klo : Vlo;
    const bool dorope = (z < 2);

#pragma unroll 4
    for (int it = 0; it < 32; it++) {
        int idx = it * 256 + tid;
        int r = idx >> 6;
        int d = idx & 63;
        float v1 = sC[r * LDC + d];
        float v2 = sC[r * LDC + d + 64];
        int tg = row0 + r;
        float o1 = v1, o2 = v2;
        if (dorope) {
            float s1 = sint[tg * HD_ + d],      c1 = cost[tg * HD_ + d];
            float s2 = sint[tg * HD_ + d + 64], c2 = cost[tg * HD_ + d + 64];
            o1 = v1 * c1 - v2 * s1;
            o2 = v2 * c2 + v1 * s2;
        }
        size_t gi = (size_t)tg * D_ + col0 + d;
        Ohi[gi]      = __float2bfloat16(o1);
        Olo[gi]      = __float2bfloat16(o1 - bfround(o1));
        Ohi[gi + 64] = __float2bfloat16(o2);
        Olo[gi + 64] = __float2bfloat16(o2 - bfround(o2));
    }
}

// ---------------------------------------------------------------------------
// O-projection GEMM (tf32): fp32 output, register epilogue.
// ---------------------------------------------------------------------------
__global__ __launch_bounds__(256, 2) void gemm_out_tf32(
    const float* __restrict__ A, const float* __restrict__ Bt,
    float* __restrict__ C)
{
    extern __shared__ char smem[];
    const int row0 = blockIdx.y * 128;
    const int col0 = blockIdx.x * 128;

    float acc[4][4][4];
#pragma unroll
    for (int i = 0; i < 4; i++)
#pragma unroll
        for (int j = 0; j < 4; j++)
#pragma unroll
            for (int q = 0; q < 4; q++) acc[i][j][q] = 0.0f;

    tf32_mainloop128(A, Bt, row0, col0, smem, acc);

    const int tid  = threadIdx.x;
    const int wid  = tid >> 5;
    const int lane = tid & 31;
    const int wm = wid >> 2, wn = wid & 3;
    const int g = lane >> 2, t = lane & 3;
#pragma unroll
    for (int i = 0; i < 4; i++)
#pragma unroll
        for (int j = 0; j < 4; j++) {
            int row = row0 + wm * 64 + i * 16 + g;
            int col = col0 + wn * 32 + j * 8 + 2 * t;
            *(float2*)&C[(size_t)row * D_ + col] =
                make_float2(acc[i][j][0], acc[i][j][1]);
            *(float2*)&C[(size_t)(row + 8) * D_ + col] =
                make_float2(acc[i][j][2], acc[i][j][3]);
        }
}

// ---------------------------------------------------------------------------
// HMMA flash attention (FROZEN core), BMA=64, 4 warps, 96KB smem, 2 CTAs/SM.
// Epilogue writes tf32-rounded fp32 to g_Af (feeds tf32 O-proj).
// ---------------------------------------------------------------------------
#define BMA 64
#define BNA 64
#define ASMEM_BYTES 98304

__global__ __launch_bounds__(128, 2) void attn_hmma(
    const bf16* __restrict__ Qhi, const bf16* __restrict__ Qlo,
    const bf16* __restrict__ Khi, const bf16* __restrict__ Klo,
    const bf16* __restrict__ Vhi, const bf16* __restrict__ Vlo,
    const int* __restrict__ doc,
    float* __restrict__ Af)
{
    extern __shared__ char smem[];
    const uint32_t sQh = smem_u32(smem);
    const uint32_t sQl = sQh + 16384;
    const uint32_t sKh = sQh + 32768;
    const uint32_t sKl = sQh + 49152;
    const uint32_t sVh = sQh + 65536;
    const uint32_t sVl = sQh + 81920;
    __shared__ int qdoc[BMA];

    const int h = blockIdx.y;
    const int qt = (int)(gridDim.x - 1 - blockIdx.x);
    const int qbase = qt * BMA;
    const int tid = threadIdx.x;
    const int wid = tid >> 5;
    const int lane = tid & 31;
    const int g = lane >> 2;
    const int t = lane & 3;
    const int r0 = wid * 16;
    const float scale = 0.08838834764831845f;

    const int qd_first = doc[qbase];

    int kt0 = 0;
    while (doc[kt0 * BNA + BNA - 1] < qd_first) kt0++;

    auto load_K = [&](int kt) {
        const bf16* srcs[2] = {Khi, Klo};
#pragma unroll
        for (int j = 0; j < 16; j++) {
            int i = tid + (j << 7);
            int m = i >> 10;
            int idx = i & 1023;
            int r = idx >> 4;
            int cb = (idx & 15) << 4;
            size_t gidx = (size_t)(kt * BNA + r) * D_ + h * HD_ + (cb >> 1);
            uint32_t off = (uint32_t)(r * 256) + (cb ^ ((r & 7) << 4));
            CPA16((m ? sKl : sKh) + off, (const char*)&srcs[m][gidx]);
        }
        CPA_COMMIT();
    };
    auto load_V = [&](int kt) {
        const bf16* srcs[2] = {Vhi, Vlo};
#pragma unroll
        for (int j = 0; j < 16; j++) {
            int i = tid + (j << 7);
            int m = i >> 10;
            int idx = i & 1023;
            int r = idx >> 4;
            int cb = (idx & 15) << 4;
            size_t gidx = (size_t)(kt * BNA + r) * D_ + h * HD_ + (cb >> 1);
            uint32_t off = (uint32_t)(r * 256) + (cb ^ ((r & 7) << 4));
            CPA16((m ? sVl : sVh) + off, (const char*)&srcs[m][gidx]);
        }
        CPA_COMMIT();
    };

    load_K(kt0);
    load_V(kt0);

    for (int i = tid; i < BMA * 16; i += 128) {
        int r = i >> 4;
        int cb = (i & 15) << 4;
        size_t gidx = (size_t)(qbase + r) * D_ + h * HD_ + (cb >> 1);
        uint32_t off = (uint32_t)(r * 256) + (cb ^ ((r & 7) << 4));
        *(uint4*)(smem + off)         = *(const uint4*)&Qhi[gidx];
        *(uint4*)(smem + 16384 + off) = *(const uint4*)&Qlo[gidx];
    }
    if (tid < BMA) qdoc[tid] = doc[qbase + tid];
    __syncthreads();

    float oacc[16][4];
#pragma unroll
    for (int nt = 0; nt < 16; nt++)
#pragma unroll
        for (int q = 0; q < 4; q++) oacc[nt][q] = 0.0f;

    float m0 = -1e30f, m1 = -1e30f, l0 = 0.0f, l1 = 0.0f;
    const int qr0 = qbase + r0 + g;
    const int qr1 = qr0 + 8;
    const int dq0 = qdoc[r0 + g];
    const int dq1 = qdoc[r0 + g + 8];

    for (int kt = kt0; kt <= qt; kt++) {
        const int kbase = kt * BNA;
        const bool more = (kt < qt);

        CPA_WAIT(1);
        __syncthreads();

        float sacc[8][4];
#pragma unroll
        for (int nt = 0; nt < 8; nt++)
#pragma unroll
            for (int q = 0; q < 4; q++) sacc[nt][q] = 0.0f;

#pragma unroll
        for (int ks = 0; ks < 8; ks++) {
            uint32_t qh[4], ql[4];
            {
                int row = r0 + (lane & 15);
                int cb = ks * 32 + ((lane >> 4) & 1) * 16;
                uint32_t off = (uint32_t)(row * 256) + (cb ^ ((row & 7) << 4));
                ldsm_x4(qh, sQh + off);
                ldsm_x4(ql, sQl + off);
            }
#pragma unroll
            for (int jp = 0; jp < 4; jp++) {
                uint32_t kh[4], kl[4];
                int row = jp * 16 + ((lane >> 4) & 1) * 8 + (lane & 7);
                int cb = ks * 32 + ((lane >> 3) & 1) * 16;
                uint32_t off = (uint32_t)(row * 256) + (cb ^ ((row & 7) << 4));
                ldsm_x4(kh, sKh + off);
                ldsm_x4(kl, sKl + off);
                mma_bf16(sacc[2 * jp],     qh, &kh[0]);
                mma_bf16(sacc[2 * jp],     ql, &kh[0]);
                mma_bf16(sacc[2 * jp],     qh, &kl[0]);
                mma_bf16(sacc[2 * jp + 1], qh, &kh[2]);
                mma_bf16(sacc[2 * jp + 1], ql, &kh[2]);
                mma_bf16(sacc[2 * jp + 1], qh, &kl[2]);
            }
        }

        __syncthreads();
        if (more) load_K(kt + 1);

#pragma unroll
        for (int nt = 0; nt < 8; nt++) {
#pragma unroll
            for (int e = 0; e < 2; e++) {
                int col = nt * 8 + 2 * t + e;
                int kc = kbase + col;
                int kd = doc[kc];
                float v0 = sacc[nt][e] * scale;
                float v1 = sacc[nt][2 + e] * scale;
                sacc[nt][e]     = (kc <= qr0 && kd == dq0) ? v0 : -1e30f;
                sacc[nt][2 + e] = (kc <= qr1 && kd == dq1) ? v1 : -1e30f;
            }
        }

        float mr0 = -1e30f, mr1 = -1e30f;
#pragma unroll
        for (int nt = 0; nt < 8; nt++) {
            mr0 = fmaxf(mr0, fmaxf(sacc[nt][0], sacc[nt][1]));
            mr1 = fmaxf(mr1, fmaxf(sacc[nt][2], sacc[nt][3]));
        }
        mr0 = fmaxf(mr0, __shfl_xor_sync(0xffffffffu, mr0, 1));
        mr0 = fmaxf(mr0, __shfl_xor_sync(0xffffffffu, mr0, 2));
        mr1 = fmaxf(mr1, __shfl_xor_sync(0xffffffffu, mr1, 1));
        mr1 = fmaxf(mr1, __shfl_xor_sync(0xffffffffu, mr1, 2));
        float mn0 = fmaxf(m0, mr0), mn1 = fmaxf(m1, mr1);
        float rs0 = __expf(m0 - mn0), rs1 = __expf(m1 - mn1);
        float s0 = 0.0f, s1 = 0.0f;
#pragma unroll
        for (int nt = 0; nt < 8; nt++) {
#pragma unroll
            for (int e = 0; e < 2; e++) {
                float a = sacc[nt][e];
                a = (a <= -1e29f) ? 0.0f : __expf(a - mn0);
                sacc[nt][e] = a; s0 += a;
                float b = sacc[nt][2 + e];
                b = (b <= -1e29f) ? 0.0f : __expf(b - mn1);
                sacc[nt][2 + e] = b; s1 += b;
            }
        }
        s0 += __shfl_xor_sync(0xffffffffu, s0, 1);
        s0 += __shfl_xor_sync(0xffffffffu, s0, 2);
        s1 += __shfl_xor_sync(0xffffffffu, s1, 1);
        s1 += __shfl_xor_sync(0xffffffffu, s1, 2);
        l0 = l0 * rs0 + s0; m0 = mn0;
        l1 = l1 * rs1 + s1; m1 = mn1;

#pragma unroll
        for (int nt = 0; nt < 16; nt++) {
            oacc[nt][0] *= rs0; oacc[nt][1] *= rs0;
            oacc[nt][2] *= rs1; oacc[nt][3] *= rs1;
        }

        if (more) { CPA_WAIT(1); } else { CPA_WAIT(0); }
        __syncthreads();

#pragma unroll
        for (int ks = 0; ks < 4; ks++) {
            float p00 = sacc[2 * ks][0],     p01 = sacc[2 * ks][1];
            float p02 = sacc[2 * ks][2],     p03 = sacc[2 * ks][3];
            float p10 = sacc[2 * ks + 1][0], p11 = sacc[2 * ks + 1][1];
            float p12 = sacc[2 * ks + 1][2], p13 = sacc[2 * ks + 1][3];
            uint32_t phi[4], plo[4];
            phi[0] = packbf(p00, p01); phi[1] = packbf(p02, p03);
            phi[2] = packbf(p10, p11); phi[3] = packbf(p12, p13);
            plo[0] = packbf(p00 - bfround(p00), p01 - bfround(p01));
            plo[1] = packbf(p02 - bfround(p02), p03 - bfround(p03));
            plo[2] = packbf(p10 - bfround(p10), p11 - bfround(p11));
            plo[3] = packbf(p12 - bfround(p12), p13 - bfround(p13));

#pragma unroll
            for (int n0 = 0; n0 < 128; n0 += 16) {
                uint32_t vh[4], vl[4];
                int row = ks * 16 + ((lane >> 3) & 1) * 8 + (lane & 7);
                int cb = n0 * 2 + ((lane >> 4) & 1) * 16;
                uint32_t off = (uint32_t)(row * 256) + (cb ^ ((row & 7) << 4));
                ldsm_x4_t(vh, sVh + off);
                ldsm_x4_t(vl, sVl + off);
                int nt = n0 >> 3;
                mma_bf16(oacc[nt],     phi, &vh[0]);
                mma_bf16(oacc[nt],     plo, &vh[0]);
                mma_bf16(oacc[nt],     phi, &vl[0]);
                mma_bf16(oacc[nt + 1], phi, &vh[2]);
                mma_bf16(oacc[nt + 1], plo, &vh[2]);
                mma_bf16(oacc[nt + 1], phi, &vl[2]);
            }
        }

        __syncthreads();
        if (more) load_V(kt + 1);
    }

    float i0 = 1.0f / l0, i1 = 1.0f / l1;
#pragma unroll
    for (int nt = 0; nt < 16; nt++) {
        float v0 = oacc[nt][0] * i0, v1 = oacc[nt][1] * i0;
        float v2 = oacc[nt][2] * i1, v3 = oacc[nt][3] * i1;
        size_t idx0 = (size_t)qr0 * D_ + h * HD_ + nt * 8 + 2 * t;
        size_t idx1 = idx0 + (size_t)8 * D_;
        *(float2*)&Af[idx0] = make_float2(tf32r(v0), tf32r(v1));
        *(float2*)&Af[idx1] = make_float2(tf32r(v2), tf32r(v3));
    }
}

// ---------------------------------------------------------------------------
// Launch
// ---------------------------------------------------------------------------
extern "C" void kernel_launch(void* const* d_in, const int* in_sizes, int n_in,
                              void* d_out, int out_size)
{
    const float* x    = (const float*)d_in[0];
    const float* Wq   = (const float*)d_in[1];
    const float* Wk   = (const float*)d_in[2];
    const float* Wv   = (const float*)d_in[3];
    const float* Wo   = (const float*)d_in[4];
    const float* sint = (const float*)d_in[5];
    const float* cost = (const float*)d_in[6];
    const int*   doc  = (const int*)d_in[7];

    bf16 *Qhi, *Qlo, *Khi, *Klo, *Vhi, *Vlo;
    float *xtf, *Af, *Wttf;
    cudaGetSymbolAddress((void**)&xtf, g_xtf);
    cudaGetSymbolAddress((void**)&Af, g_Af);
    cudaGetSymbolAddress((void**)&Qhi, g_Qhi);
    cudaGetSymbolAddress((void**)&Qlo, g_Qlo);
    cudaGetSymbolAddress((void**)&Khi, g_Khi);
    cudaGetSymbolAddress((void**)&Klo, g_Klo);
    cudaGetSymbolAddress((void**)&Vhi, g_Vhi);
    cudaGetSymbolAddress((void**)&Vlo, g_Vlo);
    cudaGetSymbolAddress((void**)&Wttf, g_Wttf);

    const size_t WSZ = (size_t)D_ * D_;
    const int NELEM = T_ * D_;

    tf32_round_kernel<<<(NELEM + 255) / 256, 256>>>(x, xtf);
    dim3 tsBlk(32, 8);
    dim3 tsGrid4(D_ / 32, D_ / 32, 4);
    transpose_tf32_4<<<tsGrid4, tsBlk>>>(Wq, Wk, Wv, Wo, Wttf);

    cudaFuncSetAttribute(gemm_qkv_tf32,
                         cudaFuncAttributeMaxDynamicSharedMemorySize, GSMEM_BYTES);
    cudaFuncSetAttribute(gemm_out_tf32,
                         cudaFuncAttributeMaxDynamicSharedMemorySize, GSMEM_BYTES);

    dim3 gGridQKV(D_ / 128, T_ / 128, 3);   // (16, 16, 3)
    gemm_qkv_tf32<<<gGridQKV, 256, GSMEM_BYTES>>>(xtf, Wttf, sint, cost,
                                                  Qhi, Qlo, Khi, Klo, Vhi, Vlo);

    cudaFuncSetAttribute(attn_hmma,
                         cudaFuncAttributeMaxDynamicSharedMemorySize, ASMEM_BYTES);
    attn_hmma<<<dim3(T_ / BMA, H_), 128, ASMEM_BYTES>>>(
        Qhi, Qlo, Khi, Klo, Vhi, Vlo, doc, Af);

    dim3 gGridO(D_ / 128, T_ / 128, 1);     // (16, 16)
    gemm_out_tf32<<<gGridO, 256, GSMEM_BYTES>>>(Af, Wttf + 3 * WSZ, (float*)d_out);
}

// round 16
// speedup vs baseline: 2.3509x; 1.6048x over previous
#include <cuda_runtime.h>
#include <cuda_bf16.h>
#include <cuda_fp16.h>
#include <cstdint>
#include <math.h>

#define T_  2048
#define D_  2048
#define H_  16
#define HD_ 128

typedef __nv_bfloat16 bf16;

// ---------------------------------------------------------------------------
// Scratch (allocation-free rule: __device__ globals)
// ---------------------------------------------------------------------------
__device__ __half g_xh[T_ * D_];       // x, fp16 (rn)
__device__ __half g_Ah[T_ * D_];       // attention output, fp16 (rn)
__device__ bf16 g_Qhi[T_ * D_];
__device__ bf16 g_Qlo[T_ * D_];
__device__ bf16 g_Khi[T_ * D_];
__device__ bf16 g_Klo[T_ * D_];
__device__ bf16 g_Vhi[T_ * D_];
__device__ bf16 g_Vlo[T_ * D_];
__device__ __half g_Wth[4][D_ * D_];   // transposed weights [N,K], fp16 (rn)

// ---------------------------------------------------------------------------
// PTX helpers (compute_103-safe: mma.sync / ldmatrix / cp.async only)
// ---------------------------------------------------------------------------
__device__ __forceinline__ uint32_t smem_u32(const void* p) {
    uint32_t a;
    asm("{ .reg .u64 t; cvta.to.shared.u64 t, %1; cvt.u32.u64 %0, t; }"
        : "=r"(a) : "l"(p));
    return a;
}

#define CPA16(dst, src) \
    asm volatile("cp.async.cg.shared.global [%0], [%1], 16;" :: "r"(dst), "l"(src) : "memory")
#define CPA_COMMIT() asm volatile("cp.async.commit_group;" ::: "memory")
#define CPA_WAIT(n)  asm volatile("cp.async.wait_group %0;" :: "n"(n) : "memory")

__device__ __forceinline__ void ldsm_x4(uint32_t* r, uint32_t addr) {
    asm volatile("ldmatrix.sync.aligned.m8n8.x4.shared.b16 {%0,%1,%2,%3}, [%4];"
                 : "=r"(r[0]), "=r"(r[1]), "=r"(r[2]), "=r"(r[3]) : "r"(addr));
}

__device__ __forceinline__ void ldsm_x4_t(uint32_t* r, uint32_t addr) {
    asm volatile("ldmatrix.sync.aligned.m8n8.x4.trans.shared.b16 {%0,%1,%2,%3}, [%4];"
                 : "=r"(r[0]), "=r"(r[1]), "=r"(r[2]), "=r"(r[3]) : "r"(addr));
}

__device__ __forceinline__ void mma_bf16(float* d, const uint32_t* a,
                                         const uint32_t* b) {
    asm volatile(
        "mma.sync.aligned.m16n8k16.row.col.f32.bf16.bf16.f32 "
        "{%0,%1,%2,%3}, {%4,%5,%6,%7}, {%8,%9}, {%0,%1,%2,%3};"
        : "+f"(d[0]), "+f"(d[1]), "+f"(d[2]), "+f"(d[3])
        : "r"(a[0]), "r"(a[1]), "r"(a[2]), "r"(a[3]), "r"(b[0]), "r"(b[1]));
}

__device__ __forceinline__ void mma_f16(float* d, const uint32_t* a,
                                        const uint32_t* b) {
    asm volatile(
        "mma.sync.aligned.m16n8k16.row.col.f32.f16.f16.f32 "
        "{%0,%1,%2,%3}, {%4,%5,%6,%7}, {%8,%9}, {%0,%1,%2,%3};"
        : "+f"(d[0]), "+f"(d[1]), "+f"(d[2]), "+f"(d[3])
        : "r"(a[0]), "r"(a[1]), "r"(a[2]), "r"(a[3]), "r"(b[0]), "r"(b[1]));
}

__device__ __forceinline__ uint32_t packbf(float lo, float hi) {
    uint32_t r;
    asm("cvt.rn.bf16x2.f32 %0, %1, %2;" : "=r"(r) : "f"(hi), "f"(lo));
    return r;
}

__device__ __forceinline__ uint32_t packh(float lo, float hi) {
    uint32_t r;
    asm("cvt.rn.f16x2.f32 %0, %1, %2;" : "=r"(r) : "f"(hi), "f"(lo));
    return r;
}

__device__ __forceinline__ float bfround(float v) {
    return __bfloat162float(__float2bfloat16(v));
}

// ---------------------------------------------------------------------------
// Elementwise fp16 rounding: x -> xh.
// ---------------------------------------------------------------------------
__global__ __launch_bounds__(256) void f16_round_kernel(
    const float* __restrict__ src, __half* __restrict__ dst)
{
    int i = blockIdx.x * 256 + threadIdx.x;
    if (i >= T_ * D_) return;
    dst[i] = __float2half_rn(src[i]);
}

// ---------------------------------------------------------------------------
// Transpose all 4 weights: W[K,N] fp32 -> T[N,K] fp16 (rn).
// ---------------------------------------------------------------------------
__global__ __launch_bounds__(256) void transpose_f16_4(
    const float* __restrict__ W0, const float* __restrict__ W1,
    const float* __restrict__ W2, const float* __restrict__ W3,
    __half* __restrict__ TtB)
{
    __shared__ float tile[32][33];
    const size_t WSZ = (size_t)D_ * D_;
    int z = blockIdx.z;
    const float* W = (z == 0) ? W0 : (z == 1) ? W1 : (z == 2) ? W2 : W3;
    __half* Tt = TtB + z * WSZ;

    int bx = blockIdx.x * 32;
    int by = blockIdx.y * 32;
    int tx = threadIdx.x;
    int ty = threadIdx.y;
#pragma unroll
    for (int j = 0; j < 32; j += 8)
        tile[ty + j][tx] = W[(size_t)(by + ty + j) * D_ + bx + tx];
    __syncthreads();
#pragma unroll
    for (int j = 0; j < 32; j += 8)
        Tt[(size_t)(bx + ty + j) * D_ + by + tx] = __float2half_rn(tile[tx][ty + j]);
}

// ---------------------------------------------------------------------------
// fp16 single-pass GEMM mainloop: CTA tile 128x128, warp 64x32, BK=64 fp16
// (128B rows), 3 stages x 32KB = 96KB -> 2 CTAs/SM, single sync per chunk.
// Same skeleton as the proven bf16 loop, minus hi/lo terms.
// ---------------------------------------------------------------------------
#define STAGE_BYTES 32768
#define GSMEM_BYTES (3 * STAGE_BYTES)

__device__ __forceinline__ void f16_mainloop128(
    const __half* __restrict__ A, const __half* __restrict__ Bt,
    int row0, int col0, char* smem, float acc[4][4][4])
{
    uint32_t sb = smem_u32(smem);
    const int tid  = threadIdx.x;
    const int wid  = tid >> 5;
    const int lane = tid & 31;
    const int wm = wid >> 2;
    const int wn = wid & 3;

    const char* baseA = (const char*)(A  + (size_t)row0 * D_);
    const char* baseB = (const char*)(Bt + (size_t)col0 * D_);

    // Stage: A 128 rows x 128B (16KB) + B 128 rows x 128B (16KB).
    auto load_stage = [&](int c, int s) {
        uint32_t st = sb + s * STAGE_BYTES;
#pragma unroll
        for (int j = 0; j < 8; j++) {
            int m = j >> 2;                  // 0=A, 1=B
            int q = tid + ((j & 3) << 8);    // 0..1023
            int r = q >> 3;                  // row 0..127
            int cb = (q & 7) << 4;           // byte col 0..112
            const char* src = (m ? baseB : baseA)
                              + (size_t)r * (D_ * 2) + c * 128 + cb;
            uint32_t off = (uint32_t)(r * 128) + (cb ^ ((r & 7) << 4));
            CPA16(st + m * 16384 + off, src);
        }
        CPA_COMMIT();
    };

    load_stage(0, 0);
    load_stage(1, 1);

    for (int c = 0; c < 32; c++) {
        if (c < 31) CPA_WAIT(1);
        else        CPA_WAIT(0);
        __syncthreads();
        if (c + 2 < 32) load_stage(c + 2, (c + 2) % 3);

        uint32_t st = sb + (c % 3) * STAGE_BYTES;
        uint32_t sA = st;
        uint32_t sB = st + 16384;

#pragma unroll
        for (int ks = 0; ks < 4; ks++) {
            uint32_t a[4][4];
#pragma unroll
            for (int i = 0; i < 4; i++) {
                int row = wm * 64 + i * 16 + (lane & 15);
                uint32_t colb = ks * 32 + ((lane >> 4) & 1) * 16;
                uint32_t off = (uint32_t)(row * 128) + (colb ^ ((row & 7) << 4));
                ldsm_x4(a[i], sA + off);
            }
            uint32_t b[8];
#pragma unroll
            for (int jp = 0; jp < 2; jp++) {
                int row = wn * 32 + jp * 16 + ((lane >> 4) & 1) * 8 + (lane & 7);
                uint32_t colb = ks * 32 + ((lane >> 3) & 1) * 16;
                uint32_t off = (uint32_t)(row * 128) + (colb ^ ((row & 7) << 4));
                ldsm_x4(&b[jp * 4], sB + off);
            }
#pragma unroll
            for (int i = 0; i < 4; i++)
#pragma unroll
                for (int j = 0; j < 4; j++)
                    mma_f16(acc[i][j], a[i], &b[j * 2]);
        }
    }
}

// ---------------------------------------------------------------------------
// QKV GEMM (fp16 single-pass) with fused RoPE (z<2) + split-bf16 epilogue.
// ---------------------------------------------------------------------------
#define LDC 132

__global__ __launch_bounds__(256, 2) void gemm_qkv_f16(
    const __half* __restrict__ xh, const __half* __restrict__ Wth,
    const float* __restrict__ sint, const float* __restrict__ cost,
    bf16* __restrict__ Qhi, bf16* __restrict__ Qlo,
    bf16* __restrict__ Khi, bf16* __restrict__ Klo,
    bf16* __restrict__ Vhi, bf16* __restrict__ Vlo)
{
    extern __shared__ char smem[];
    const int z = blockIdx.z;
    const int row0 = blockIdx.y * 128;
    const int col0 = blockIdx.x * 128;
    const size_t WSZ = (size_t)D_ * D_;

    float acc[4][4][4];
#pragma unroll
    for (int i = 0; i < 4; i++)
#pragma unroll
        for (int j = 0; j < 4; j++)
#pragma unroll
            for (int q = 0; q < 4; q++) acc[i][j][q] = 0.0f;

    f16_mainloop128(xh, Wth + z * WSZ, row0, col0, smem, acc);

    // Epilogue via smem staging: 128x132 fp32 = 67.6KB <= 96KB.
    __syncthreads();
    float* sC = (float*)smem;
    const int tid  = threadIdx.x;
    const int wid  = tid >> 5;
    const int lane = tid & 31;
    const int wm = wid >> 2, wn = wid & 3;
    const int g = lane >> 2, t = lane & 3;
#pragma unroll
    for (int i = 0; i < 4; i++)
#pragma unroll
        for (int j = 0; j < 4; j++) {
            int row = wm * 64 + i * 16 + g;
            int col = wn * 32 + j * 8 + 2 * t;
            *(float2*)&sC[row * LDC + col] = make_float2(acc[i][j][0], acc[i][j][1]);
            *(float2*)&sC[(row + 8) * LDC + col] = make_float2(acc[i][j][2], acc[i][j][3]);
        }
    __syncthreads();

    bf16* Ohi = (z == 0) ? Qhi : (z == 1) ? Khi : Vhi;
    bf16* Olo = (z == 0) ? Qlo : (z == 1) ? Klo : Vlo;
    const bool dorope = (z < 2);

#pragma unroll 4
    for (int it = 0; it < 32; it++) {
        int idx = it * 256 + tid;
        int r = idx >> 6;
        int d = idx & 63;
        float v1 = sC[r * LDC + d];
        float v2 = sC[r * LDC + d + 64];
        int tg = row0 + r;
        float o1 = v1, o2 = v2;
        if (dorope) {
            float s1 = sint[tg * HD_ + d],      c1 = cost[tg * HD_ + d];
            float s2 = sint[tg * HD_ + d + 64], c2 = cost[tg * HD_ + d + 64];
            o1 = v1 * c1 - v2 * s1;
            o2 = v2 * c2 + v1 * s2;
        }
        size_t gi = (size_t)tg * D_ + col0 + d;
        Ohi[gi]      = __float2bfloat16(o1);
        Olo[gi]      = __float2bfloat16(o1 - bfround(o1));
        Ohi[gi + 64] = __float2bfloat16(o2);
        Olo[gi + 64] = __float2bfloat16(o2 - bfround(o2));
    }
}

// ---------------------------------------------------------------------------
// O-projection GEMM (fp16 single-pass): fp32 output, register epilogue.
// ---------------------------------------------------------------------------
__global__ __launch_bounds__(256, 2) void gemm_out_f16(
    const __half* __restrict__ A, const __half* __restrict__ Bt,
    float* __restrict__ C)
{
    extern __shared__ char smem[];
    const int row0 = blockIdx.y * 128;
    const int col0 = blockIdx.x * 128;

    float acc[4][4][4];
#pragma unroll
    for (int i = 0; i < 4; i++)
#pragma unroll
        for (int j = 0; j < 4; j++)
#pragma unroll
            for (int q = 0; q < 4; q++) acc[i][j][q] = 0.0f;

    f16_mainloop128(A, Bt, row0, col0, smem, acc);

    const int tid  = threadIdx.x;
    const int wid  = tid >> 5;
    const int lane = tid & 31;
    const int wm = wid >> 2, wn = wid & 3;
    const int g = lane >> 2, t = lane & 3;
#pragma unroll
    for (int i = 0; i < 4; i++)
#pragma unroll
        for (int j = 0; j < 4; j++) {
            int row = row0 + wm * 64 + i * 16 + g;
            int col = col0 + wn * 32 + j * 8 + 2 * t;
            *(float2*)&C[(size_t)row * D_ + col] =
                make_float2(acc[i][j][0], acc[i][j][1]);
            *(float2*)&C[(size_t)(row + 8) * D_ + col] =
                make_float2(acc[i][j][2], acc[i][j][3]);
        }
}

// ---------------------------------------------------------------------------
// HMMA flash attention (FROZEN core), BMA=64, 4 warps, 96KB smem, 2 CTAs/SM.
// Epilogue writes fp16 to g_Ah (feeds fp16 O-proj).
// ---------------------------------------------------------------------------
#define BMA 64
#define BNA 64
#define ASMEM_BYTES 98304

__global__ __launch_bounds__(128, 2) void attn_hmma(
    const bf16* __restrict__ Qhi, const bf16* __restrict__ Qlo,
    const bf16* __restrict__ Khi, const bf16* __restrict__ Klo,
    const bf16* __restrict__ Vhi, const bf16* __restrict__ Vlo,
    const int* __restrict__ doc,
    __half* __restrict__ Ah)
{
    extern __shared__ char smem[];
    const uint32_t sQh = smem_u32(smem);
    const uint32_t sQl = sQh + 16384;
    const uint32_t sKh = sQh + 32768;
    const uint32_t sKl = sQh + 49152;
    const uint32_t sVh = sQh + 65536;
    const uint32_t sVl = sQh + 81920;
    __shared__ int qdoc[BMA];

    const int h = blockIdx.y;
    const int qt = (int)(gridDim.x - 1 - blockIdx.x);
    const int qbase = qt * BMA;
    const int tid = threadIdx.x;
    const int wid = tid >> 5;
    const int lane = tid & 31;
    const int g = lane >> 2;
    const int t = lane & 3;
    const int r0 = wid * 16;
    const float scale = 0.08838834764831845f;

    const int qd_first = doc[qbase];

    int kt0 = 0;
    while (doc[kt0 * BNA + BNA - 1] < qd_first) kt0++;

    auto load_K = [&](int kt) {
        const bf16* srcs[2] = {Khi, Klo};
#pragma unroll
        for (int j = 0; j < 16; j++) {
            int i = tid + (j << 7);
            int m = i >> 10;
            int idx = i & 1023;
            int r = idx >> 4;
            int cb = (idx & 15) << 4;
            size_t gidx = (size_t)(kt * BNA + r) * D_ + h * HD_ + (cb >> 1);
            uint32_t off = (uint32_t)(r * 256) + (cb ^ ((r & 7) << 4));
            CPA16((m ? sKl : sKh) + off, (const char*)&srcs[m][gidx]);
        }
        CPA_COMMIT();
    };
    auto load_V = [&](int kt) {
        const bf16* srcs[2] = {Vhi, Vlo};
#pragma unroll
        for (int j = 0; j < 16; j++) {
            int i = tid + (j << 7);
            int m = i >> 10;
            int idx = i & 1023;
            int r = idx >> 4;
            int cb = (idx & 15) << 4;
            size_t gidx = (size_t)(kt * BNA + r) * D_ + h * HD_ + (cb >> 1);
            uint32_t off = (uint32_t)(r * 256) + (cb ^ ((r & 7) << 4));
            CPA16((m ? sVl : sVh) + off, (const char*)&srcs[m][gidx]);
        }
        CPA_COMMIT();
    };

    load_K(kt0);
    load_V(kt0);

    for (int i = tid; i < BMA * 16; i += 128) {
        int r = i >> 4;
        int cb = (i & 15) << 4;
        size_t gidx = (size_t)(qbase + r) * D_ + h * HD_ + (cb >> 1);
        uint32_t off = (uint32_t)(r * 256) + (cb ^ ((r & 7) << 4));
        *(uint4*)(smem + off)         = *(const uint4*)&Qhi[gidx];
        *(uint4*)(smem + 16384 + off) = *(const uint4*)&Qlo[gidx];
    }
    if (tid < BMA) qdoc[tid] = doc[qbase + tid];
    __syncthreads();

    float oacc[16][4];
#pragma unroll
    for (int nt = 0; nt < 16; nt++)
#pragma unroll
        for (int q = 0; q < 4; q++) oacc[nt][q] = 0.0f;

    float m0 = -1e30f, m1 = -1e30f, l0 = 0.0f, l1 = 0.0f;
    const int qr0 = qbase + r0 + g;
    const int qr1 = qr0 + 8;
    const int dq0 = qdoc[r0 + g];
    const int dq1 = qdoc[r0 + g + 8];

    for (int kt = kt0; kt <= qt; kt++) {
        const int kbase = kt * BNA;
        const bool more = (kt < qt);

        CPA_WAIT(1);
        __syncthreads();

        float sacc[8][4];
#pragma unroll
        for (int nt = 0; nt < 8; nt++)
#pragma unroll
            for (int q = 0; q < 4; q++) sacc[nt][q] = 0.0f;

#pragma unroll
        for (int ks = 0; ks < 8; ks++) {
            uint32_t qh[4], ql[4];
            {
                int row = r0 + (lane & 15);
                int cb = ks * 32 + ((lane >> 4) & 1) * 16;
                uint32_t off = (uint32_t)(row * 256) + (cb ^ ((row & 7) << 4));
                ldsm_x4(qh, sQh + off);
                ldsm_x4(ql, sQl + off);
            }
#pragma unroll
            for (int jp = 0; jp < 4; jp++) {
                uint32_t kh[4], kl[4];
                int row = jp * 16 + ((lane >> 4) & 1) * 8 + (lane & 7);
                int cb = ks * 32 + ((lane >> 3) & 1) * 16;
                uint32_t off = (uint32_t)(row * 256) + (cb ^ ((row & 7) << 4));
                ldsm_x4(kh, sKh + off);
                ldsm_x4(kl, sKl + off);
                mma_bf16(sacc[2 * jp],     qh, &kh[0]);
                mma_bf16(sacc[2 * jp],     ql, &kh[0]);
                mma_bf16(sacc[2 * jp],     qh, &kl[0]);
                mma_bf16(sacc[2 * jp + 1], qh, &kh[2]);
                mma_bf16(sacc[2 * jp + 1], ql, &kh[2]);
                mma_bf16(sacc[2 * jp + 1], qh, &kl[2]);
            }
        }

        __syncthreads();
        if (more) load_K(kt + 1);

#pragma unroll
        for (int nt = 0; nt < 8; nt++) {
#pragma unroll
            for (int e = 0; e < 2; e++) {
                int col = nt * 8 + 2 * t + e;
                int kc = kbase + col;
                int kd = doc[kc];
                float v0 = sacc[nt][e] * scale;
                float v1 = sacc[nt][2 + e] * scale;
                sacc[nt][e]     = (kc <= qr0 && kd == dq0) ? v0 : -1e30f;
                sacc[nt][2 + e] = (kc <= qr1 && kd == dq1) ? v1 : -1e30f;
            }
        }

        float mr0 = -1e30f, mr1 = -1e30f;
#pragma unroll
        for (int nt = 0; nt < 8; nt++) {
            mr0 = fmaxf(mr0, fmaxf(sacc[nt][0], sacc[nt][1]));
            mr1 = fmaxf(mr1, fmaxf(sacc[nt][2], sacc[nt][3]));
        }
        mr0 = fmaxf(mr0, __shfl_xor_sync(0xffffffffu, mr0, 1));
        mr0 = fmaxf(mr0, __shfl_xor_sync(0xffffffffu, mr0, 2));
        mr1 = fmaxf(mr1, __shfl_xor_sync(0xffffffffu, mr1, 1));
        mr1 = fmaxf(mr1, __shfl_xor_sync(0xffffffffu, mr1, 2));
        float mn0 = fmaxf(m0, mr0), mn1 = fmaxf(m1, mr1);
        float rs0 = __expf(m0 - mn0), rs1 = __expf(m1 - mn1);
        float s0 = 0.0f, s1 = 0.0f;
#pragma unroll
        for (int nt = 0; nt < 8; nt++) {
#pragma unroll
            for (int e = 0; e < 2; e++) {
                float a = sacc[nt][e];
                a = (a <= -1e29f) ? 0.0f : __expf(a - mn0);
                sacc[nt][e] = a; s0 += a;
                float b = sacc[nt][2 + e];
                b = (b <= -1e29f) ? 0.0f : __expf(b - mn1);
                sacc[nt][2 + e] = b; s1 += b;
            }
        }
        s0 += __shfl_xor_sync(0xffffffffu, s0, 1);
        s0 += __shfl_xor_sync(0xffffffffu, s0, 2);
        s1 += __shfl_xor_sync(0xffffffffu, s1, 1);
        s1 += __shfl_xor_sync(0xffffffffu, s1, 2);
        l0 = l0 * rs0 + s0; m0 = mn0;
        l1 = l1 * rs1 + s1; m1 = mn1;

#pragma unroll
        for (int nt = 0; nt < 16; nt++) {
            oacc[nt][0] *= rs0; oacc[nt][1] *= rs0;
            oacc[nt][2] *= rs1; oacc[nt][3] *= rs1;
        }

        if (more) { CPA_WAIT(1); } else { CPA_WAIT(0); }
        __syncthreads();

#pragma unroll
        for (int ks = 0; ks < 4; ks++) {
            float p00 = sacc[2 * ks][0],     p01 = sacc[2 * ks][1];
            float p02 = sacc[2 * ks][2],     p03 = sacc[2 * ks][3];
            float p10 = sacc[2 * ks + 1][0], p11 = sacc[2 * ks + 1][1];
            float p12 = sacc[2 * ks + 1][2], p13 = sacc[2 * ks + 1][3];
            uint32_t phi[4], plo[4];
            phi[0] = packbf(p00, p01); phi[1] = packbf(p02, p03);
            phi[2] = packbf(p10, p11); phi[3] = packbf(p12, p13);
            plo[0] = packbf(p00 - bfround(p00), p01 - bfround(p01));
            plo[1] = packbf(p02 - bfround(p02), p03 - bfround(p03));
            plo[2] = packbf(p10 - bfround(p10), p11 - bfround(p11));
            plo[3] = packbf(p12 - bfround(p12), p13 - bfround(p13));

#pragma unroll
            for (int n0 = 0; n0 < 128; n0 += 16) {
                uint32_t vh[4], vl[4];
                int row = ks * 16 + ((lane >> 3) & 1) * 8 + (lane & 7);
                int cb = n0 * 2 + ((lane >> 4) & 1) * 16;
                uint32_t off = (uint32_t)(row * 256) + (cb ^ ((row & 7) << 4));
                ldsm_x4_t(vh, sVh + off);
                ldsm_x4_t(vl, sVl + off);
                int nt = n0 >> 3;
                mma_bf16(oacc[nt],     phi, &vh[0]);
                mma_bf16(oacc[nt],     plo, &vh[0]);
                mma_bf16(oacc[nt],     phi, &vl[0]);
                mma_bf16(oacc[nt + 1], phi, &vh[2]);
                mma_bf16(oacc[nt + 1], plo, &vh[2]);
                mma_bf16(oacc[nt + 1], phi, &vl[2]);
            }
        }

        __syncthreads();
        if (more) load_V(kt + 1);
    }

    // Epilogue: normalize, fp16 write (feeds fp16 O-proj).
    float i0 = 1.0f / l0, i1 = 1.0f / l1;
#pragma unroll
    for (int nt = 0; nt < 16; nt++) {
        float v0 = oacc[nt][0] * i0, v1 = oacc[nt][1] * i0;
        float v2 = oacc[nt][2] * i1, v3 = oacc[nt][3] * i1;
        size_t idx0 = (size_t)qr0 * D_ + h * HD_ + nt * 8 + 2 * t;
        size_t idx1 = idx0 + (size_t)8 * D_;
        *(uint32_t*)&Ah[idx0] = packh(v0, v1);
        *(uint32_t*)&Ah[idx1] = packh(v2, v3);
    }
}

// ---------------------------------------------------------------------------
// Launch
// ---------------------------------------------------------------------------
extern "C" void kernel_launch(void* const* d_in, const int* in_sizes, int n_in,
                              void* d_out, int out_size)
{
    const float* x    = (const float*)d_in[0];
    const float* Wq   = (const float*)d_in[1];
    const float* Wk   = (const float*)d_in[2];
    const float* Wv   = (const float*)d_in[3];
    const float* Wo   = (const float*)d_in[4];
    const float* sint = (const float*)d_in[5];
    const float* cost = (const float*)d_in[6];
    const int*   doc  = (const int*)d_in[7];

    bf16 *Qhi, *Qlo, *Khi, *Klo, *Vhi, *Vlo;
    __half *xh, *Ah, *Wth;
    cudaGetSymbolAddress((void**)&xh, g_xh);
    cudaGetSymbolAddress((void**)&Ah, g_Ah);
    cudaGetSymbolAddress((void**)&Qhi, g_Qhi);
    cudaGetSymbolAddress((void**)&Qlo, g_Qlo);
    cudaGetSymbolAddress((void**)&Khi, g_Khi);
    cudaGetSymbolAddress((void**)&Klo, g_Klo);
    cudaGetSymbolAddress((void**)&Vhi, g_Vhi);
    cudaGetSymbolAddress((void**)&Vlo, g_Vlo);
    cudaGetSymbolAddress((void**)&Wth, g_Wth);

    const size_t WSZ = (size_t)D_ * D_;
    const int NELEM = T_ * D_;

    f16_round_kernel<<<(NELEM + 255) / 256, 256>>>(x, xh);
    dim3 tsBlk(32, 8);
    dim3 tsGrid4(D_ / 32, D_ / 32, 4);
    transpose_f16_4<<<tsGrid4, tsBlk>>>(Wq, Wk, Wv, Wo, Wth);

    cudaFuncSetAttribute(gemm_qkv_f16,
                         cudaFuncAttributeMaxDynamicSharedMemorySize, GSMEM_BYTES);
    cudaFuncSetAttribute(gemm_out_f16,
                         cudaFuncAttributeMaxDynamicSharedMemorySize, GSMEM_BYTES);

    dim3 gGridQKV(D_ / 128, T_ / 128, 3);   // (16, 16, 3)
    gemm_qkv_f16<<<gGridQKV, 256, GSMEM_BYTES>>>(xh, Wth, sint, cost,
                                                 Qhi, Qlo, Khi, Klo, Vhi, Vlo);

    cudaFuncSetAttribute(attn_hmma,
                         cudaFuncAttributeMaxDynamicSharedMemorySize, ASMEM_BYTES);
    attn_hmma<<<dim3(T_ / BMA, H_), 128, ASMEM_BYTES>>>(
        Qhi, Qlo, Khi, Klo, Vhi, Vlo, doc, Ah);

    dim3 gGridO(D_ / 128, T_ / 128, 1);     // (16, 16)
    gemm_out_f16<<<gGridO, 256, GSMEM_BYTES>>>(Ah, Wth + 3 * WSZ, (float*)d_out);
}

// round 17
// speedup vs baseline: 2.5592x; 1.0886x over previous
#include <cuda_runtime.h>
#include <cuda_bf16.h>
#include <cuda_fp16.h>
#include <cstdint>
#include <math.h>

#define T_  2048
#define D_  2048
#define H_  16
#define HD_ 128

typedef __nv_bfloat16 bf16;

// ---------------------------------------------------------------------------
// Scratch (allocation-free rule: __device__ globals)
// ---------------------------------------------------------------------------
__device__ __half g_xh[T_ * D_];       // x, fp16 (rn)
__device__ __half g_Ah[T_ * D_];       // attention output, fp16 (rn)
__device__ __half g_Qh[T_ * D_];       // Q (roped), fp16
__device__ __half g_Kh[T_ * D_];       // K (roped), fp16
__device__ __half g_Vh[T_ * D_];       // V, fp16
__device__ __half g_Wth[4][D_ * D_];   // transposed weights [N,K], fp16 (rn)

// ---------------------------------------------------------------------------
// PTX helpers (compute_103-safe: mma.sync / ldmatrix / cp.async only)
// ---------------------------------------------------------------------------
__device__ __forceinline__ uint32_t smem_u32(const void* p) {
    uint32_t a;
    asm("{ .reg .u64 t; cvta.to.shared.u64 t, %1; cvt.u32.u64 %0, t; }"
        : "=r"(a) : "l"(p));
    return a;
}

#define CPA16(dst, src) \
    asm volatile("cp.async.cg.shared.global [%0], [%1], 16;" :: "r"(dst), "l"(src) : "memory")
#define CPA_COMMIT() asm volatile("cp.async.commit_group;" ::: "memory")
#define CPA_WAIT(n)  asm volatile("cp.async.wait_group %0;" :: "n"(n) : "memory")

__device__ __forceinline__ void ldsm_x4(uint32_t* r, uint32_t addr) {
    asm volatile("ldmatrix.sync.aligned.m8n8.x4.shared.b16 {%0,%1,%2,%3}, [%4];"
                 : "=r"(r[0]), "=r"(r[1]), "=r"(r[2]), "=r"(r[3]) : "r"(addr));
}

__device__ __forceinline__ void ldsm_x4_t(uint32_t* r, uint32_t addr) {
    asm volatile("ldmatrix.sync.aligned.m8n8.x4.trans.shared.b16 {%0,%1,%2,%3}, [%4];"
                 : "=r"(r[0]), "=r"(r[1]), "=r"(r[2]), "=r"(r[3]) : "r"(addr));
}

__device__ __forceinline__ void mma_f16(float* d, const uint32_t* a,
                                        const uint32_t* b) {
    asm volatile(
        "mma.sync.aligned.m16n8k16.row.col.f32.f16.f16.f32 "
        "{%0,%1,%2,%3}, {%4,%5,%6,%7}, {%8,%9}, {%0,%1,%2,%3};"
        : "+f"(d[0]), "+f"(d[1]), "+f"(d[2]), "+f"(d[3])
        : "r"(a[0]), "r"(a[1]), "r"(a[2]), "r"(a[3]), "r"(b[0]), "r"(b[1]));
}

__device__ __forceinline__ uint32_t packh(float lo, float hi) {
    uint32_t r;
    asm("cvt.rn.f16x2.f32 %0, %1, %2;" : "=r"(r) : "f"(hi), "f"(lo));
    return r;
}

__device__ __forceinline__ float hround(float v) {
    return __half2float(__float2half_rn(v));
}

// ---------------------------------------------------------------------------
// Elementwise fp16 rounding: x -> xh.
// ---------------------------------------------------------------------------
__global__ __launch_bounds__(256) void f16_round_kernel(
    const float* __restrict__ src, __half* __restrict__ dst)
{
    int i = blockIdx.x * 256 + threadIdx.x;
    if (i >= T_ * D_) return;
    dst[i] = __float2half_rn(src[i]);
}

// ---------------------------------------------------------------------------
// Transpose all 4 weights: W[K,N] fp32 -> T[N,K] fp16 (rn).
// ---------------------------------------------------------------------------
__global__ __launch_bounds__(256) void transpose_f16_4(
    const float* __restrict__ W0, const float* __restrict__ W1,
    const float* __restrict__ W2, const float* __restrict__ W3,
    __half* __restrict__ TtB)
{
    __shared__ float tile[32][33];
    const size_t WSZ = (size_t)D_ * D_;
    int z = blockIdx.z;
    const float* W = (z == 0) ? W0 : (z == 1) ? W1 : (z == 2) ? W2 : W3;
    __half* Tt = TtB + z * WSZ;

    int bx = blockIdx.x * 32;
    int by = blockIdx.y * 32;
    int tx = threadIdx.x;
    int ty = threadIdx.y;
#pragma unroll
    for (int j = 0; j < 32; j += 8)
        tile[ty + j][tx] = W[(size_t)(by + ty + j) * D_ + bx + tx];
    __syncthreads();
#pragma unroll
    for (int j = 0; j < 32; j += 8)
        Tt[(size_t)(bx + ty + j) * D_ + by + tx] = __float2half_rn(tile[tx][ty + j]);
}

// ---------------------------------------------------------------------------
// fp16 single-pass GEMM mainloop (FROZEN): CTA 128x128, warp 64x32, BK=64,
// 3 stages x 32KB = 96KB -> 2 CTAs/SM, single sync per chunk.
// ---------------------------------------------------------------------------
#define STAGE_BYTES 32768
#define GSMEM_BYTES (3 * STAGE_BYTES)

__device__ __forceinline__ void f16_mainloop128(
    const __half* __restrict__ A, const __half* __restrict__ Bt,
    int row0, int col0, char* smem, float acc[4][4][4])
{
    uint32_t sb = smem_u32(smem);
    const int tid  = threadIdx.x;
    const int wid  = tid >> 5;
    const int lane = tid & 31;
    const int wm = wid >> 2;
    const int wn = wid & 3;

    const char* baseA = (const char*)(A  + (size_t)row0 * D_);
    const char* baseB = (const char*)(Bt + (size_t)col0 * D_);

    auto load_stage = [&](int c, int s) {
        uint32_t st = sb + s * STAGE_BYTES;
#pragma unroll
        for (int j = 0; j < 8; j++) {
            int m = j >> 2;
            int q = tid + ((j & 3) << 8);
            int r = q >> 3;
            int cb = (q & 7) << 4;
            const char* src = (m ? baseB : baseA)
                              + (size_t)r * (D_ * 2) + c * 128 + cb;
            uint32_t off = (uint32_t)(r * 128) + (cb ^ ((r & 7) << 4));
            CPA16(st + m * 16384 + off, src);
        }
        CPA_COMMIT();
    };

    load_stage(0, 0);
    load_stage(1, 1);

    for (int c = 0; c < 32; c++) {
        if (c < 31) CPA_WAIT(1);
        else        CPA_WAIT(0);
        __syncthreads();
        if (c + 2 < 32) load_stage(c + 2, (c + 2) % 3);

        uint32_t st = sb + (c % 3) * STAGE_BYTES;
        uint32_t sA = st;
        uint32_t sB = st + 16384;

#pragma unroll
        for (int ks = 0; ks < 4; ks++) {
            uint32_t a[4][4];
#pragma unroll
            for (int i = 0; i < 4; i++) {
                int row = wm * 64 + i * 16 + (lane & 15);
                uint32_t colb = ks * 32 + ((lane >> 4) & 1) * 16;
                uint32_t off = (uint32_t)(row * 128) + (colb ^ ((row & 7) << 4));
                ldsm_x4(a[i], sA + off);
            }
            uint32_t b[8];
#pragma unroll
            for (int jp = 0; jp < 2; jp++) {
                int row = wn * 32 + jp * 16 + ((lane >> 4) & 1) * 8 + (lane & 7);
                uint32_t colb = ks * 32 + ((lane >> 3) & 1) * 16;
                uint32_t off = (uint32_t)(row * 128) + (colb ^ ((row & 7) << 4));
                ldsm_x4(&b[jp * 4], sB + off);
            }
#pragma unroll
            for (int i = 0; i < 4; i++)
#pragma unroll
                for (int j = 0; j < 4; j++)
                    mma_f16(acc[i][j], a[i], &b[j * 2]);
        }
    }
}

// ---------------------------------------------------------------------------
// QKV GEMM (fp16) with fused RoPE (z<2); writes single-fp16 Q/K/V.
// ---------------------------------------------------------------------------
#define LDC 132

__global__ __launch_bounds__(256, 2) void gemm_qkv_f16(
    const __half* __restrict__ xh, const __half* __restrict__ Wth,
    const float* __restrict__ sint, const float* __restrict__ cost,
    __half* __restrict__ Qh, __half* __restrict__ Kh, __half* __restrict__ Vh)
{
    extern __shared__ char smem[];
    const int z = blockIdx.z;
    const int row0 = blockIdx.y * 128;
    const int col0 = blockIdx.x * 128;
    const size_t WSZ = (size_t)D_ * D_;

    float acc[4][4][4];
#pragma unroll
    for (int i = 0; i < 4; i++)
#pragma unroll
        for (int j = 0; j < 4; j++)
#pragma unroll
            for (int q = 0; q < 4; q++) acc[i][j][q] = 0.0f;

    f16_mainloop128(xh, Wth + z * WSZ, row0, col0, smem, acc);

    __syncthreads();
    float* sC = (float*)smem;
    const int tid  = threadIdx.x;
    const int wid  = tid >> 5;
    const int lane = tid & 31;
    const int wm = wid >> 2, wn = wid & 3;
    const int g = lane >> 2, t = lane & 3;
#pragma unroll
    for (int i = 0; i < 4; i++)
#pragma unroll
        for (int j = 0; j < 4; j++) {
            int row = wm * 64 + i * 16 + g;
            int col = wn * 32 + j * 8 + 2 * t;
            *(float2*)&sC[row * LDC + col] = make_float2(acc[i][j][0], acc[i][j][1]);
            *(float2*)&sC[(row + 8) * LDC + col] = make_float2(acc[i][j][2], acc[i][j][3]);
        }
    __syncthreads();

    __half* Oh = (z == 0) ? Qh : (z == 1) ? Kh : Vh;
    const bool dorope = (z < 2);

#pragma unroll 4
    for (int it = 0; it < 32; it++) {
        int idx = it * 256 + tid;
        int r = idx >> 6;
        int d = idx & 63;
        float v1 = sC[r * LDC + d];
        float v2 = sC[r * LDC + d + 64];
        int tg = row0 + r;
        float o1 = v1, o2 = v2;
        if (dorope) {
            float s1 = sint[tg * HD_ + d],      c1 = cost[tg * HD_ + d];
            float s2 = sint[tg * HD_ + d + 64], c2 = cost[tg * HD_ + d + 64];
            o1 = v1 * c1 - v2 * s1;
            o2 = v2 * c2 + v1 * s2;
        }
        size_t gi = (size_t)tg * D_ + col0 + d;
        Oh[gi]      = __float2half_rn(o1);
        Oh[gi + 64] = __float2half_rn(o2);
    }
}

// ---------------------------------------------------------------------------
// O-projection GEMM (fp16): fp32 output, register epilogue.
// ---------------------------------------------------------------------------
__global__ __launch_bounds__(256, 2) void gemm_out_f16(
    const __half* __restrict__ A, const __half* __restrict__ Bt,
    float* __restrict__ C)
{
    extern __shared__ char smem[];
    const int row0 = blockIdx.y * 128;
    const int col0 = blockIdx.x * 128;

    float acc[4][4][4];
#pragma unroll
    for (int i = 0; i < 4; i++)
#pragma unroll
        for (int j = 0; j < 4; j++)
#pragma unroll
            for (int q = 0; q < 4; q++) acc[i][j][q] = 0.0f;

    f16_mainloop128(A, Bt, row0, col0, smem, acc);

    const int tid  = threadIdx.x;
    const int wid  = tid >> 5;
    const int lane = tid & 31;
    const int wm = wid >> 2, wn = wid & 3;
    const int g = lane >> 2, t = lane & 3;
#pragma unroll
    for (int i = 0; i < 4; i++)
#pragma unroll
        for (int j = 0; j < 4; j++) {
            int row = row0 + wm * 64 + i * 16 + g;
            int col = col0 + wn * 32 + j * 8 + 2 * t;
            *(float2*)&C[(size_t)row * D_ + col] =
                make_float2(acc[i][j][0], acc[i][j][1]);
            *(float2*)&C[(size_t)(row + 8) * D_ + col] =
                make_float2(acc[i][j][2], acc[i][j][3]);
        }
}

// ---------------------------------------------------------------------------
// fp16 flash attention: BMA=64, 4 warps, 48KB smem -> 3 CTAs/SM.
// S = Qh Kh^T single fp16; PV with split-fp16 P x single fp16 V.
// K/V cp.async pipelined (temporal single-buffering), contiguous live range.
// ---------------------------------------------------------------------------
#define BMA 64
#define BNA 64
#define ASMEM_BYTES 49152

__global__ __launch_bounds__(128, 3) void attn_f16(
    const __half* __restrict__ Qh, const __half* __restrict__ Kh,
    const __half* __restrict__ Vh, const int* __restrict__ doc,
    __half* __restrict__ Ah)
{
    extern __shared__ char smem[];
    const uint32_t sQ = smem_u32(smem);
    const uint32_t sK = sQ + 16384;
    const uint32_t sV = sQ + 32768;
    __shared__ int qdoc[BMA];

    const int h = blockIdx.y;
    const int qt = (int)(gridDim.x - 1 - blockIdx.x);   // heavy tiles first
    const int qbase = qt * BMA;
    const int tid = threadIdx.x;
    const int wid = tid >> 5;
    const int lane = tid & 31;
    const int g = lane >> 2;
    const int t = lane & 3;
    const int r0 = wid * 16;
    const float scale = 0.08838834764831845f;

    const int qd_first = doc[qbase];

    int kt0 = 0;
    while (doc[kt0 * BNA + BNA - 1] < qd_first) kt0++;

    // Loaders: one matrix = 64 rows x 256B = 16KB = 1024 16B chunks.
    auto load_K = [&](int kt) {
#pragma unroll
        for (int j = 0; j < 8; j++) {
            int i = tid + (j << 7);          // 0..1023
            int r = i >> 4;
            int cb = (i & 15) << 4;
            size_t gidx = (size_t)(kt * BNA + r) * D_ + h * HD_ + (cb >> 1);
            uint32_t off = (uint32_t)(r * 256) + (cb ^ ((r & 7) << 4));
            CPA16(sK + off, (const char*)&Kh[gidx]);
        }
        CPA_COMMIT();
    };
    auto load_V = [&](int kt) {
#pragma unroll
        for (int j = 0; j < 8; j++) {
            int i = tid + (j << 7);
            int r = i >> 4;
            int cb = (i & 15) << 4;
            size_t gidx = (size_t)(kt * BNA + r) * D_ + h * HD_ + (cb >> 1);
            uint32_t off = (uint32_t)(r * 256) + (cb ^ ((r & 7) << 4));
            CPA16(sV + off, (const char*)&Vh[gidx]);
        }
        CPA_COMMIT();
    };

    load_K(kt0);
    load_V(kt0);

    // Q tile (sync loads, overlap the cp.async above).
    for (int i = tid; i < BMA * 16; i += 128) {
        int r = i >> 4;
        int cb = (i & 15) << 4;
        size_t gidx = (size_t)(qbase + r) * D_ + h * HD_ + (cb >> 1);
        uint32_t off = (uint32_t)(r * 256) + (cb ^ ((r & 7) << 4));
        *(uint4*)(smem + off) = *(const uint4*)&Qh[gidx];
    }
    if (tid < BMA) qdoc[tid] = doc[qbase + tid];
    __syncthreads();

    float oacc[16][4];
#pragma unroll
    for (int nt = 0; nt < 16; nt++)
#pragma unroll
        for (int q = 0; q < 4; q++) oacc[nt][q] = 0.0f;

    float m0 = -1e30f, m1 = -1e30f, l0 = 0.0f, l1 = 0.0f;
    const int qr0 = qbase + r0 + g;
    const int qr1 = qr0 + 8;
    const int dq0 = qdoc[r0 + g];
    const int dq1 = qdoc[r0 + g + 8];

    for (int kt = kt0; kt <= qt; kt++) {
        const int kbase = kt * BNA;
        const bool more = (kt < qt);

        // K(kt) ready (V(kt) may still be in flight).
        CPA_WAIT(1);
        __syncthreads();

        // --- S = Q K^T (single fp16) ---
        float sacc[8][4];
#pragma unroll
        for (int nt = 0; nt < 8; nt++)
#pragma unroll
            for (int q = 0; q < 4; q++) sacc[nt][q] = 0.0f;

#pragma unroll
        for (int ks = 0; ks < 8; ks++) {
            uint32_t qf[4];
            {
                int row = r0 + (lane & 15);
                int cb = ks * 32 + ((lane >> 4) & 1) * 16;
                uint32_t off = (uint32_t)(row * 256) + (cb ^ ((row & 7) << 4));
                ldsm_x4(qf, sQ + off);
            }
#pragma unroll
            for (int jp = 0; jp < 4; jp++) {
                uint32_t kf[4];
                int row = jp * 16 + ((lane >> 4) & 1) * 8 + (lane & 7);
                int cb = ks * 32 + ((lane >> 3) & 1) * 16;
                uint32_t off = (uint32_t)(row * 256) + (cb ^ ((row & 7) << 4));
                ldsm_x4(kf, sK + off);
                mma_f16(sacc[2 * jp],     qf, &kf[0]);
                mma_f16(sacc[2 * jp + 1], qf, &kf[2]);
            }
        }

        // sK consumed -> prefetch K(kt+1).
        __syncthreads();
        if (more) load_K(kt + 1);

        // --- scale + mask ---
#pragma unroll
        for (int nt = 0; nt < 8; nt++) {
#pragma unroll
            for (int e = 0; e < 2; e++) {
                int col = nt * 8 + 2 * t + e;
                int kc = kbase + col;
                int kd = doc[kc];
                float v0 = sacc[nt][e] * scale;
                float v1 = sacc[nt][2 + e] * scale;
                sacc[nt][e]     = (kc <= qr0 && kd == dq0) ? v0 : -1e30f;
                sacc[nt][2 + e] = (kc <= qr1 && kd == dq1) ? v1 : -1e30f;
            }
        }

        // --- online softmax ---
        float mr0 = -1e30f, mr1 = -1e30f;
#pragma unroll
        for (int nt = 0; nt < 8; nt++) {
            mr0 = fmaxf(mr0, fmaxf(sacc[nt][0], sacc[nt][1]));
            mr1 = fmaxf(mr1, fmaxf(sacc[nt][2], sacc[nt][3]));
        }
        mr0 = fmaxf(mr0, __shfl_xor_sync(0xffffffffu, mr0, 1));
        mr0 = fmaxf(mr0, __shfl_xor_sync(0xffffffffu, mr0, 2));
        mr1 = fmaxf(mr1, __shfl_xor_sync(0xffffffffu, mr1, 1));
        mr1 = fmaxf(mr1, __shfl_xor_sync(0xffffffffu, mr1, 2));
        float mn0 = fmaxf(m0, mr0), mn1 = fmaxf(m1, mr1);
        float rs0 = __expf(m0 - mn0), rs1 = __expf(m1 - mn1);
        float s0 = 0.0f, s1 = 0.0f;
#pragma unroll
        for (int nt = 0; nt < 8; nt++) {
#pragma unroll
            for (int e = 0; e < 2; e++) {
                float a = sacc[nt][e];
                a = (a <= -1e29f) ? 0.0f : __expf(a - mn0);
                sacc[nt][e] = a; s0 += a;
                float b = sacc[nt][2 + e];
                b = (b <= -1e29f) ? 0.0f : __expf(b - mn1);
                sacc[nt][2 + e] = b; s1 += b;
            }
        }
        s0 += __shfl_xor_sync(0xffffffffu, s0, 1);
        s0 += __shfl_xor_sync(0xffffffffu, s0, 2);
        s1 += __shfl_xor_sync(0xffffffffu, s1, 1);
        s1 += __shfl_xor_sync(0xffffffffu, s1, 2);
        l0 = l0 * rs0 + s0; m0 = mn0;
        l1 = l1 * rs1 + s1; m1 = mn1;

#pragma unroll
        for (int nt = 0; nt < 16; nt++) {
            oacc[nt][0] *= rs0; oacc[nt][1] *= rs0;
            oacc[nt][2] *= rs1; oacc[nt][3] *= rs1;
        }

        // V(kt) ready (K(kt+1) may be in flight).
        if (more) { CPA_WAIT(1); } else { CPA_WAIT(0); }
        __syncthreads();

        // --- O += P V (split-fp16 P x fp16 V) ---
#pragma unroll
        for (int ks = 0; ks < 4; ks++) {
            float p00 = sacc[2 * ks][0],     p01 = sacc[2 * ks][1];
            float p02 = sacc[2 * ks][2],     p03 = sacc[2 * ks][3];
            float p10 = sacc[2 * ks + 1][0], p11 = sacc[2 * ks + 1][1];
            float p12 = sacc[2 * ks + 1][2], p13 = sacc[2 * ks + 1][3];
            uint32_t phi[4], plo[4];
            phi[0] = packh(p00, p01); phi[1] = packh(p02, p03);
            phi[2] = packh(p10, p11); phi[3] = packh(p12, p13);
            plo[0] = packh(p00 - hround(p00), p01 - hround(p01));
            plo[1] = packh(p02 - hround(p02), p03 - hround(p03));
            plo[2] = packh(p10 - hround(p10), p11 - hround(p11));
            plo[3] = packh(p12 - hround(p12), p13 - hround(p13));

#pragma unroll
            for (int n0 = 0; n0 < 128; n0 += 16) {
                uint32_t vf[4];
                int row = ks * 16 + ((lane >> 3) & 1) * 8 + (lane & 7);
                int cb = n0 * 2 + ((lane >> 4) & 1) * 16;
                uint32_t off = (uint32_t)(row * 256) + (cb ^ ((row & 7) << 4));
                ldsm_x4_t(vf, sV + off);
                int nt = n0 >> 3;
                mma_f16(oacc[nt],     phi, &vf[0]);
                mma_f16(oacc[nt],     plo, &vf[0]);
                mma_f16(oacc[nt + 1], phi, &vf[2]);
                mma_f16(oacc[nt + 1], plo, &vf[2]);
            }
        }

        // sV consumed -> prefetch V(kt+1).
        __syncthreads();
        if (more) load_V(kt + 1);
    }

    // Epilogue: normalize, fp16 write (feeds fp16 O-proj).
    float i0 = 1.0f / l0, i1 = 1.0f / l1;
#pragma unroll
    for (int nt = 0; nt < 16; nt++) {
        float v0 = oacc[nt][0] * i0, v1 = oacc[nt][1] * i0;
        float v2 = oacc[nt][2] * i1, v3 = oacc[nt][3] * i1;
        size_t idx0 = (size_t)qr0 * D_ + h * HD_ + nt * 8 + 2 * t;
        size_t idx1 = idx0 + (size_t)8 * D_;
        *(uint32_t*)&Ah[idx0] = packh(v0, v1);
        *(uint32_t*)&Ah[idx1] = packh(v2, v3);
    }
}

// ---------------------------------------------------------------------------
// Launch
// ---------------------------------------------------------------------------
extern "C" void kernel_launch(void* const* d_in, const int* in_sizes, int n_in,
                              void* d_out, int out_size)
{
    const float* x    = (const float*)d_in[0];
    const float* Wq   = (const float*)d_in[1];
    const float* Wk   = (const float*)d_in[2];
    const float* Wv   = (const float*)d_in[3];
    const float* Wo   = (const float*)d_in[4];
    const float* sint = (const float*)d_in[5];
    const float* cost = (const float*)d_in[6];
    const int*   doc  = (const int*)d_in[7];

    __half *xh, *Ah, *Qh, *Kh, *Vh, *Wth;
    cudaGetSymbolAddress((void**)&xh, g_xh);
    cudaGetSymbolAddress((void**)&Ah, g_Ah);
    cudaGetSymbolAddress((void**)&Qh, g_Qh);
    cudaGetSymbolAddress((void**)&Kh, g_Kh);
    cudaGetSymbolAddress((void**)&Vh, g_Vh);
    cudaGetSymbolAddress((void**)&Wth, g_Wth);

    const size_t WSZ = (size_t)D_ * D_;
    const int NELEM = T_ * D_;

    f16_round_kernel<<<(NELEM + 255) / 256, 256>>>(x, xh);
    dim3 tsBlk(32, 8);
    dim3 tsGrid4(D_ / 32, D_ / 32, 4);
    transpose_f16_4<<<tsGrid4, tsBlk>>>(Wq, Wk, Wv, Wo, Wth);

    cudaFuncSetAttribute(gemm_qkv_f16,
                         cudaFuncAttributeMaxDynamicSharedMemorySize, GSMEM_BYTES);
    cudaFuncSetAttribute(gemm_out_f16,
                         cudaFuncAttributeMaxDynamicSharedMemorySize, GSMEM_BYTES);

    dim3 gGridQKV(D_ / 128, T_ / 128, 3);   // (16, 16, 3)
    gemm_qkv_f16<<<gGridQKV, 256, GSMEM_BYTES>>>(xh, Wth, sint, cost, Qh, Kh, Vh);

    cudaFuncSetAttribute(attn_f16,
                         cudaFuncAttributeMaxDynamicSharedMemorySize, ASMEM_BYTES);
    attn_f16<<<dim3(T_ / BMA, H_), 128, ASMEM_BYTES>>>(Qh, Kh, Vh, doc, Ah);

    dim3 gGridO(D_ / 128, T_ / 128, 1);     // (16, 16)
    gemm_out_f16<<<gGridO, 256, GSMEM_BYTES>>>(Ah, Wth + 3 * WSZ, (float*)d_out);
}